// round 10
// baseline (speedup 1.0000x reference)
#include <cuda_runtime.h>
#include <cuda_bf16.h>
#include <math.h>
#include <cstdint>

// ---------------- problem constants ----------------
#define BQ 2
#define LSEQ 4096
#define DMODEL 1024
#define DINNER 2048
#define NH 32
#define HD 64
#define DSTATE 128
#define CHK 64
#define NC 64
#define DPROJ 4384
#define CONVCH 2304
#define MROWS (BQ*LSEQ)
#define NPAD1 4480      // DPROJ padded to 128

// ---------------- scratch (device globals; no allocation) ----------------
__device__ float g_zx[(size_t)MROWS * DPROJ];
__device__ float g_xbc[(size_t)MROWS * CONVCH];
__device__ float g_acum[BQ * NC * NH * CHK];
__device__ float g_suma[BQ * NC * NH];
__device__ float g_states[(size_t)BQ * NC * NH * HD * DSTATE];
__device__ float g_y[(size_t)MROWS * DINNER];

__device__ __nv_bfloat16 g_a1h[(size_t)MROWS * DMODEL];
__device__ __nv_bfloat16 g_a1l[(size_t)MROWS * DMODEL];
__device__ __nv_bfloat16 g_b1h[(size_t)NPAD1 * DMODEL];
__device__ __nv_bfloat16 g_b1l[(size_t)NPAD1 * DMODEL];
__device__ __nv_bfloat16 g_a2h[(size_t)MROWS * DINNER];
__device__ __nv_bfloat16 g_a2l[(size_t)MROWS * DINNER];
__device__ __nv_bfloat16 g_b2h[(size_t)DMODEL * DINNER];
__device__ __nv_bfloat16 g_b2l[(size_t)DMODEL * DINNER];

// ---------------- PTX helpers ----------------
__device__ __forceinline__ uint32_t smem_u32(const void* p) {
    uint32_t a;
    asm("{ .reg .u64 t; cvta.to.shared.u64 t, %1; cvt.u32.u64 %0, t; }" : "=r"(a) : "l"(p));
    return a;
}
#define SMEM_SWIZZLE_128B(byte_offset) ((byte_offset) ^ (((byte_offset) >> 3) & 0x70))
#define CP_ASYNC16(dst, src) \
    asm volatile("cp.async.cg.shared.global [%0], [%1], 16;" :: "r"(dst), "l"(src) : "memory")
#define CP_COMMIT() asm volatile("cp.async.commit_group;" ::: "memory")
#define CP_WAIT0()  asm volatile("cp.async.wait_group 0;" ::: "memory")

#define LDSM_X4(r0,r1,r2,r3,addr) \
    asm volatile("ldmatrix.sync.aligned.m8n8.x4.shared.b16 {%0,%1,%2,%3}, [%4];" \
        : "=r"(r0), "=r"(r1), "=r"(r2), "=r"(r3) : "r"(addr))

#define MMA16816(d, a, b0, b1) \
    asm volatile("mma.sync.aligned.m16n8k16.row.col.f32.bf16.bf16.f32 " \
        "{%0,%1,%2,%3}, {%4,%5,%6,%7}, {%8,%9}, {%0,%1,%2,%3};" \
        : "+f"((d)[0]), "+f"((d)[1]), "+f"((d)[2]), "+f"((d)[3]) \
        : "r"((a)[0]), "r"((a)[1]), "r"((a)[2]), "r"((a)[3]), "r"(b0), "r"(b1))

// packed f32x2 (2x fp32 FMA rate) for SSD kernels
#define FMA2(d, a, b) asm("fma.rn.f32x2 %0, %1, %2, %0;" : "+l"(d) : "l"(a), "l"(b))
#define MUL2(d, a, b) asm("mul.rn.f32x2 %0, %1, %2;" : "=l"(d) : "l"(a), "l"(b))
__device__ __forceinline__ uint64_t dup2(float x) {
    uint64_t r; asm("mov.b64 %0, {%1, %1};" : "=l"(r) : "f"(x)); return r;
}
__device__ __forceinline__ void up2(uint64_t v, float& lo, float& hi) {
    asm("mov.b64 {%0, %1}, %2;" : "=f"(lo), "=f"(hi) : "l"(v));
}

__device__ __forceinline__ void ldsmA(uint32_t base, int row, int ks, int lane, uint32_t* r) {
    int rr = row + (lane & 15);
    int off = rr * 128 + ks * 32 + ((lane >> 4) << 4);
    LDSM_X4(r[0], r[1], r[2], r[3], base + SMEM_SWIZZLE_128B((uint32_t)off));
}
__device__ __forceinline__ void ldsmB(uint32_t base, int nrow, int ks, int lane, uint32_t* r) {
    int n = nrow + ((lane >> 4) << 3) + (lane & 7);
    int off = n * 128 + ks * 32 + (((lane >> 3) & 1) << 4);
    LDSM_X4(r[0], r[1], r[2], r[3], base + SMEM_SWIZZLE_128B((uint32_t)off));
}

// ---------------- HMMA split-bf16 GEMM (unchanged, 78.5% tensor) ----------------
__global__ __launch_bounds__(256, 2) void hmma_gemm_kernel(
    const __nv_bfloat16* __restrict__ Ah, const __nv_bfloat16* __restrict__ Al,
    const __nv_bfloat16* __restrict__ Bh, const __nv_bfloat16* __restrict__ Bl,
    float* __restrict__ C, int N, int K, int ldc)
{
    extern __shared__ char smem[];
    const uint32_t sb = smem_u32(smem);
    const int tid = threadIdx.x, wid = tid >> 5, lane = tid & 31;
    const int wr = wid & 3, wc = wid >> 2;
    const int rowbase = blockIdx.y * 128, colbase = blockIdx.x * 64;
    const int KC = K >> 6;

    float acc[2][4][4];
#pragma unroll
    for (int mi = 0; mi < 2; mi++)
#pragma unroll
        for (int ni = 0; ni < 4; ni++)
#pragma unroll
            for (int j = 0; j < 4; j++) acc[mi][ni][j] = 0.f;

    auto issue_chunk = [&](int i) {
        const uint32_t st = (uint32_t)(i & 1) * 49152u;
        const int k0 = i << 6;
#pragma unroll
        for (int v = 0; v < 12; v++) {
            const int idx = v * 256 + tid;
            const __nv_bfloat16* src;
            uint32_t dst;
            if (idx < 2048) {
                const int buf = idx >> 10;
                const int r = (idx & 1023) >> 3, c8 = idx & 7;
                src = (buf ? Al : Ah) + (size_t)(rowbase + r) * K + k0 + c8 * 8;
                dst = sb + st + (uint32_t)buf * 16384u +
                      SMEM_SWIZZLE_128B((uint32_t)(r * 128 + c8 * 16));
            } else {
                const int j = idx - 2048;
                const int buf = j >> 9;
                const int r = (j & 511) >> 3, c8 = j & 7;
                src = (buf ? Bl : Bh) + (size_t)(colbase + r) * K + k0 + c8 * 8;
                dst = sb + st + 32768u + (uint32_t)buf * 8192u +
                      SMEM_SWIZZLE_128B((uint32_t)(r * 128 + c8 * 16));
            }
            CP_ASYNC16(dst, src);
        }
    };

    issue_chunk(0);
    CP_COMMIT();

    for (int i = 0; i < KC; i++) {
        CP_WAIT0();
        __syncthreads();
        if (i + 1 < KC) { issue_chunk(i + 1); CP_COMMIT(); }

        const uint32_t st = sb + (uint32_t)(i & 1) * 49152u;
        const uint32_t aH = st, aL = st + 16384u, bH = st + 32768u, bL = st + 40960u;
#pragma unroll
        for (int ks = 0; ks < 4; ks++) {
            uint32_t ah[2][4], al[2][4], bh[2][4], bl[2][4];
#pragma unroll
            for (int mi = 0; mi < 2; mi++) {
                ldsmA(aH, wr * 32 + mi * 16, ks, lane, ah[mi]);
                ldsmA(aL, wr * 32 + mi * 16, ks, lane, al[mi]);
            }
#pragma unroll
            for (int np = 0; np < 2; np++) {
                ldsmB(bH, wc * 32 + np * 16, ks, lane, bh[np]);
                ldsmB(bL, wc * 32 + np * 16, ks, lane, bl[np]);
            }
#pragma unroll
            for (int mi = 0; mi < 2; mi++)
#pragma unroll
                for (int ni = 0; ni < 4; ni++) {
                    const int np = ni >> 1, o = (ni & 1) << 1;
                    MMA16816(acc[mi][ni], ah[mi], bh[np][o], bh[np][o + 1]);
                    MMA16816(acc[mi][ni], ah[mi], bl[np][o], bl[np][o + 1]);
                    MMA16816(acc[mi][ni], al[mi], bh[np][o], bh[np][o + 1]);
                }
        }
        __syncthreads();
    }

#pragma unroll
    for (int mi = 0; mi < 2; mi++) {
        const int row = rowbase + wr * 32 + mi * 16 + (lane >> 2);
#pragma unroll
        for (int ni = 0; ni < 4; ni++) {
            const int col = colbase + wc * 32 + ni * 8 + (lane & 3) * 2;
            if (col < N) {
                *reinterpret_cast<float2*>(&C[(size_t)row * ldc + col]) =
                    make_float2(acc[mi][ni][0], acc[mi][ni][1]);
                *reinterpret_cast<float2*>(&C[(size_t)(row + 8) * ldc + col]) =
                    make_float2(acc[mi][ni][2], acc[mi][ni][3]);
            }
        }
    }
}

// ---------------- fused prep: cvt_split(u) + transpose_split(W_in) + transpose_split(W_out) ----------------
// 1024 threads/block. blocks: [0,2048) cvt, [2048,6528) t1, [6528,8576) t2.
__global__ __launch_bounds__(1024) void prep_kernel(
    const float* __restrict__ u, const float* __restrict__ W_in, const float* __restrict__ W_out,
    __nv_bfloat16* __restrict__ a1h, __nv_bfloat16* __restrict__ a1l,
    __nv_bfloat16* __restrict__ b1h, __nv_bfloat16* __restrict__ b1l,
    __nv_bfloat16* __restrict__ b2h, __nv_bfloat16* __restrict__ b2l)
{
    __shared__ float t[32][33];
    const int bx = blockIdx.x, tid = threadIdx.x;
    if (bx < 2048) {
        int i = bx * 1024 + tid;   // < 2097152 always
        float4 x = reinterpret_cast<const float4*>(u)[i];
        float xs[4] = {x.x, x.y, x.z, x.w};
        __nv_bfloat16 h[4], l[4];
#pragma unroll
        for (int j = 0; j < 4; j++) {
            h[j] = __float2bfloat16(xs[j]);
            l[j] = __float2bfloat16(xs[j] - __bfloat162float(h[j]));
        }
        reinterpret_cast<__nv_bfloat162*>(a1h)[2 * i]     = __nv_bfloat162(h[0], h[1]);
        reinterpret_cast<__nv_bfloat162*>(a1h)[2 * i + 1] = __nv_bfloat162(h[2], h[3]);
        reinterpret_cast<__nv_bfloat162*>(a1l)[2 * i]     = __nv_bfloat162(l[0], l[1]);
        reinterpret_cast<__nv_bfloat162*>(a1l)[2 * i + 1] = __nv_bfloat162(l[2], l[3]);
        return;
    }
    const float* W;
    __nv_bfloat16 *th, *tl;
    int K, N, bxx, byy;
    if (bx < 2048 + 4480) {
        int bb = bx - 2048;
        bxx = bb % 140; byy = bb / 140;
        W = W_in; th = b1h; tl = b1l; K = DMODEL; N = DPROJ;
    } else {
        int bb = bx - 6528;
        bxx = bb % 32; byy = bb / 32;
        W = W_out; th = b2h; tl = b2l; K = DINNER; N = DMODEL;
    }
    const int tx = tid & 31, ty = tid >> 5;
    int n = bxx * 32 + tx;
    int k = byy * 32 + ty;
    t[ty][tx] = (n < N) ? W[(size_t)k * N + n] : 0.f;
    __syncthreads();
    int nn = bxx * 32 + ty;
    int kk = byy * 32 + tx;
    float v = t[tx][ty];
    __nv_bfloat16 h = __float2bfloat16(v);
    th[(size_t)nn * K + kk] = h;
    tl[(size_t)nn * K + kk] = __float2bfloat16(v - __bfloat162float(h));
}

// ---------------- depthwise causal conv(4) + bias + SiLU (smem-tiled) ----------------
__global__ __launch_bounds__(256) void conv_kernel(const float* __restrict__ cw,
                                                   const float* __restrict__ cb) {
    __shared__ float s[19][256];
    int tid = threadIdx.x;
    int ch = blockIdx.x * 256 + tid;
    int m0 = blockIdx.y * 16;
    int l0 = m0 & (LSEQ - 1);
#pragma unroll
    for (int r = 0; r < 19; r++) {
        int l = l0 - 3 + r;
        s[r][tid] = (l >= 0) ? g_zx[(size_t)(m0 - 3 + r) * DPROJ + DINNER + ch] : 0.f;
    }
    __syncthreads();
    float w0 = cw[ch * 4], w1 = cw[ch * 4 + 1], w2 = cw[ch * 4 + 2], w3 = cw[ch * 4 + 3];
    float bias = cb[ch];
#pragma unroll
    for (int r = 0; r < 16; r++) {
        float acc = bias;
        acc = fmaf(s[r][tid], w0, acc);
        acc = fmaf(s[r + 1][tid], w1, acc);
        acc = fmaf(s[r + 2][tid], w2, acc);
        acc = fmaf(s[r + 3][tid], w3, acc);
        g_xbc[(size_t)(m0 + r) * CONVCH + ch] = acc / (1.f + expf(-acc));
    }
}

// ---------------- SSD intra-chunk (now also computes dt softplus + cumsum in-block) ----------------
#define TS_STR 66
#define CS_STR 132
#define XS_STR 68
__global__ __launch_bounds__(256, 1) void ssd_diag_kernel(const float* __restrict__ A_log,
                                                          const float* __restrict__ dt_bias) {
    int blk = blockIdx.x;
    int h = blk & 31;
    int c = (blk >> 5) & 63;
    int b = blk >> 11;
    int m0 = b * LSEQ + c * CHK;

    extern __shared__ float sm[];
    float* Bst = sm;                         // 128*66
    float* Cs  = Bst + 128 * TS_STR;         // 64*132
    float* xs  = Cs + 64 * CS_STR;           // 64*68
    float* Gs  = xs + 64 * XS_STR;           // 64*68
    float* ac  = Gs + 64 * XS_STR;           // 64
    float* wd  = ac + 64;                    // 64
    float* dts = wd + 64;                    // 64
    int tid = threadIdx.x;

    // --- dt = softplus(zx[..., -32:][h] + bias); ac = cumsum(A*dt) (Hillis-Steele) ---
    if (tid < 64) {
        float A = -expf(A_log[h]);
        float raw = g_zx[(size_t)(m0 + tid) * DPROJ + (DPROJ - NH) + h] + dt_bias[h];
        float dtv = (raw > 20.f) ? raw : log1pf(expf(raw));
        dts[tid] = dtv;
        ac[tid] = A * dtv;
    }
    __syncthreads();
#pragma unroll
    for (int off = 1; off < 64; off <<= 1) {
        float v = 0.f;
        if (tid < 64) {
            v = ac[tid];
            if (tid >= off) v += ac[tid - off];
        }
        __syncthreads();
        if (tid < 64) ac[tid] = v;
        __syncthreads();
    }
    if (tid < 64) {
        wd[tid] = expf(ac[63] - ac[tid]);
        g_acum[blk * CHK + tid] = ac[tid];
    }
    if (tid == 0) g_suma[blk] = expf(ac[63]);

    // --- tile loads ---
    for (int i = tid; i < 64 * 128; i += 256) {
        int l = i >> 7, n = i & 127;
        Bst[n * TS_STR + l] = g_xbc[(size_t)(m0 + l) * CONVCH + DINNER + n];
    }
    for (int i = tid; i < 64 * 32; i += 256) {
        int l = i >> 5, q = i & 31;
        float4 v = *reinterpret_cast<const float4*>(
            g_xbc + (size_t)(m0 + l) * CONVCH + DINNER + DSTATE + 4 * q);
        *reinterpret_cast<float4*>(Cs + l * CS_STR + 4 * q) = v;
    }
    for (int i = tid; i < 64 * 16; i += 256) {
        int l = i >> 4, q = i & 15;
        float dtv = dts[l];
        float4 v = *reinterpret_cast<const float4*>(
            g_xbc + (size_t)(m0 + l) * CONVCH + h * HD + 4 * q);
        v.x *= dtv; v.y *= dtv; v.z *= dtv; v.w *= dtv;
        *reinterpret_cast<float4*>(xs + l * XS_STR + 4 * q) = v;
    }
    __syncthreads();

    const int tr = tid >> 4, tc = tid & 15;
    const int r0 = tr * 4, c0 = tc * 4;

    // --- G[l][s] = C[l]·B[s] ---
    if (tc <= tr) {
        uint64_t acc2[4][2] = {{0ull,0ull},{0ull,0ull},{0ull,0ull},{0ull,0ull}};
        for (int n4 = 0; n4 < 128; n4 += 4) {
            float4 cr[4];
#pragma unroll
            for (int i = 0; i < 4; i++)
                cr[i] = *reinterpret_cast<const float4*>(Cs + (r0 + i) * CS_STR + n4);
#pragma unroll
            for (int nn = 0; nn < 4; nn++) {
                uint64_t b0 = *reinterpret_cast<const uint64_t*>(Bst + (n4 + nn) * TS_STR + c0);
                uint64_t b1 = *reinterpret_cast<const uint64_t*>(Bst + (n4 + nn) * TS_STR + c0 + 2);
#pragma unroll
                for (int i = 0; i < 4; i++) {
                    uint64_t a2 = dup2((&cr[i].x)[nn]);
                    FMA2(acc2[i][0], a2, b0);
                    FMA2(acc2[i][1], a2, b1);
                }
            }
        }
#pragma unroll
        for (int i = 0; i < 4; i++) {
            int l = r0 + i;
            float al = ac[l];
            float v0, v1, v2, v3;
            up2(acc2[i][0], v0, v1);
            up2(acc2[i][1], v2, v3);
            float4 o;
            o.x = (c0     <= l) ? v0 * expf(al - ac[c0])     : 0.f;
            o.y = (c0 + 1 <= l) ? v1 * expf(al - ac[c0 + 1]) : 0.f;
            o.z = (c0 + 2 <= l) ? v2 * expf(al - ac[c0 + 2]) : 0.f;
            o.w = (c0 + 3 <= l) ? v3 * expf(al - ac[c0 + 3]) : 0.f;
            *reinterpret_cast<float4*>(Gs + l * XS_STR + c0) = o;
        }
    }
    __syncthreads();

    // --- Y_diag[l][p] = sum_{s<=l} G[l][s]*x[s][p] ---
    {
        uint64_t acc2[4][2] = {{0ull,0ull},{0ull,0ull},{0ull,0ull},{0ull,0ull}};
        for (int s4 = 0; s4 < r0 + 4; s4 += 4) {
            float4 gr[4];
#pragma unroll
            for (int i = 0; i < 4; i++)
                gr[i] = *reinterpret_cast<const float4*>(Gs + (r0 + i) * XS_STR + s4);
#pragma unroll
            for (int ss = 0; ss < 4; ss++) {
                uint64_t x0 = *reinterpret_cast<const uint64_t*>(xs + (s4 + ss) * XS_STR + c0);
                uint64_t x1 = *reinterpret_cast<const uint64_t*>(xs + (s4 + ss) * XS_STR + c0 + 2);
#pragma unroll
                for (int i = 0; i < 4; i++) {
                    uint64_t a2 = dup2((&gr[i].x)[ss]);
                    FMA2(acc2[i][0], a2, x0);
                    FMA2(acc2[i][1], a2, x1);
                }
            }
        }
#pragma unroll
        for (int i = 0; i < 4; i++) {
            float v0, v1, v2, v3;
            up2(acc2[i][0], v0, v1);
            up2(acc2[i][1], v2, v3);
            *reinterpret_cast<float4*>(g_y + (size_t)(m0 + r0 + i) * DINNER + h * HD + c0) =
                make_float4(v0, v1, v2, v3);
        }
    }

    // --- states S[p][n] = sum_l wd[l]*x[l][p]*B[l][n] ---
    {
        const int p0 = (tid & 15) * 4, n0 = (tid >> 4) * 8;
        uint64_t acc2[2][8];
#pragma unroll
        for (int pp = 0; pp < 2; pp++)
#pragma unroll
            for (int j = 0; j < 8; j++) acc2[pp][j] = 0ull;
        for (int l = 0; l < 64; l++) {
            uint64_t w2 = dup2(wd[l]);
            uint64_t xa = *reinterpret_cast<const uint64_t*>(xs + l * XS_STR + p0);
            uint64_t xb = *reinterpret_cast<const uint64_t*>(xs + l * XS_STR + p0 + 2);
            uint64_t wxa, wxb;
            MUL2(wxa, xa, w2);
            MUL2(wxb, xb, w2);
#pragma unroll
            for (int j = 0; j < 8; j++) {
                uint64_t b2 = dup2(Bst[(n0 + j) * TS_STR + l]);
                FMA2(acc2[0][j], wxa, b2);
                FMA2(acc2[1][j], wxb, b2);
            }
        }
        float rowv[4][8];
#pragma unroll
        for (int pp = 0; pp < 2; pp++)
#pragma unroll
            for (int j = 0; j < 8; j++)
                up2(acc2[pp][j], rowv[2 * pp][j], rowv[2 * pp + 1][j]);
#pragma unroll
        for (int i = 0; i < 4; i++) {
            float* dst = g_states + ((size_t)blk * HD + p0 + i) * DSTATE + n0;
            *reinterpret_cast<float4*>(dst)     = make_float4(rowv[i][0], rowv[i][1], rowv[i][2], rowv[i][3]);
            *reinterpret_cast<float4*>(dst + 4) = make_float4(rowv[i][4], rowv[i][5], rowv[i][6], rowv[i][7]);
        }
    }
}

// ---------------- inter-chunk scan ----------------
__global__ void scan_kernel() {
    int idx = blockIdx.x * blockDim.x + threadIdx.x;
    int n = idx & 127;
    int p = (idx >> 7) & 63;
    int h = (idx >> 13) & 31;
    int b = idx >> 18;
    float prev = 0.f;
    for (int c = 0; c < NC; c++) {
        int bch = (b * NC + c) * NH + h;
        size_t off = ((size_t)bch * HD + p) * DSTATE + n;
        float loc = g_states[off];
        g_states[off] = prev;
        prev = fmaf(prev, g_suma[bch], loc);
    }
}

// ---------------- Y_off + skip (f32x2, half-C double pass, 2 CTAs/SM) ----------------
#define CS2_STR 68
__global__ __launch_bounds__(256, 2) void yoff_kernel(const float* __restrict__ Dv) {
    int blk = blockIdx.x;
    int h = blk & 31;
    int c = (blk >> 5) & 63;
    int b = blk >> 11;
    int m0 = b * LSEQ + c * CHK;

    extern __shared__ float sm[];
    float* Pst = sm;                        // 128 x stride 66 ([n][p])
    float* Cs2 = Pst + 128 * TS_STR;        // 64 x stride 68 (half of C)
    float* ac  = Cs2 + 64 * CS2_STR;        // 64
    int tid = threadIdx.x;

    for (int i = tid; i < 64 * 128; i += 256) {
        int p = i >> 7, n = i & 127;
        Pst[n * TS_STR + p] = g_states[((size_t)blk * HD + p) * DSTATE + n];
    }
    if (tid < 64) ac[tid] = g_acum[blk * CHK + tid];
    float Dh = Dv[h];

    const int tr = tid >> 4, tc = tid & 15;
    const int r0 = tr * 4, c0 = tc * 4;
    uint64_t acc2[4][2] = {{0ull,0ull},{0ull,0ull},{0ull,0ull},{0ull,0ull}};

#pragma unroll
    for (int half = 0; half < 2; half++) {
        __syncthreads();   // also protects Cs2 reuse between halves
        for (int i = tid; i < 64 * 16; i += 256) {
            int l = i >> 4, q = i & 15;
            float4 v = *reinterpret_cast<const float4*>(
                g_xbc + (size_t)(m0 + l) * CONVCH + DINNER + DSTATE + half * 64 + 4 * q);
            *reinterpret_cast<float4*>(Cs2 + l * CS2_STR + 4 * q) = v;
        }
        __syncthreads();
        for (int n4 = 0; n4 < 64; n4 += 4) {
            float4 cr[4];
#pragma unroll
            for (int i = 0; i < 4; i++)
                cr[i] = *reinterpret_cast<const float4*>(Cs2 + (r0 + i) * CS2_STR + n4);
#pragma unroll
            for (int nn = 0; nn < 4; nn++) {
                int n = half * 64 + n4 + nn;
                uint64_t p0v = *reinterpret_cast<const uint64_t*>(Pst + n * TS_STR + c0);
                uint64_t p1v = *reinterpret_cast<const uint64_t*>(Pst + n * TS_STR + c0 + 2);
#pragma unroll
                for (int i = 0; i < 4; i++) {
                    uint64_t a2 = dup2((&cr[i].x)[nn]);
                    FMA2(acc2[i][0], a2, p0v);
                    FMA2(acc2[i][1], a2, p1v);
                }
            }
        }
    }

#pragma unroll
    for (int i = 0; i < 4; i++) {
        int l = r0 + i;
        int row = m0 + l;
        float el = expf(ac[l]);
        float v0, v1, v2, v3;
        up2(acc2[i][0], v0, v1);
        up2(acc2[i][1], v2, v3);
        float4 xv = *reinterpret_cast<const float4*>(
            g_xbc + (size_t)row * CONVCH + h * HD + c0);
        float4* yp = reinterpret_cast<float4*>(g_y + (size_t)row * DINNER + h * HD + c0);
        float4 yv = *yp;
        yv.x += v0 * el + xv.x * Dh;
        yv.y += v1 * el + xv.y * Dh;
        yv.z += v2 * el + xv.z * Dh;
        yv.w += v3 * el + xv.w * Dh;
        *yp = yv;
    }
}

// ---------------- gate (silu(z)) + RMSNorm, fused bf16 split output ----------------
__global__ void gate_kernel(const float* __restrict__ norm_w,
                            __nv_bfloat16* __restrict__ a2h, __nv_bfloat16* __restrict__ a2l) {
    int m = blockIdx.x;
    int tid = threadIdx.x;
    __shared__ float red[256];
    float tv[8];
    float ss = 0.f;
#pragma unroll
    for (int j = 0; j < 8; j++) {
        int i = tid + 256 * j;
        float zv = g_zx[(size_t)m * DPROJ + i];
        float yv = g_y[(size_t)m * DINNER + i];
        float g = yv * (zv / (1.f + expf(-zv)));
        tv[j] = g;
        ss += g * g;
    }
    red[tid] = ss;
    __syncthreads();
    for (int s = 128; s > 0; s >>= 1) {
        if (tid < s) red[tid] += red[tid + s];
        __syncthreads();
    }
    float scale = rsqrtf(red[0] / (float)DINNER + 1e-5f);
#pragma unroll
    for (int j = 0; j < 8; j++) {
        int i = tid + 256 * j;
        float val = tv[j] * scale * norm_w[i];
        __nv_bfloat16 hv = __float2bfloat16(val);
        a2h[(size_t)m * DINNER + i] = hv;
        a2l[(size_t)m * DINNER + i] = __float2bfloat16(val - __bfloat162float(hv));
    }
}

// ---------------- launch ----------------
extern "C" void kernel_launch(void* const* d_in, const int* in_sizes, int n_in,
                              void* d_out, int out_size) {
    const float* u      = (const float*)d_in[0];
    const float* W_in   = (const float*)d_in[1];
    const float* conv_w = (const float*)d_in[2];
    const float* conv_b = (const float*)d_in[3];
    const float* dt_b   = (const float*)d_in[4];
    const float* A_log  = (const float*)d_in[5];
    const float* Dv     = (const float*)d_in[6];
    const float* norm_w = (const float*)d_in[7];
    const float* W_out  = (const float*)d_in[8];
    float* out = (float*)d_out;

    float* zx = nullptr;
    cudaGetSymbolAddress((void**)&zx, g_zx);
    __nv_bfloat16 *a1h, *a1l, *b1h, *b1l, *a2h, *a2l, *b2h, *b2l;
    cudaGetSymbolAddress((void**)&a1h, g_a1h);
    cudaGetSymbolAddress((void**)&a1l, g_a1l);
    cudaGetSymbolAddress((void**)&b1h, g_b1h);
    cudaGetSymbolAddress((void**)&b1l, g_b1l);
    cudaGetSymbolAddress((void**)&a2h, g_a2h);
    cudaGetSymbolAddress((void**)&a2l, g_a2l);
    cudaGetSymbolAddress((void**)&b2h, g_b2h);
    cudaGetSymbolAddress((void**)&b2l, g_b2l);

    const size_t gemm_smem = 2 * 49152;   // 98304 -> 2 CTAs/SM
    const size_t diag_smem = (size_t)(128 * TS_STR + 64 * CS_STR + 2 * 64 * XS_STR + 192) * sizeof(float);
    const size_t yoff_smem = (size_t)(128 * TS_STR + 64 * CS2_STR + 64) * sizeof(float);   // ~50.3KB
    cudaFuncSetAttribute(hmma_gemm_kernel, cudaFuncAttributeMaxDynamicSharedMemorySize, (int)gemm_smem);
    cudaFuncSetAttribute(ssd_diag_kernel, cudaFuncAttributeMaxDynamicSharedMemorySize, (int)diag_smem);
    cudaFuncSetAttribute(yoff_kernel, cudaFuncAttributeMaxDynamicSharedMemorySize, (int)yoff_smem);

    // 0: fused prep (cvt u + transpose W_in + transpose W_out)
    prep_kernel<<<8576, 1024>>>(u, W_in, W_out, a1h, a1l, b1h, b1l, b2h, b2l);

    // 1: GEMM1 zx[8192,4384] = u @ W_in
    hmma_gemm_kernel<<<dim3(NPAD1 / 64, MROWS / 128), 256, gemm_smem>>>(
        a1h, a1l, b1h, b1l, zx, DPROJ, DMODEL, DPROJ);

    // 2: conv
    conv_kernel<<<dim3(CONVCH / 256, MROWS / 16), 256>>>(conv_w, conv_b);

    // 3: SSD intra-chunk (profiled launch) — includes dt softplus + cumsum
    ssd_diag_kernel<<<BQ * NC * NH, 256, diag_smem>>>(A_log, dt_b);

    // 4: inter-chunk scan
    scan_kernel<<<(BQ * NH * HD * DSTATE) / 256, 256>>>();

    // 5: Y_off + skip
    yoff_kernel<<<BQ * NC * NH, 256, yoff_smem>>>(Dv);

    // 6: gate + rmsnorm (writes bf16 split A for GEMM2)
    gate_kernel<<<MROWS, 256>>>(norm_w, a2h, a2l);

    // 7: GEMM2 out[8192,1024] = y @ W_out
    hmma_gemm_kernel<<<dim3(DMODEL / 64, MROWS / 128), 256, gemm_smem>>>(
        a2h, a2l, b2h, b2l, out, DMODEL, DINNER, DMODEL);
}

// round 11
// speedup vs baseline: 1.5599x; 1.5599x over previous
#include <cuda_runtime.h>
#include <cuda_bf16.h>
#include <cuda_fp16.h>
#include <math.h>
#include <cstdint>

// ---------------- problem constants ----------------
#define BQ 2
#define LSEQ 4096
#define DMODEL 1024
#define DINNER 2048
#define NH 32
#define HD 64
#define DSTATE 128
#define CHK 64
#define NC 64
#define DPROJ 4384
#define CONVCH 2304
#define MROWS (BQ*LSEQ)
#define NPAD1 4480      // DPROJ padded to 128

// ---------------- scratch (device globals; no allocation) ----------------
__device__ float g_zx[(size_t)MROWS * DPROJ];
__device__ float g_xbc[(size_t)MROWS * CONVCH];
__device__ float g_acum[BQ * NC * NH * CHK];
__device__ float g_suma[BQ * NC * NH];
__device__ float g_states[(size_t)BQ * NC * NH * HD * DSTATE];
__device__ float g_y[(size_t)MROWS * DINNER];

// GEMM1 operands: bf16 hi/lo (3-product)
__device__ __nv_bfloat16 g_a1h[(size_t)MROWS * DMODEL];
__device__ __nv_bfloat16 g_a1l[(size_t)MROWS * DMODEL];
__device__ __nv_bfloat16 g_b1h[(size_t)NPAD1 * DMODEL];
__device__ __nv_bfloat16 g_b1l[(size_t)NPAD1 * DMODEL];
// GEMM2 operands: fp16 (A hi/lo 2-product, B single)
__device__ __half g_a2h[(size_t)MROWS * DINNER];
__device__ __half g_a2l[(size_t)MROWS * DINNER];
__device__ __half g_b2h[(size_t)DMODEL * DINNER];

// ---------------- PTX helpers ----------------
__device__ __forceinline__ uint32_t smem_u32(const void* p) {
    uint32_t a;
    asm("{ .reg .u64 t; cvta.to.shared.u64 t, %1; cvt.u32.u64 %0, t; }" : "=r"(a) : "l"(p));
    return a;
}
#define SMEM_SWIZZLE_128B(byte_offset) ((byte_offset) ^ (((byte_offset) >> 3) & 0x70))
#define CP_ASYNC16(dst, src) \
    asm volatile("cp.async.cg.shared.global [%0], [%1], 16;" :: "r"(dst), "l"(src) : "memory")
#define CP_COMMIT() asm volatile("cp.async.commit_group;" ::: "memory")
#define CP_WAIT0()  asm volatile("cp.async.wait_group 0;" ::: "memory")

#define LDSM_X4(r0,r1,r2,r3,addr) \
    asm volatile("ldmatrix.sync.aligned.m8n8.x4.shared.b16 {%0,%1,%2,%3}, [%4];" \
        : "=r"(r0), "=r"(r1), "=r"(r2), "=r"(r3) : "r"(addr))

#define MMA16816(d, a, b0, b1) \
    asm volatile("mma.sync.aligned.m16n8k16.row.col.f32.bf16.bf16.f32 " \
        "{%0,%1,%2,%3}, {%4,%5,%6,%7}, {%8,%9}, {%0,%1,%2,%3};" \
        : "+f"((d)[0]), "+f"((d)[1]), "+f"((d)[2]), "+f"((d)[3]) \
        : "r"((a)[0]), "r"((a)[1]), "r"((a)[2]), "r"((a)[3]), "r"(b0), "r"(b1))

#define MMAH16816(d, a, b0, b1) \
    asm volatile("mma.sync.aligned.m16n8k16.row.col.f32.f16.f16.f32 " \
        "{%0,%1,%2,%3}, {%4,%5,%6,%7}, {%8,%9}, {%0,%1,%2,%3};" \
        : "+f"((d)[0]), "+f"((d)[1]), "+f"((d)[2]), "+f"((d)[3]) \
        : "r"((a)[0]), "r"((a)[1]), "r"((a)[2]), "r"((a)[3]), "r"(b0), "r"(b1))

// packed f32x2 (2x fp32 FMA rate) for SSD kernels
#define FMA2(d, a, b) asm("fma.rn.f32x2 %0, %1, %2, %0;" : "+l"(d) : "l"(a), "l"(b))
#define MUL2(d, a, b) asm("mul.rn.f32x2 %0, %1, %2;" : "=l"(d) : "l"(a), "l"(b))
__device__ __forceinline__ uint64_t dup2(float x) {
    uint64_t r; asm("mov.b64 %0, {%1, %1};" : "=l"(r) : "f"(x)); return r;
}
__device__ __forceinline__ void up2(uint64_t v, float& lo, float& hi) {
    asm("mov.b64 {%0, %1}, %2;" : "=f"(lo), "=f"(hi) : "l"(v));
}

__device__ __forceinline__ void ldsmA(uint32_t base, int row, int ks, int lane, uint32_t* r) {
    int rr = row + (lane & 15);
    int off = rr * 128 + ks * 32 + ((lane >> 4) << 4);
    LDSM_X4(r[0], r[1], r[2], r[3], base + SMEM_SWIZZLE_128B((uint32_t)off));
}
__device__ __forceinline__ void ldsmB(uint32_t base, int nrow, int ks, int lane, uint32_t* r) {
    int n = nrow + ((lane >> 4) << 3) + (lane & 7);
    int off = n * 128 + ks * 32 + (((lane >> 3) & 1) << 4);
    LDSM_X4(r[0], r[1], r[2], r[3], base + SMEM_SWIZZLE_128B((uint32_t)off));
}

// ---------------- GEMM1: HMMA split-bf16, 3 products (96% of mma.sync floor) ----------------
__global__ __launch_bounds__(256, 2) void hmma_gemm_kernel(
    const __nv_bfloat16* __restrict__ Ah, const __nv_bfloat16* __restrict__ Al,
    const __nv_bfloat16* __restrict__ Bh, const __nv_bfloat16* __restrict__ Bl,
    float* __restrict__ C, int N, int K, int ldc)
{
    extern __shared__ char smem[];
    const uint32_t sb = smem_u32(smem);
    const int tid = threadIdx.x, wid = tid >> 5, lane = tid & 31;
    const int wr = wid & 3, wc = wid >> 2;
    const int rowbase = blockIdx.y * 128, colbase = blockIdx.x * 64;
    const int KC = K >> 6;

    float acc[2][4][4];
#pragma unroll
    for (int mi = 0; mi < 2; mi++)
#pragma unroll
        for (int ni = 0; ni < 4; ni++)
#pragma unroll
            for (int j = 0; j < 4; j++) acc[mi][ni][j] = 0.f;

    auto issue_chunk = [&](int i) {
        const uint32_t st = (uint32_t)(i & 1) * 49152u;
        const int k0 = i << 6;
#pragma unroll
        for (int v = 0; v < 12; v++) {
            const int idx = v * 256 + tid;
            const __nv_bfloat16* src;
            uint32_t dst;
            if (idx < 2048) {
                const int buf = idx >> 10;
                const int r = (idx & 1023) >> 3, c8 = idx & 7;
                src = (buf ? Al : Ah) + (size_t)(rowbase + r) * K + k0 + c8 * 8;
                dst = sb + st + (uint32_t)buf * 16384u +
                      SMEM_SWIZZLE_128B((uint32_t)(r * 128 + c8 * 16));
            } else {
                const int j = idx - 2048;
                const int buf = j >> 9;
                const int r = (j & 511) >> 3, c8 = j & 7;
                src = (buf ? Bl : Bh) + (size_t)(colbase + r) * K + k0 + c8 * 8;
                dst = sb + st + 32768u + (uint32_t)buf * 8192u +
                      SMEM_SWIZZLE_128B((uint32_t)(r * 128 + c8 * 16));
            }
            CP_ASYNC16(dst, src);
        }
    };

    issue_chunk(0);
    CP_COMMIT();

    for (int i = 0; i < KC; i++) {
        CP_WAIT0();
        __syncthreads();
        if (i + 1 < KC) { issue_chunk(i + 1); CP_COMMIT(); }

        const uint32_t st = sb + (uint32_t)(i & 1) * 49152u;
        const uint32_t aH = st, aL = st + 16384u, bH = st + 32768u, bL = st + 40960u;
#pragma unroll
        for (int ks = 0; ks < 4; ks++) {
            uint32_t ah[2][4], al[2][4], bh[2][4], bl[2][4];
#pragma unroll
            for (int mi = 0; mi < 2; mi++) {
                ldsmA(aH, wr * 32 + mi * 16, ks, lane, ah[mi]);
                ldsmA(aL, wr * 32 + mi * 16, ks, lane, al[mi]);
            }
#pragma unroll
            for (int np = 0; np < 2; np++) {
                ldsmB(bH, wc * 32 + np * 16, ks, lane, bh[np]);
                ldsmB(bL, wc * 32 + np * 16, ks, lane, bl[np]);
            }
#pragma unroll
            for (int mi = 0; mi < 2; mi++)
#pragma unroll
                for (int ni = 0; ni < 4; ni++) {
                    const int np = ni >> 1, o = (ni & 1) << 1;
                    MMA16816(acc[mi][ni], ah[mi], bh[np][o], bh[np][o + 1]);
                    MMA16816(acc[mi][ni], ah[mi], bl[np][o], bl[np][o + 1]);
                    MMA16816(acc[mi][ni], al[mi], bh[np][o], bh[np][o + 1]);
                }
        }
        __syncthreads();
    }

#pragma unroll
    for (int mi = 0; mi < 2; mi++) {
        const int row = rowbase + wr * 32 + mi * 16 + (lane >> 2);
#pragma unroll
        for (int ni = 0; ni < 4; ni++) {
            const int col = colbase + wc * 32 + ni * 8 + (lane & 3) * 2;
            if (col < N) {
                *reinterpret_cast<float2*>(&C[(size_t)row * ldc + col]) =
                    make_float2(acc[mi][ni][0], acc[mi][ni][1]);
                *reinterpret_cast<float2*>(&C[(size_t)(row + 8) * ldc + col]) =
                    make_float2(acc[mi][ni][2], acc[mi][ni][3]);
            }
        }
    }
}

// ---------------- GEMM2: fp16 2-product (A hi/lo fp16, B single fp16) ----------------
// CTA 128x64, stage: Ah [0,16K) Al [16K,32K) Bh [32K,40K) -> 40KB/stage, 80KB total, 2 CTAs/SM
__global__ __launch_bounds__(256, 2) void hgemm2_kernel(
    const __half* __restrict__ Ah, const __half* __restrict__ Al,
    const __half* __restrict__ Bh, float* __restrict__ C, int N, int K, int ldc)
{
    extern __shared__ char smem[];
    const uint32_t sb = smem_u32(smem);
    const int tid = threadIdx.x, wid = tid >> 5, lane = tid & 31;
    const int wr = wid & 3, wc = wid >> 2;
    const int rowbase = blockIdx.y * 128, colbase = blockIdx.x * 64;
    const int KC = K >> 6;

    float acc[2][4][4];
#pragma unroll
    for (int mi = 0; mi < 2; mi++)
#pragma unroll
        for (int ni = 0; ni < 4; ni++)
#pragma unroll
            for (int j = 0; j < 4; j++) acc[mi][ni][j] = 0.f;

    auto issue_chunk = [&](int i) {
        const uint32_t st = (uint32_t)(i & 1) * 40960u;
        const int k0 = i << 6;
#pragma unroll
        for (int v = 0; v < 10; v++) {
            const int idx = v * 256 + tid;     // 0..2559
            const __half* src;
            uint32_t dst;
            if (idx < 2048) {
                const int buf = idx >> 10;
                const int r = (idx & 1023) >> 3, c8 = idx & 7;
                src = (buf ? Al : Ah) + (size_t)(rowbase + r) * K + k0 + c8 * 8;
                dst = sb + st + (uint32_t)buf * 16384u +
                      SMEM_SWIZZLE_128B((uint32_t)(r * 128 + c8 * 16));
            } else {
                const int j = idx - 2048;      // 0..511
                const int r = j >> 3, c8 = j & 7;
                src = Bh + (size_t)(colbase + r) * K + k0 + c8 * 8;
                dst = sb + st + 32768u + SMEM_SWIZZLE_128B((uint32_t)(r * 128 + c8 * 16));
            }
            CP_ASYNC16(dst, src);
        }
    };

    issue_chunk(0);
    CP_COMMIT();

    for (int i = 0; i < KC; i++) {
        CP_WAIT0();
        __syncthreads();
        if (i + 1 < KC) { issue_chunk(i + 1); CP_COMMIT(); }

        const uint32_t st = sb + (uint32_t)(i & 1) * 40960u;
        const uint32_t aH = st, aL = st + 16384u, bH = st + 32768u;
#pragma unroll
        for (int ks = 0; ks < 4; ks++) {
            uint32_t ah[2][4], al[2][4], bh[2][4];
#pragma unroll
            for (int mi = 0; mi < 2; mi++) {
                ldsmA(aH, wr * 32 + mi * 16, ks, lane, ah[mi]);
                ldsmA(aL, wr * 32 + mi * 16, ks, lane, al[mi]);
            }
#pragma unroll
            for (int np = 0; np < 2; np++)
                ldsmB(bH, wc * 32 + np * 16, ks, lane, bh[np]);
#pragma unroll
            for (int mi = 0; mi < 2; mi++)
#pragma unroll
                for (int ni = 0; ni < 4; ni++) {
                    const int np = ni >> 1, o = (ni & 1) << 1;
                    MMAH16816(acc[mi][ni], ah[mi], bh[np][o], bh[np][o + 1]);
                    MMAH16816(acc[mi][ni], al[mi], bh[np][o], bh[np][o + 1]);
                }
        }
        __syncthreads();
    }

#pragma unroll
    for (int mi = 0; mi < 2; mi++) {
        const int row = rowbase + wr * 32 + mi * 16 + (lane >> 2);
#pragma unroll
        for (int ni = 0; ni < 4; ni++) {
            const int col = colbase + wc * 32 + ni * 8 + (lane & 3) * 2;
            if (col < N) {
                *reinterpret_cast<float2*>(&C[(size_t)row * ldc + col]) =
                    make_float2(acc[mi][ni][0], acc[mi][ni][1]);
                *reinterpret_cast<float2*>(&C[(size_t)(row + 8) * ldc + col]) =
                    make_float2(acc[mi][ni][2], acc[mi][ni][3]);
            }
        }
    }
}

// ---------------- fused prep: cvt_split(u) + transpose_split(W_in) + transpose_fp16(W_out) ----
__global__ __launch_bounds__(1024) void prep_kernel(
    const float* __restrict__ u, const float* __restrict__ W_in, const float* __restrict__ W_out,
    __nv_bfloat16* __restrict__ a1h, __nv_bfloat16* __restrict__ a1l,
    __nv_bfloat16* __restrict__ b1h, __nv_bfloat16* __restrict__ b1l,
    __half* __restrict__ b2h)
{
    __shared__ float t[32][33];
    const int bx = blockIdx.x, tid = threadIdx.x;
    if (bx < 2048) {
        int i = bx * 1024 + tid;
        float4 x = reinterpret_cast<const float4*>(u)[i];
        float xs[4] = {x.x, x.y, x.z, x.w};
        __nv_bfloat16 h[4], l[4];
#pragma unroll
        for (int j = 0; j < 4; j++) {
            h[j] = __float2bfloat16(xs[j]);
            l[j] = __float2bfloat16(xs[j] - __bfloat162float(h[j]));
        }
        reinterpret_cast<__nv_bfloat162*>(a1h)[2 * i]     = __nv_bfloat162(h[0], h[1]);
        reinterpret_cast<__nv_bfloat162*>(a1h)[2 * i + 1] = __nv_bfloat162(h[2], h[3]);
        reinterpret_cast<__nv_bfloat162*>(a1l)[2 * i]     = __nv_bfloat162(l[0], l[1]);
        reinterpret_cast<__nv_bfloat162*>(a1l)[2 * i + 1] = __nv_bfloat162(l[2], l[3]);
        return;
    }
    const int tx = tid & 31, ty = tid >> 5;
    if (bx < 2048 + 4480) {                 // W_in -> b1h/b1l (bf16 hi/lo)
        int bb = bx - 2048;
        int bxx = bb % 140, byy = bb / 140;
        int n = bxx * 32 + tx, k = byy * 32 + ty;
        t[ty][tx] = (n < DPROJ) ? W_in[(size_t)k * DPROJ + n] : 0.f;
        __syncthreads();
        int nn = bxx * 32 + ty, kk = byy * 32 + tx;
        float v = t[tx][ty];
        __nv_bfloat16 h = __float2bfloat16(v);
        b1h[(size_t)nn * DMODEL + kk] = h;
        b1l[(size_t)nn * DMODEL + kk] = __float2bfloat16(v - __bfloat162float(h));
    } else {                                // W_out -> b2h (fp16 single)
        int bb = bx - 6528;
        int bxx = bb % 32, byy = bb / 32;
        int n = bxx * 32 + tx, k = byy * 32 + ty;
        t[ty][tx] = W_out[(size_t)k * DMODEL + n];
        __syncthreads();
        int nn = bxx * 32 + ty, kk = byy * 32 + tx;
        b2h[(size_t)nn * DINNER + kk] = __float2half(t[tx][ty]);
    }
}

// ---------------- depthwise causal conv(4) + bias + SiLU (smem-tiled) ----------------
__global__ __launch_bounds__(256) void conv_kernel(const float* __restrict__ cw,
                                                   const float* __restrict__ cb) {
    __shared__ float s[19][256];
    int tid = threadIdx.x;
    int ch = blockIdx.x * 256 + tid;
    int m0 = blockIdx.y * 16;
    int l0 = m0 & (LSEQ - 1);
#pragma unroll
    for (int r = 0; r < 19; r++) {
        int l = l0 - 3 + r;
        s[r][tid] = (l >= 0) ? g_zx[(size_t)(m0 - 3 + r) * DPROJ + DINNER + ch] : 0.f;
    }
    __syncthreads();
    float w0 = cw[ch * 4], w1 = cw[ch * 4 + 1], w2 = cw[ch * 4 + 2], w3 = cw[ch * 4 + 3];
    float bias = cb[ch];
#pragma unroll
    for (int r = 0; r < 16; r++) {
        float acc = bias;
        acc = fmaf(s[r][tid], w0, acc);
        acc = fmaf(s[r + 1][tid], w1, acc);
        acc = fmaf(s[r + 2][tid], w2, acc);
        acc = fmaf(s[r + 3][tid], w3, acc);
        g_xbc[(size_t)(m0 + r) * CONVCH + ch] = acc / (1.f + expf(-acc));
    }
}

// ---------------- SSD intra-chunk (dt softplus + warp-shfl cumsum inline; 2 CTAs/SM) -------
#define TS_STR 66
#define CS_STR 132
#define XS_STR 68
__global__ __launch_bounds__(256, 2) void ssd_diag_kernel(const float* __restrict__ A_log,
                                                          const float* __restrict__ dt_bias) {
    int blk = blockIdx.x;
    int h = blk & 31;
    int c = (blk >> 5) & 63;
    int b = blk >> 11;
    int m0 = b * LSEQ + c * CHK;

    extern __shared__ float sm[];
    float* Bst = sm;                         // 128*66
    float* Cs  = Bst + 128 * TS_STR;         // 64*132
    float* xs  = Cs + 64 * CS_STR;           // 64*68
    float* Gs  = xs + 64 * XS_STR;           // 64*68
    float* ac  = Gs + 64 * XS_STR;           // 64
    float* wd  = ac + 64;                    // 64
    float* dts = wd + 64;                    // 64
    int tid = threadIdx.x;

    // --- dt + cumsum(A*dt): single warp, shfl scan (2 elems/lane) ---
    if (tid < 32) {
        float A = -expf(A_log[h]);
        float bias = dt_bias[h];
        float r0v = g_zx[(size_t)(m0 + 2 * tid) * DPROJ + (DPROJ - NH) + h] + bias;
        float r1v = g_zx[(size_t)(m0 + 2 * tid + 1) * DPROJ + (DPROJ - NH) + h] + bias;
        float dt0 = (r0v > 20.f) ? r0v : log1pf(expf(r0v));
        float dt1 = (r1v > 20.f) ? r1v : log1pf(expf(r1v));
        dts[2 * tid] = dt0;
        dts[2 * tid + 1] = dt1;
        float e0 = A * dt0, e1 = A * dt1;
        float s = e0 + e1, run = s;
#pragma unroll
        for (int off = 1; off < 32; off <<= 1) {
            float v = __shfl_up_sync(0xFFFFFFFFu, run, off);
            if (tid >= off) run += v;
        }
        ac[2 * tid]     = run - e1;
        ac[2 * tid + 1] = run;
    }
    __syncthreads();
    if (tid < 64) {
        wd[tid] = expf(ac[63] - ac[tid]);
        g_acum[blk * CHK + tid] = ac[tid];
    }
    if (tid == 0) g_suma[blk] = expf(ac[63]);

    // --- tile loads ---
    for (int i = tid; i < 64 * 128; i += 256) {
        int l = i >> 7, n = i & 127;
        Bst[n * TS_STR + l] = g_xbc[(size_t)(m0 + l) * CONVCH + DINNER + n];
    }
    for (int i = tid; i < 64 * 32; i += 256) {
        int l = i >> 5, q = i & 31;
        float4 v = *reinterpret_cast<const float4*>(
            g_xbc + (size_t)(m0 + l) * CONVCH + DINNER + DSTATE + 4 * q);
        *reinterpret_cast<float4*>(Cs + l * CS_STR + 4 * q) = v;
    }
    for (int i = tid; i < 64 * 16; i += 256) {
        int l = i >> 4, q = i & 15;
        float dtv = dts[l];
        float4 v = *reinterpret_cast<const float4*>(
            g_xbc + (size_t)(m0 + l) * CONVCH + h * HD + 4 * q);
        v.x *= dtv; v.y *= dtv; v.z *= dtv; v.w *= dtv;
        *reinterpret_cast<float4*>(xs + l * XS_STR + 4 * q) = v;
    }
    __syncthreads();

    const int tr = tid >> 4, tc = tid & 15;
    const int r0 = tr * 4, c0 = tc * 4;

    // --- G[l][s] = C[l]·B[s] (lower-tri tiles only) ---
    if (tc <= tr) {
        uint64_t acc2[4][2] = {{0ull,0ull},{0ull,0ull},{0ull,0ull},{0ull,0ull}};
        for (int n4 = 0; n4 < 128; n4 += 4) {
            float4 cr[4];
#pragma unroll
            for (int i = 0; i < 4; i++)
                cr[i] = *reinterpret_cast<const float4*>(Cs + (r0 + i) * CS_STR + n4);
#pragma unroll
            for (int nn = 0; nn < 4; nn++) {
                uint64_t b0 = *reinterpret_cast<const uint64_t*>(Bst + (n4 + nn) * TS_STR + c0);
                uint64_t b1 = *reinterpret_cast<const uint64_t*>(Bst + (n4 + nn) * TS_STR + c0 + 2);
#pragma unroll
                for (int i = 0; i < 4; i++) {
                    uint64_t a2 = dup2((&cr[i].x)[nn]);
                    FMA2(acc2[i][0], a2, b0);
                    FMA2(acc2[i][1], a2, b1);
                }
            }
        }
#pragma unroll
        for (int i = 0; i < 4; i++) {
            int l = r0 + i;
            float al = ac[l];
            float v0, v1, v2, v3;
            up2(acc2[i][0], v0, v1);
            up2(acc2[i][1], v2, v3);
            float4 o;
            o.x = (c0     <= l) ? v0 * expf(al - ac[c0])     : 0.f;
            o.y = (c0 + 1 <= l) ? v1 * expf(al - ac[c0 + 1]) : 0.f;
            o.z = (c0 + 2 <= l) ? v2 * expf(al - ac[c0 + 2]) : 0.f;
            o.w = (c0 + 3 <= l) ? v3 * expf(al - ac[c0 + 3]) : 0.f;
            *reinterpret_cast<float4*>(Gs + l * XS_STR + c0) = o;
        }
    }
    __syncthreads();

    // --- Y_diag[l][p] = sum_{s<=l} G[l][s]*x[s][p] ---
    {
        uint64_t acc2[4][2] = {{0ull,0ull},{0ull,0ull},{0ull,0ull},{0ull,0ull}};
        for (int s4 = 0; s4 < r0 + 4; s4 += 4) {
            float4 gr[4];
#pragma unroll
            for (int i = 0; i < 4; i++)
                gr[i] = *reinterpret_cast<const float4*>(Gs + (r0 + i) * XS_STR + s4);
#pragma unroll
            for (int ss = 0; ss < 4; ss++) {
                uint64_t x0 = *reinterpret_cast<const uint64_t*>(xs + (s4 + ss) * XS_STR + c0);
                uint64_t x1 = *reinterpret_cast<const uint64_t*>(xs + (s4 + ss) * XS_STR + c0 + 2);
#pragma unroll
                for (int i = 0; i < 4; i++) {
                    uint64_t a2 = dup2((&gr[i].x)[ss]);
                    FMA2(acc2[i][0], a2, x0);
                    FMA2(acc2[i][1], a2, x1);
                }
            }
        }
#pragma unroll
        for (int i = 0; i < 4; i++) {
            float v0, v1, v2, v3;
            up2(acc2[i][0], v0, v1);
            up2(acc2[i][1], v2, v3);
            *reinterpret_cast<float4*>(g_y + (size_t)(m0 + r0 + i) * DINNER + h * HD + c0) =
                make_float4(v0, v1, v2, v3);
        }
    }

    // --- states S[p][n] = sum_l wd[l]*x[l][p]*B[l][n] ---
    {
        const int p0 = (tid & 15) * 4, n0 = (tid >> 4) * 8;
        uint64_t acc2[2][8];
#pragma unroll
        for (int pp = 0; pp < 2; pp++)
#pragma unroll
            for (int j = 0; j < 8; j++) acc2[pp][j] = 0ull;
        for (int l = 0; l < 64; l++) {
            uint64_t w2 = dup2(wd[l]);
            uint64_t xa = *reinterpret_cast<const uint64_t*>(xs + l * XS_STR + p0);
            uint64_t xb = *reinterpret_cast<const uint64_t*>(xs + l * XS_STR + p0 + 2);
            uint64_t wxa, wxb;
            MUL2(wxa, xa, w2);
            MUL2(wxb, xb, w2);
#pragma unroll
            for (int j = 0; j < 8; j++) {
                uint64_t b2 = dup2(Bst[(n0 + j) * TS_STR + l]);
                FMA2(acc2[0][j], wxa, b2);
                FMA2(acc2[1][j], wxb, b2);
            }
        }
        float rowv[4][8];
#pragma unroll
        for (int pp = 0; pp < 2; pp++)
#pragma unroll
            for (int j = 0; j < 8; j++)
                up2(acc2[pp][j], rowv[2 * pp][j], rowv[2 * pp + 1][j]);
#pragma unroll
        for (int i = 0; i < 4; i++) {
            float* dst = g_states + ((size_t)blk * HD + p0 + i) * DSTATE + n0;
            *reinterpret_cast<float4*>(dst)     = make_float4(rowv[i][0], rowv[i][1], rowv[i][2], rowv[i][3]);
            *reinterpret_cast<float4*>(dst + 4) = make_float4(rowv[i][4], rowv[i][5], rowv[i][6], rowv[i][7]);
        }
    }
}

// ---------------- inter-chunk scan (prefetched) ----------------
__global__ void scan_kernel() {
    int idx = blockIdx.x * blockDim.x + threadIdx.x;
    int n = idx & 127;
    int p = (idx >> 7) & 63;
    int h = (idx >> 13) & 31;
    int b = idx >> 18;
    const size_t cstep = (size_t)NH * HD * DSTATE;
    int bch0 = b * NC * NH + h;
    size_t off = ((size_t)bch0 * HD + p) * DSTATE + n;
    float prev = 0.f;
    float loc = g_states[off];
    for (int c = 0; c < NC; c++) {
        float nxt = (c + 1 < NC) ? g_states[off + cstep] : 0.f;
        float e = g_suma[bch0 + c * NH];
        g_states[off] = prev;
        prev = fmaf(prev, e, loc);
        loc = nxt;
        off += cstep;
    }
}

// ---------------- Y_off + skip (f32x2, half-C double pass, 2 CTAs/SM) ----------------
#define CS2_STR 68
__global__ __launch_bounds__(256, 2) void yoff_kernel(const float* __restrict__ Dv) {
    int blk = blockIdx.x;
    int h = blk & 31;
    int c = (blk >> 5) & 63;
    int b = blk >> 11;
    int m0 = b * LSEQ + c * CHK;

    extern __shared__ float sm[];
    float* Pst = sm;                        // 128 x stride 66 ([n][p])
    float* Cs2 = Pst + 128 * TS_STR;        // 64 x stride 68 (half of C)
    float* ac  = Cs2 + 64 * CS2_STR;        // 64
    int tid = threadIdx.x;

    for (int i = tid; i < 64 * 128; i += 256) {
        int p = i >> 7, n = i & 127;
        Pst[n * TS_STR + p] = g_states[((size_t)blk * HD + p) * DSTATE + n];
    }
    if (tid < 64) ac[tid] = g_acum[blk * CHK + tid];
    float Dh = Dv[h];

    const int tr = tid >> 4, tc = tid & 15;
    const int r0 = tr * 4, c0 = tc * 4;
    uint64_t acc2[4][2] = {{0ull,0ull},{0ull,0ull},{0ull,0ull},{0ull,0ull}};

#pragma unroll
    for (int half = 0; half < 2; half++) {
        __syncthreads();
        for (int i = tid; i < 64 * 16; i += 256) {
            int l = i >> 4, q = i & 15;
            float4 v = *reinterpret_cast<const float4*>(
                g_xbc + (size_t)(m0 + l) * CONVCH + DINNER + DSTATE + half * 64 + 4 * q);
            *reinterpret_cast<float4*>(Cs2 + l * CS2_STR + 4 * q) = v;
        }
        __syncthreads();
        for (int n4 = 0; n4 < 64; n4 += 4) {
            float4 cr[4];
#pragma unroll
            for (int i = 0; i < 4; i++)
                cr[i] = *reinterpret_cast<const float4*>(Cs2 + (r0 + i) * CS2_STR + n4);
#pragma unroll
            for (int nn = 0; nn < 4; nn++) {
                int n = half * 64 + n4 + nn;
                uint64_t p0v = *reinterpret_cast<const uint64_t*>(Pst + n * TS_STR + c0);
                uint64_t p1v = *reinterpret_cast<const uint64_t*>(Pst + n * TS_STR + c0 + 2);
#pragma unroll
                for (int i = 0; i < 4; i++) {
                    uint64_t a2 = dup2((&cr[i].x)[nn]);
                    FMA2(acc2[i][0], a2, p0v);
                    FMA2(acc2[i][1], a2, p1v);
                }
            }
        }
    }

#pragma unroll
    for (int i = 0; i < 4; i++) {
        int l = r0 + i;
        int row = m0 + l;
        float el = expf(ac[l]);
        float v0, v1, v2, v3;
        up2(acc2[i][0], v0, v1);
        up2(acc2[i][1], v2, v3);
        float4 xv = *reinterpret_cast<const float4*>(
            g_xbc + (size_t)row * CONVCH + h * HD + c0);
        float4* yp = reinterpret_cast<float4*>(g_y + (size_t)row * DINNER + h * HD + c0);
        float4 yv = *yp;
        yv.x += v0 * el + xv.x * Dh;
        yv.y += v1 * el + xv.y * Dh;
        yv.z += v2 * el + xv.z * Dh;
        yv.w += v3 * el + xv.w * Dh;
        *yp = yv;
    }
}

// ---------------- gate (silu(z)) + RMSNorm, fused fp16 split output ----------------
__global__ void gate_kernel(const float* __restrict__ norm_w,
                            __half* __restrict__ a2h, __half* __restrict__ a2l) {
    int m = blockIdx.x;
    int tid = threadIdx.x;
    __shared__ float red[256];
    float tv[8];
    float ss = 0.f;
#pragma unroll
    for (int j = 0; j < 8; j++) {
        int i = tid + 256 * j;
        float zv = g_zx[(size_t)m * DPROJ + i];
        float yv = g_y[(size_t)m * DINNER + i];
        float g = yv * (zv / (1.f + expf(-zv)));
        tv[j] = g;
        ss += g * g;
    }
    red[tid] = ss;
    __syncthreads();
    for (int s = 128; s > 0; s >>= 1) {
        if (tid < s) red[tid] += red[tid + s];
        __syncthreads();
    }
    float scale = rsqrtf(red[0] / (float)DINNER + 1e-5f);
#pragma unroll
    for (int j = 0; j < 8; j++) {
        int i = tid + 256 * j;
        float val = tv[j] * scale * norm_w[i];
        __half hv = __float2half(val);
        a2h[(size_t)m * DINNER + i] = hv;
        a2l[(size_t)m * DINNER + i] = __float2half(val - __half2float(hv));
    }
}

// ---------------- launch ----------------
extern "C" void kernel_launch(void* const* d_in, const int* in_sizes, int n_in,
                              void* d_out, int out_size) {
    const float* u      = (const float*)d_in[0];
    const float* W_in   = (const float*)d_in[1];
    const float* conv_w = (const float*)d_in[2];
    const float* conv_b = (const float*)d_in[3];
    const float* dt_b   = (const float*)d_in[4];
    const float* A_log  = (const float*)d_in[5];
    const float* Dv     = (const float*)d_in[6];
    const float* norm_w = (const float*)d_in[7];
    const float* W_out  = (const float*)d_in[8];
    float* out = (float*)d_out;

    float* zx = nullptr;
    cudaGetSymbolAddress((void**)&zx, g_zx);
    __nv_bfloat16 *a1h, *a1l, *b1h, *b1l;
    __half *a2h, *a2l, *b2h;
    cudaGetSymbolAddress((void**)&a1h, g_a1h);
    cudaGetSymbolAddress((void**)&a1l, g_a1l);
    cudaGetSymbolAddress((void**)&b1h, g_b1h);
    cudaGetSymbolAddress((void**)&b1l, g_b1l);
    cudaGetSymbolAddress((void**)&a2h, g_a2h);
    cudaGetSymbolAddress((void**)&a2l, g_a2l);
    cudaGetSymbolAddress((void**)&b2h, g_b2h);

    const size_t gemm_smem  = 2 * 49152;   // 98304 (GEMM1)
    const size_t gemm2_smem = 2 * 40960;   // 81920 (GEMM2 fp16)
    const size_t diag_smem = (size_t)(128 * TS_STR + 64 * CS_STR + 2 * 64 * XS_STR + 192) * sizeof(float); // 103168
    const size_t yoff_smem = (size_t)(128 * TS_STR + 64 * CS2_STR + 64) * sizeof(float);
    cudaFuncSetAttribute(hmma_gemm_kernel, cudaFuncAttributeMaxDynamicSharedMemorySize, (int)gemm_smem);
    cudaFuncSetAttribute(hgemm2_kernel, cudaFuncAttributeMaxDynamicSharedMemorySize, (int)gemm2_smem);
    cudaFuncSetAttribute(ssd_diag_kernel, cudaFuncAttributeMaxDynamicSharedMemorySize, (int)diag_smem);
    cudaFuncSetAttribute(yoff_kernel, cudaFuncAttributeMaxDynamicSharedMemorySize, (int)yoff_smem);

    // 0: fused prep
    prep_kernel<<<8576, 1024>>>(u, W_in, W_out, a1h, a1l, b1h, b1l, b2h);

    // 1: GEMM1 zx[8192,4384] = u @ W_in (bf16, 3-product)
    hmma_gemm_kernel<<<dim3(NPAD1 / 64, MROWS / 128), 256, gemm_smem>>>(
        a1h, a1l, b1h, b1l, zx, DPROJ, DMODEL, DPROJ);

    // 2: conv
    conv_kernel<<<dim3(CONVCH / 256, MROWS / 16), 256>>>(conv_w, conv_b);

    // 3: SSD intra-chunk (profiled launch; 2 CTAs/SM target)
    ssd_diag_kernel<<<BQ * NC * NH, 256, diag_smem>>>(A_log, dt_b);

    // 4: inter-chunk scan (prefetched)
    scan_kernel<<<(BQ * NH * HD * DSTATE) / 256, 256>>>();

    // 5: Y_off + skip
    yoff_kernel<<<BQ * NC * NH, 256, yoff_smem>>>(Dv);

    // 6: gate + rmsnorm (writes fp16 split A for GEMM2)
    gate_kernel<<<MROWS, 256>>>(norm_w, a2h, a2l);

    // 7: GEMM2 out[8192,1024] = y @ W_out (fp16, 2-product)
    hgemm2_kernel<<<dim3(DMODEL / 64, MROWS / 128), 256, gemm2_smem>>>(
        a2h, a2l, b2h, out, DMODEL, DINNER, DMODEL);
}

// round 12
// speedup vs baseline: 1.5832x; 1.0149x over previous
#include <cuda_runtime.h>
#include <cuda_bf16.h>
#include <cuda_fp16.h>
#include <math.h>
#include <cstdint>

// ---------------- problem constants ----------------
#define BQ 2
#define LSEQ 4096
#define DMODEL 1024
#define DINNER 2048
#define NH 32
#define HD 64
#define DSTATE 128
#define CHK 64
#define NC 64
#define DPROJ 4384
#define CONVCH 2304
#define MROWS (BQ*LSEQ)
#define NPAD1 4480      // DPROJ padded to 128

// ---------------- scratch (device globals; no allocation) ----------------
__device__ float g_zx[(size_t)MROWS * DPROJ];
__device__ float g_xbc[(size_t)MROWS * CONVCH];
__device__ float g_dt[MROWS * NH];
__device__ float g_acum[BQ * NC * NH * CHK];
__device__ float g_suma[BQ * NC * NH];
__device__ float g_states[(size_t)BQ * NC * NH * HD * DSTATE];
__device__ float g_y[(size_t)MROWS * DINNER];

// GEMM operands: fp16, A hi/lo 2-product, B single
__device__ __half g_a1h[(size_t)MROWS * DMODEL];
__device__ __half g_a1l[(size_t)MROWS * DMODEL];
__device__ __half g_b1h[(size_t)NPAD1 * DMODEL];
__device__ __half g_a2h[(size_t)MROWS * DINNER];
__device__ __half g_a2l[(size_t)MROWS * DINNER];
__device__ __half g_b2h[(size_t)DMODEL * DINNER];

// ---------------- PTX helpers ----------------
__device__ __forceinline__ uint32_t smem_u32(const void* p) {
    uint32_t a;
    asm("{ .reg .u64 t; cvta.to.shared.u64 t, %1; cvt.u32.u64 %0, t; }" : "=r"(a) : "l"(p));
    return a;
}
#define SMEM_SWIZZLE_128B(byte_offset) ((byte_offset) ^ (((byte_offset) >> 3) & 0x70))
#define CP_ASYNC16(dst, src) \
    asm volatile("cp.async.cg.shared.global [%0], [%1], 16;" :: "r"(dst), "l"(src) : "memory")
#define CP_COMMIT() asm volatile("cp.async.commit_group;" ::: "memory")
#define CP_WAIT0()  asm volatile("cp.async.wait_group 0;" ::: "memory")

#define LDSM_X4(r0,r1,r2,r3,addr) \
    asm volatile("ldmatrix.sync.aligned.m8n8.x4.shared.b16 {%0,%1,%2,%3}, [%4];" \
        : "=r"(r0), "=r"(r1), "=r"(r2), "=r"(r3) : "r"(addr))

#define MMAH16816(d, a, b0, b1) \
    asm volatile("mma.sync.aligned.m16n8k16.row.col.f32.f16.f16.f32 " \
        "{%0,%1,%2,%3}, {%4,%5,%6,%7}, {%8,%9}, {%0,%1,%2,%3};" \
        : "+f"((d)[0]), "+f"((d)[1]), "+f"((d)[2]), "+f"((d)[3]) \
        : "r"((a)[0]), "r"((a)[1]), "r"((a)[2]), "r"((a)[3]), "r"(b0), "r"(b1))

// packed f32x2 (2x fp32 FMA rate) for SSD kernels
#define FMA2(d, a, b) asm("fma.rn.f32x2 %0, %1, %2, %0;" : "+l"(d) : "l"(a), "l"(b))
#define MUL2(d, a, b) asm("mul.rn.f32x2 %0, %1, %2;" : "=l"(d) : "l"(a), "l"(b))
__device__ __forceinline__ uint64_t dup2(float x) {
    uint64_t r; asm("mov.b64 %0, {%1, %1};" : "=l"(r) : "f"(x)); return r;
}
__device__ __forceinline__ void up2(uint64_t v, float& lo, float& hi) {
    asm("mov.b64 {%0, %1}, %2;" : "=f"(lo), "=f"(hi) : "l"(v));
}

__device__ __forceinline__ void ldsmA(uint32_t base, int row, int ks, int lane, uint32_t* r) {
    int rr = row + (lane & 15);
    int off = rr * 128 + ks * 32 + ((lane >> 4) << 4);
    LDSM_X4(r[0], r[1], r[2], r[3], base + SMEM_SWIZZLE_128B((uint32_t)off));
}
__device__ __forceinline__ void ldsmB(uint32_t base, int nrow, int ks, int lane, uint32_t* r) {
    int n = nrow + ((lane >> 4) << 3) + (lane & 7);
    int off = n * 128 + ks * 32 + (((lane >> 3) & 1) << 4);
    LDSM_X4(r[0], r[1], r[2], r[3], base + SMEM_SWIZZLE_128B((uint32_t)off));
}

// ---------------- fp16 2-product GEMM: C[M,N] = A(hi+lo)[M,K] @ Bt[N,K]^T ----------------
// CTA 128x64, stage: Ah [0,16K) Al [16K,32K) Bh [32K,40K) -> 40KB/stage, 80KB, 2 CTAs/SM
__global__ __launch_bounds__(256, 2) void hgemm_kernel(
    const __half* __restrict__ Ah, const __half* __restrict__ Al,
    const __half* __restrict__ Bh, float* __restrict__ C, int N, int K, int ldc)
{
    extern __shared__ char smem[];
    const uint32_t sb = smem_u32(smem);
    const int tid = threadIdx.x, wid = tid >> 5, lane = tid & 31;
    const int wr = wid & 3, wc = wid >> 2;
    const int rowbase = blockIdx.y * 128, colbase = blockIdx.x * 64;
    const int KC = K >> 6;

    float acc[2][4][4];
#pragma unroll
    for (int mi = 0; mi < 2; mi++)
#pragma unroll
        for (int ni = 0; ni < 4; ni++)
#pragma unroll
            for (int j = 0; j < 4; j++) acc[mi][ni][j] = 0.f;

    auto issue_chunk = [&](int i) {
        const uint32_t st = (uint32_t)(i & 1) * 40960u;
        const int k0 = i << 6;
#pragma unroll
        for (int v = 0; v < 10; v++) {
            const int idx = v * 256 + tid;     // 0..2559
            const __half* src;
            uint32_t dst;
            if (idx < 2048) {
                const int buf = idx >> 10;
                const int r = (idx & 1023) >> 3, c8 = idx & 7;
                src = (buf ? Al : Ah) + (size_t)(rowbase + r) * K + k0 + c8 * 8;
                dst = sb + st + (uint32_t)buf * 16384u +
                      SMEM_SWIZZLE_128B((uint32_t)(r * 128 + c8 * 16));
            } else {
                const int j = idx - 2048;      // 0..511
                const int r = j >> 3, c8 = j & 7;
                src = Bh + (size_t)(colbase + r) * K + k0 + c8 * 8;
                dst = sb + st + 32768u + SMEM_SWIZZLE_128B((uint32_t)(r * 128 + c8 * 16));
            }
            CP_ASYNC16(dst, src);
        }
    };

    issue_chunk(0);
    CP_COMMIT();

    for (int i = 0; i < KC; i++) {
        CP_WAIT0();
        __syncthreads();
        if (i + 1 < KC) { issue_chunk(i + 1); CP_COMMIT(); }

        const uint32_t st = sb + (uint32_t)(i & 1) * 40960u;
        const uint32_t aH = st, aL = st + 16384u, bH = st + 32768u;
#pragma unroll
        for (int ks = 0; ks < 4; ks++) {
            uint32_t ah[2][4], al[2][4], bh[2][4];
#pragma unroll
            for (int mi = 0; mi < 2; mi++) {
                ldsmA(aH, wr * 32 + mi * 16, ks, lane, ah[mi]);
                ldsmA(aL, wr * 32 + mi * 16, ks, lane, al[mi]);
            }
#pragma unroll
            for (int np = 0; np < 2; np++)
                ldsmB(bH, wc * 32 + np * 16, ks, lane, bh[np]);
#pragma unroll
            for (int mi = 0; mi < 2; mi++)
#pragma unroll
                for (int ni = 0; ni < 4; ni++) {
                    const int np = ni >> 1, o = (ni & 1) << 1;
                    MMAH16816(acc[mi][ni], ah[mi], bh[np][o], bh[np][o + 1]);
                    MMAH16816(acc[mi][ni], al[mi], bh[np][o], bh[np][o + 1]);
                }
        }
        __syncthreads();
    }

#pragma unroll
    for (int mi = 0; mi < 2; mi++) {
        const int row = rowbase + wr * 32 + mi * 16 + (lane >> 2);
#pragma unroll
        for (int ni = 0; ni < 4; ni++) {
            const int col = colbase + wc * 32 + ni * 8 + (lane & 3) * 2;
            if (col < N) {
                *reinterpret_cast<float2*>(&C[(size_t)row * ldc + col]) =
                    make_float2(acc[mi][ni][0], acc[mi][ni][1]);
                *reinterpret_cast<float2*>(&C[(size_t)(row + 8) * ldc + col]) =
                    make_float2(acc[mi][ni][2], acc[mi][ni][3]);
            }
        }
    }
}

// ---------------- exact fp32 dt: raw = u @ W_in[:, -32:], softplus(+bias) -> g_dt ----------------
__global__ __launch_bounds__(256) void dt_exact_kernel(const float* __restrict__ u,
                                                       const float* __restrict__ W_in,
                                                       const float* __restrict__ dt_bias) {
    __shared__ float us[16 * 256];
    __shared__ float ws[256 * 32];
    const int m0 = blockIdx.x * 16;
    const int t = threadIdx.x;
    const int mloc = t >> 4, h0 = t & 15, h1 = 16 + (t & 15);
    float acc0 = 0.f, acc1 = 0.f;
    for (int kc = 0; kc < 4; kc++) {
        __syncthreads();
        for (int i = t; i < 4096; i += 256) {
            int mm = i >> 8, kk = i & 255;
            us[i] = u[(size_t)(m0 + mm) * DMODEL + kc * 256 + kk];
        }
        for (int i = t; i < 8192; i += 256) {
            int kk = i >> 5, hh = i & 31;
            ws[i] = W_in[(size_t)(kc * 256 + kk) * DPROJ + (DPROJ - NH) + hh];
        }
        __syncthreads();
#pragma unroll 8
        for (int kk = 0; kk < 256; kk++) {
            float uv = us[mloc * 256 + kk];
            acc0 = fmaf(uv, ws[kk * 32 + h0], acc0);
            acc1 = fmaf(uv, ws[kk * 32 + h1], acc1);
        }
    }
    float x0 = acc0 + dt_bias[h0];
    float x1 = acc1 + dt_bias[h1];
    g_dt[(m0 + mloc) * NH + h0] = (x0 > 20.f) ? x0 : log1pf(expf(x0));
    g_dt[(m0 + mloc) * NH + h1] = (x1 > 20.f) ? x1 : log1pf(expf(x1));
}

// ---------------- prep A: u -> fp16 hi/lo ----------------
__global__ __launch_bounds__(1024) void prep_cvt_kernel(const float* __restrict__ u,
                                                        __half* __restrict__ a1h,
                                                        __half* __restrict__ a1l) {
    int i = blockIdx.x * 1024 + threadIdx.x;   // MROWS*DMODEL/4 elements of float4
    float4 x = reinterpret_cast<const float4*>(u)[i];
    float xs[4] = {x.x, x.y, x.z, x.w};
    __half h[4], l[4];
#pragma unroll
    for (int j = 0; j < 4; j++) {
        h[j] = __float2half(xs[j]);
        l[j] = __float2half(xs[j] - __half2float(h[j]));
    }
    reinterpret_cast<__half2*>(a1h)[2 * i]     = __half2(h[0], h[1]);
    reinterpret_cast<__half2*>(a1h)[2 * i + 1] = __half2(h[2], h[3]);
    reinterpret_cast<__half2*>(a1l)[2 * i]     = __half2(l[0], l[1]);
    reinterpret_cast<__half2*>(a1l)[2 * i + 1] = __half2(l[2], l[3]);
}

// ---------------- prep W: transpose W_in and W_out to fp16 [N][K] ----------------
__global__ __launch_bounds__(1024) void prep_w_kernel(const float* __restrict__ W_in,
                                                      const float* __restrict__ W_out,
                                                      __half* __restrict__ b1h,
                                                      __half* __restrict__ b2h) {
    __shared__ float t[32][33];
    const int bx = blockIdx.x, tid = threadIdx.x;
    const int tx = tid & 31, ty = tid >> 5;
    if (bx < 4480) {                        // W_in[k][n] -> b1h[n][k], zero-padded n
        int bxx = bx % 140, byy = bx / 140;
        int n = bxx * 32 + tx, k = byy * 32 + ty;
        t[ty][tx] = (n < DPROJ) ? W_in[(size_t)k * DPROJ + n] : 0.f;
        __syncthreads();
        int nn = bxx * 32 + ty, kk = byy * 32 + tx;
        b1h[(size_t)nn * DMODEL + kk] = __float2half(t[tx][ty]);
    } else {                                // W_out[k][n] -> b2h[n][k]
        int bb = bx - 4480;
        int bxx = bb % 32, byy = bb / 32;
        int n = bxx * 32 + tx, k = byy * 32 + ty;
        t[ty][tx] = W_out[(size_t)k * DMODEL + n];
        __syncthreads();
        int nn = bxx * 32 + ty, kk = byy * 32 + tx;
        b2h[(size_t)nn * DINNER + kk] = __float2half(t[tx][ty]);
    }
}

// ---------------- depthwise causal conv(4) + bias + SiLU (smem-tiled) ----------------
__global__ __launch_bounds__(256) void conv_kernel(const float* __restrict__ cw,
                                                   const float* __restrict__ cb) {
    __shared__ float s[19][256];
    int tid = threadIdx.x;
    int ch = blockIdx.x * 256 + tid;
    int m0 = blockIdx.y * 16;
    int l0 = m0 & (LSEQ - 1);
#pragma unroll
    for (int r = 0; r < 19; r++) {
        int l = l0 - 3 + r;
        s[r][tid] = (l >= 0) ? g_zx[(size_t)(m0 - 3 + r) * DPROJ + DINNER + ch] : 0.f;
    }
    __syncthreads();
    float w0 = cw[ch * 4], w1 = cw[ch * 4 + 1], w2 = cw[ch * 4 + 2], w3 = cw[ch * 4 + 3];
    float bias = cb[ch];
#pragma unroll
    for (int r = 0; r < 16; r++) {
        float acc = bias;
        acc = fmaf(s[r][tid], w0, acc);
        acc = fmaf(s[r + 1][tid], w1, acc);
        acc = fmaf(s[r + 2][tid], w2, acc);
        acc = fmaf(s[r + 3][tid], w3, acc);
        g_xbc[(size_t)(m0 + r) * CONVCH + ch] = acc / (1.f + expf(-acc));
    }
}

// ---------------- SSD intra-chunk (reads exact g_dt; warp-shfl cumsum; f32x2) -------
#define TS_STR 66
#define CS_STR 132
#define XS_STR 68
__global__ __launch_bounds__(256, 2) void ssd_diag_kernel(const float* __restrict__ A_log) {
    int blk = blockIdx.x;
    int h = blk & 31;
    int c = (blk >> 5) & 63;
    int b = blk >> 11;
    int m0 = b * LSEQ + c * CHK;

    extern __shared__ float sm[];
    float* Bst = sm;                         // 128*66
    float* Cs  = Bst + 128 * TS_STR;         // 64*132
    float* xs  = Cs + 64 * CS_STR;           // 64*68
    float* Gs  = xs + 64 * XS_STR;           // 64*68
    float* ac  = Gs + 64 * XS_STR;           // 64
    float* wd  = ac + 64;                    // 64
    float* dts = wd + 64;                    // 64
    int tid = threadIdx.x;

    // --- cumsum(A*dt): single warp, shfl scan (2 elems/lane); dt exact from g_dt ---
    if (tid < 32) {
        float A = -expf(A_log[h]);
        float dt0 = g_dt[(m0 + 2 * tid) * NH + h];
        float dt1 = g_dt[(m0 + 2 * tid + 1) * NH + h];
        dts[2 * tid] = dt0;
        dts[2 * tid + 1] = dt1;
        float e0 = A * dt0, e1 = A * dt1;
        float run = e0 + e1;
#pragma unroll
        for (int off = 1; off < 32; off <<= 1) {
            float v = __shfl_up_sync(0xFFFFFFFFu, run, off);
            if (tid >= off) run += v;
        }
        ac[2 * tid]     = run - e1;
        ac[2 * tid + 1] = run;
    }
    __syncthreads();
    if (tid < 64) {
        wd[tid] = expf(ac[63] - ac[tid]);
        g_acum[blk * CHK + tid] = ac[tid];
    }
    if (tid == 0) g_suma[blk] = expf(ac[63]);

    // --- tile loads ---
    for (int i = tid; i < 64 * 128; i += 256) {
        int l = i >> 7, n = i & 127;
        Bst[n * TS_STR + l] = g_xbc[(size_t)(m0 + l) * CONVCH + DINNER + n];
    }
    for (int i = tid; i < 64 * 32; i += 256) {
        int l = i >> 5, q = i & 31;
        float4 v = *reinterpret_cast<const float4*>(
            g_xbc + (size_t)(m0 + l) * CONVCH + DINNER + DSTATE + 4 * q);
        *reinterpret_cast<float4*>(Cs + l * CS_STR + 4 * q) = v;
    }
    for (int i = tid; i < 64 * 16; i += 256) {
        int l = i >> 4, q = i & 15;
        float dtv = dts[l];
        float4 v = *reinterpret_cast<const float4*>(
            g_xbc + (size_t)(m0 + l) * CONVCH + h * HD + 4 * q);
        v.x *= dtv; v.y *= dtv; v.z *= dtv; v.w *= dtv;
        *reinterpret_cast<float4*>(xs + l * XS_STR + 4 * q) = v;
    }
    __syncthreads();

    const int tr = tid >> 4, tc = tid & 15;
    const int r0 = tr * 4, c0 = tc * 4;

    // --- G[l][s] = C[l]·B[s] (lower-tri tiles only) ---
    if (tc <= tr) {
        uint64_t acc2[4][2] = {{0ull,0ull},{0ull,0ull},{0ull,0ull},{0ull,0ull}};
        for (int n4 = 0; n4 < 128; n4 += 4) {
            float4 cr[4];
#pragma unroll
            for (int i = 0; i < 4; i++)
                cr[i] = *reinterpret_cast<const float4*>(Cs + (r0 + i) * CS_STR + n4);
#pragma unroll
            for (int nn = 0; nn < 4; nn++) {
                uint64_t b0 = *reinterpret_cast<const uint64_t*>(Bst + (n4 + nn) * TS_STR + c0);
                uint64_t b1 = *reinterpret_cast<const uint64_t*>(Bst + (n4 + nn) * TS_STR + c0 + 2);
#pragma unroll
                for (int i = 0; i < 4; i++) {
                    uint64_t a2 = dup2((&cr[i].x)[nn]);
                    FMA2(acc2[i][0], a2, b0);
                    FMA2(acc2[i][1], a2, b1);
                }
            }
        }
#pragma unroll
        for (int i = 0; i < 4; i++) {
            int l = r0 + i;
            float al = ac[l];
            float v0, v1, v2, v3;
            up2(acc2[i][0], v0, v1);
            up2(acc2[i][1], v2, v3);
            float4 o;
            o.x = (c0     <= l) ? v0 * expf(al - ac[c0])     : 0.f;
            o.y = (c0 + 1 <= l) ? v1 * expf(al - ac[c0 + 1]) : 0.f;
            o.z = (c0 + 2 <= l) ? v2 * expf(al - ac[c0 + 2]) : 0.f;
            o.w = (c0 + 3 <= l) ? v3 * expf(al - ac[c0 + 3]) : 0.f;
            *reinterpret_cast<float4*>(Gs + l * XS_STR + c0) = o;
        }
    }
    __syncthreads();

    // --- Y_diag[l][p] = sum_{s<=l} G[l][s]*x[s][p] ---
    {
        uint64_t acc2[4][2] = {{0ull,0ull},{0ull,0ull},{0ull,0ull},{0ull,0ull}};
        for (int s4 = 0; s4 < r0 + 4; s4 += 4) {
            float4 gr[4];
#pragma unroll
            for (int i = 0; i < 4; i++)
                gr[i] = *reinterpret_cast<const float4*>(Gs + (r0 + i) * XS_STR + s4);
#pragma unroll
            for (int ss = 0; ss < 4; ss++) {
                uint64_t x0 = *reinterpret_cast<const uint64_t*>(xs + (s4 + ss) * XS_STR + c0);
                uint64_t x1 = *reinterpret_cast<const uint64_t*>(xs + (s4 + ss) * XS_STR + c0 + 2);
#pragma unroll
                for (int i = 0; i < 4; i++) {
                    uint64_t a2 = dup2((&gr[i].x)[ss]);
                    FMA2(acc2[i][0], a2, x0);
                    FMA2(acc2[i][1], a2, x1);
                }
            }
        }
#pragma unroll
        for (int i = 0; i < 4; i++) {
            float v0, v1, v2, v3;
            up2(acc2[i][0], v0, v1);
            up2(acc2[i][1], v2, v3);
            *reinterpret_cast<float4*>(g_y + (size_t)(m0 + r0 + i) * DINNER + h * HD + c0) =
                make_float4(v0, v1, v2, v3);
        }
    }

    // --- states S[p][n] = sum_l wd[l]*x[l][p]*B[l][n] ---
    {
        const int p0 = (tid & 15) * 4, n0 = (tid >> 4) * 8;
        uint64_t acc2[2][8];
#pragma unroll
        for (int pp = 0; pp < 2; pp++)
#pragma unroll
            for (int j = 0; j < 8; j++) acc2[pp][j] = 0ull;
        for (int l = 0; l < 64; l++) {
            uint64_t w2 = dup2(wd[l]);
            uint64_t xa = *reinterpret_cast<const uint64_t*>(xs + l * XS_STR + p0);
            uint64_t xb = *reinterpret_cast<const uint64_t*>(xs + l * XS_STR + p0 + 2);
            uint64_t wxa, wxb;
            MUL2(wxa, xa, w2);
            MUL2(wxb, xb, w2);
#pragma unroll
            for (int j = 0; j < 8; j++) {
                uint64_t b2 = dup2(Bst[(n0 + j) * TS_STR + l]);
                FMA2(acc2[0][j], wxa, b2);
                FMA2(acc2[1][j], wxb, b2);
            }
        }
        float rowv[4][8];
#pragma unroll
        for (int pp = 0; pp < 2; pp++)
#pragma unroll
            for (int j = 0; j < 8; j++)
                up2(acc2[pp][j], rowv[2 * pp][j], rowv[2 * pp + 1][j]);
#pragma unroll
        for (int i = 0; i < 4; i++) {
            float* dst = g_states + ((size_t)blk * HD + p0 + i) * DSTATE + n0;
            *reinterpret_cast<float4*>(dst)     = make_float4(rowv[i][0], rowv[i][1], rowv[i][2], rowv[i][3]);
            *reinterpret_cast<float4*>(dst + 4) = make_float4(rowv[i][4], rowv[i][5], rowv[i][6], rowv[i][7]);
        }
    }
}

// ---------------- inter-chunk scan (prefetched) ----------------
__global__ void scan_kernel() {
    int idx = blockIdx.x * blockDim.x + threadIdx.x;
    int n = idx & 127;
    int p = (idx >> 7) & 63;
    int h = (idx >> 13) & 31;
    int b = idx >> 18;
    const size_t cstep = (size_t)NH * HD * DSTATE;
    int bch0 = b * NC * NH + h;
    size_t off = ((size_t)bch0 * HD + p) * DSTATE + n;
    float prev = 0.f;
    float loc = g_states[off];
    for (int c = 0; c < NC; c++) {
        float nxt = (c + 1 < NC) ? g_states[off + cstep] : 0.f;
        float e = g_suma[bch0 + c * NH];
        g_states[off] = prev;
        prev = fmaf(prev, e, loc);
        loc = nxt;
        off += cstep;
    }
}

// ---------------- Y_off + skip (f32x2, half-C double pass, 2 CTAs/SM) ----------------
#define CS2_STR 68
__global__ __launch_bounds__(256, 2) void yoff_kernel(const float* __restrict__ Dv) {
    int blk = blockIdx.x;
    int h = blk & 31;
    int c = (blk >> 5) & 63;
    int b = blk >> 11;
    int m0 = b * LSEQ + c * CHK;

    extern __shared__ float sm[];
    float* Pst = sm;                        // 128 x stride 66 ([n][p])
    float* Cs2 = Pst + 128 * TS_STR;        // 64 x stride 68 (half of C)
    float* ac  = Cs2 + 64 * CS2_STR;        // 64
    int tid = threadIdx.x;

    for (int i = tid; i < 64 * 128; i += 256) {
        int p = i >> 7, n = i & 127;
        Pst[n * TS_STR + p] = g_states[((size_t)blk * HD + p) * DSTATE + n];
    }
    if (tid < 64) ac[tid] = g_acum[blk * CHK + tid];
    float Dh = Dv[h];

    const int tr = tid >> 4, tc = tid & 15;
    const int r0 = tr * 4, c0 = tc * 4;
    uint64_t acc2[4][2] = {{0ull,0ull},{0ull,0ull},{0ull,0ull},{0ull,0ull}};

#pragma unroll
    for (int half = 0; half < 2; half++) {
        __syncthreads();
        for (int i = tid; i < 64 * 16; i += 256) {
            int l = i >> 4, q = i & 15;
            float4 v = *reinterpret_cast<const float4*>(
                g_xbc + (size_t)(m0 + l) * CONVCH + DINNER + DSTATE + half * 64 + 4 * q);
            *reinterpret_cast<float4*>(Cs2 + l * CS2_STR + 4 * q) = v;
        }
        __syncthreads();
        for (int n4 = 0; n4 < 64; n4 += 4) {
            float4 cr[4];
#pragma unroll
            for (int i = 0; i < 4; i++)
                cr[i] = *reinterpret_cast<const float4*>(Cs2 + (r0 + i) * CS2_STR + n4);
#pragma unroll
            for (int nn = 0; nn < 4; nn++) {
                int n = half * 64 + n4 + nn;
                uint64_t p0v = *reinterpret_cast<const uint64_t*>(Pst + n * TS_STR + c0);
                uint64_t p1v = *reinterpret_cast<const uint64_t*>(Pst + n * TS_STR + c0 + 2);
#pragma unroll
                for (int i = 0; i < 4; i++) {
                    uint64_t a2 = dup2((&cr[i].x)[nn]);
                    FMA2(acc2[i][0], a2, p0v);
                    FMA2(acc2[i][1], a2, p1v);
                }
            }
        }
    }

#pragma unroll
    for (int i = 0; i < 4; i++) {
        int l = r0 + i;
        int row = m0 + l;
        float el = expf(ac[l]);
        float v0, v1, v2, v3;
        up2(acc2[i][0], v0, v1);
        up2(acc2[i][1], v2, v3);
        float4 xv = *reinterpret_cast<const float4*>(
            g_xbc + (size_t)row * CONVCH + h * HD + c0);
        float4* yp = reinterpret_cast<float4*>(g_y + (size_t)row * DINNER + h * HD + c0);
        float4 yv = *yp;
        yv.x += v0 * el + xv.x * Dh;
        yv.y += v1 * el + xv.y * Dh;
        yv.z += v2 * el + xv.z * Dh;
        yv.w += v3 * el + xv.w * Dh;
        *yp = yv;
    }
}

// ---------------- gate (silu(z)) + RMSNorm, fused fp16 split output ----------------
__global__ void gate_kernel(const float* __restrict__ norm_w,
                            __half* __restrict__ a2h, __half* __restrict__ a2l) {
    int m = blockIdx.x;
    int tid = threadIdx.x;
    __shared__ float red[256];
    float tv[8];
    float ss = 0.f;
#pragma unroll
    for (int j = 0; j < 8; j++) {
        int i = tid + 256 * j;
        float zv = g_zx[(size_t)m * DPROJ + i];
        float yv = g_y[(size_t)m * DINNER + i];
        float g = yv * (zv / (1.f + expf(-zv)));
        tv[j] = g;
        ss += g * g;
    }
    red[tid] = ss;
    __syncthreads();
    for (int s = 128; s > 0; s >>= 1) {
        if (tid < s) red[tid] += red[tid + s];
        __syncthreads();
    }
    float scale = rsqrtf(red[0] / (float)DINNER + 1e-5f);
#pragma unroll
    for (int j = 0; j < 8; j++) {
        int i = tid + 256 * j;
        float val = tv[j] * scale * norm_w[i];
        __half hv = __float2half(val);
        a2h[(size_t)m * DINNER + i] = hv;
        a2l[(size_t)m * DINNER + i] = __float2half(val - __half2float(hv));
    }
}

// ---------------- launch ----------------
extern "C" void kernel_launch(void* const* d_in, const int* in_sizes, int n_in,
                              void* d_out, int out_size) {
    const float* u      = (const float*)d_in[0];
    const float* W_in   = (const float*)d_in[1];
    const float* conv_w = (const float*)d_in[2];
    const float* conv_b = (const float*)d_in[3];
    const float* dt_b   = (const float*)d_in[4];
    const float* A_log  = (const float*)d_in[5];
    const float* Dv     = (const float*)d_in[6];
    const float* norm_w = (const float*)d_in[7];
    const float* W_out  = (const float*)d_in[8];
    float* out = (float*)d_out;

    float* zx = nullptr;
    cudaGetSymbolAddress((void**)&zx, g_zx);
    __half *a1h, *a1l, *b1h, *a2h, *a2l, *b2h;
    cudaGetSymbolAddress((void**)&a1h, g_a1h);
    cudaGetSymbolAddress((void**)&a1l, g_a1l);
    cudaGetSymbolAddress((void**)&b1h, g_b1h);
    cudaGetSymbolAddress((void**)&a2h, g_a2h);
    cudaGetSymbolAddress((void**)&a2l, g_a2l);
    cudaGetSymbolAddress((void**)&b2h, g_b2h);

    const size_t gemm_smem = 2 * 40960;   // 81920, 2 CTAs/SM
    const size_t diag_smem = (size_t)(128 * TS_STR + 64 * CS_STR + 2 * 64 * XS_STR + 192) * sizeof(float);
    const size_t yoff_smem = (size_t)(128 * TS_STR + 64 * CS2_STR + 64) * sizeof(float);
    cudaFuncSetAttribute(hgemm_kernel, cudaFuncAttributeMaxDynamicSharedMemorySize, (int)gemm_smem);
    cudaFuncSetAttribute(ssd_diag_kernel, cudaFuncAttributeMaxDynamicSharedMemorySize, (int)diag_smem);
    cudaFuncSetAttribute(yoff_kernel, cudaFuncAttributeMaxDynamicSharedMemorySize, (int)yoff_smem);

    // 0: exact fp32 dt (only needs inputs)
    dt_exact_kernel<<<MROWS / 16, 256>>>(u, W_in, dt_b);

    // 1: prep A (u -> fp16 hi/lo)
    prep_cvt_kernel<<<MROWS * DMODEL / 4096, 1024>>>(u, a1h, a1l);

    // 2: prep W (transpose W_in, W_out -> fp16)
    prep_w_kernel<<<4480 + 2048, 1024>>>(W_in, W_out, b1h, b2h);

    // 3: GEMM1 (profiled): zx[8192,4384] = u @ W_in (fp16 2-product)
    hgemm_kernel<<<dim3(NPAD1 / 64, MROWS / 128), 256, gemm_smem>>>(
        a1h, a1l, b1h, zx, DPROJ, DMODEL, DPROJ);

    // 4: conv
    conv_kernel<<<dim3(CONVCH / 256, MROWS / 16), 256>>>(conv_w, conv_b);

    // 5: SSD intra-chunk
    ssd_diag_kernel<<<BQ * NC * NH, 256, diag_smem>>>(A_log);

    // 6: inter-chunk scan
    scan_kernel<<<(BQ * NH * HD * DSTATE) / 256, 256>>>();

    // 7: Y_off + skip
    yoff_kernel<<<BQ * NC * NH, 256, yoff_smem>>>(Dv);

    // 8: gate + rmsnorm (writes fp16 split A for GEMM2)
    gate_kernel<<<MROWS, 256>>>(norm_w, a2h, a2l);

    // 9: GEMM2: out[8192,1024] = y @ W_out (fp16 2-product)
    hgemm_kernel<<<dim3(DMODEL / 64, MROWS / 128), 256, gemm_smem>>>(
        a2h, a2l, b2h, out, DMODEL, DINNER, DMODEL);
}

// round 13
// speedup vs baseline: 2.1564x; 1.3621x over previous
#include <cuda_runtime.h>
#include <cuda_bf16.h>
#include <cuda_fp16.h>
#include <math.h>
#include <cstdint>

// ---------------- problem constants ----------------
#define BQ 2
#define LSEQ 4096
#define DMODEL 1024
#define DINNER 2048
#define NH 32
#define HD 64
#define DSTATE 128
#define CHK 64
#define NC 64
#define DPROJ 4384
#define CONVCH 2304
#define MROWS (BQ*LSEQ)
#define NPAD1 4480      // DPROJ padded to 128

// ---------------- scratch (device globals; no allocation) ----------------
__device__ float g_zx[(size_t)MROWS * DPROJ];
__device__ float g_xbc[(size_t)MROWS * CONVCH];
__device__ float g_dt[MROWS * NH];
__device__ float g_acum[BQ * NC * NH * CHK];
__device__ float g_suma[BQ * NC * NH];
__device__ float g_states[(size_t)BQ * NC * NH * HD * DSTATE];
__device__ float g_y[(size_t)MROWS * DINNER];
__device__ float g_cb[(size_t)BQ * NC * CHK * CHK];   // CB^T shared across heads (2MB)

// GEMM operands: fp16, A hi/lo 2-product, B single
__device__ __half g_a1h[(size_t)MROWS * DMODEL];
__device__ __half g_a1l[(size_t)MROWS * DMODEL];
__device__ __half g_b1h[(size_t)NPAD1 * DMODEL];
__device__ __half g_a2h[(size_t)MROWS * DINNER];
__device__ __half g_a2l[(size_t)MROWS * DINNER];
__device__ __half g_b2h[(size_t)DMODEL * DINNER];

// ---------------- PTX helpers ----------------
__device__ __forceinline__ uint32_t smem_u32(const void* p) {
    uint32_t a;
    asm("{ .reg .u64 t; cvta.to.shared.u64 t, %1; cvt.u32.u64 %0, t; }" : "=r"(a) : "l"(p));
    return a;
}
#define SMEM_SWIZZLE_128B(byte_offset) ((byte_offset) ^ (((byte_offset) >> 3) & 0x70))
#define CP_ASYNC16(dst, src) \
    asm volatile("cp.async.cg.shared.global [%0], [%1], 16;" :: "r"(dst), "l"(src) : "memory")
#define CP_COMMIT() asm volatile("cp.async.commit_group;" ::: "memory")
#define CP_WAIT0()  asm volatile("cp.async.wait_group 0;" ::: "memory")

#define LDSM_X4(r0,r1,r2,r3,addr) \
    asm volatile("ldmatrix.sync.aligned.m8n8.x4.shared.b16 {%0,%1,%2,%3}, [%4];" \
        : "=r"(r0), "=r"(r1), "=r"(r2), "=r"(r3) : "r"(addr))

#define MMAH16816(d, a, b0, b1) \
    asm volatile("mma.sync.aligned.m16n8k16.row.col.f32.f16.f16.f32 " \
        "{%0,%1,%2,%3}, {%4,%5,%6,%7}, {%8,%9}, {%0,%1,%2,%3};" \
        : "+f"((d)[0]), "+f"((d)[1]), "+f"((d)[2]), "+f"((d)[3]) \
        : "r"((a)[0]), "r"((a)[1]), "r"((a)[2]), "r"((a)[3]), "r"(b0), "r"(b1))

// packed f32x2 (2x fp32 FMA rate)
#define FMA2(d, a, b) asm("fma.rn.f32x2 %0, %1, %2, %0;" : "+l"(d) : "l"(a), "l"(b))
#define MUL2(d, a, b) asm("mul.rn.f32x2 %0, %1, %2;" : "=l"(d) : "l"(a), "l"(b))
__device__ __forceinline__ uint64_t dup2(float x) {
    uint64_t r; asm("mov.b64 %0, {%1, %1};" : "=l"(r) : "f"(x)); return r;
}
__device__ __forceinline__ void up2(uint64_t v, float& lo, float& hi) {
    asm("mov.b64 {%0, %1}, %2;" : "=f"(lo), "=f"(hi) : "l"(v));
}

__device__ __forceinline__ void ldsmA(uint32_t base, int row, int ks, int lane, uint32_t* r) {
    int rr = row + (lane & 15);
    int off = rr * 128 + ks * 32 + ((lane >> 4) << 4);
    LDSM_X4(r[0], r[1], r[2], r[3], base + SMEM_SWIZZLE_128B((uint32_t)off));
}
__device__ __forceinline__ void ldsmB(uint32_t base, int nrow, int ks, int lane, uint32_t* r) {
    int n = nrow + ((lane >> 4) << 3) + (lane & 7);
    int off = n * 128 + ks * 32 + (((lane >> 3) & 1) << 4);
    LDSM_X4(r[0], r[1], r[2], r[3], base + SMEM_SWIZZLE_128B((uint32_t)off));
}

// ---------------- fp16 2-product GEMM (validated: 70.5% tensor) ----------------
__global__ __launch_bounds__(256, 2) void hgemm_kernel(
    const __half* __restrict__ Ah, const __half* __restrict__ Al,
    const __half* __restrict__ Bh, float* __restrict__ C, int N, int K, int ldc)
{
    extern __shared__ char smem[];
    const uint32_t sb = smem_u32(smem);
    const int tid = threadIdx.x, wid = tid >> 5, lane = tid & 31;
    const int wr = wid & 3, wc = wid >> 2;
    const int rowbase = blockIdx.y * 128, colbase = blockIdx.x * 64;
    const int KC = K >> 6;

    float acc[2][4][4];
#pragma unroll
    for (int mi = 0; mi < 2; mi++)
#pragma unroll
        for (int ni = 0; ni < 4; ni++)
#pragma unroll
            for (int j = 0; j < 4; j++) acc[mi][ni][j] = 0.f;

    auto issue_chunk = [&](int i) {
        const uint32_t st = (uint32_t)(i & 1) * 40960u;
        const int k0 = i << 6;
#pragma unroll
        for (int v = 0; v < 10; v++) {
            const int idx = v * 256 + tid;
            const __half* src;
            uint32_t dst;
            if (idx < 2048) {
                const int buf = idx >> 10;
                const int r = (idx & 1023) >> 3, c8 = idx & 7;
                src = (buf ? Al : Ah) + (size_t)(rowbase + r) * K + k0 + c8 * 8;
                dst = sb + st + (uint32_t)buf * 16384u +
                      SMEM_SWIZZLE_128B((uint32_t)(r * 128 + c8 * 16));
            } else {
                const int j = idx - 2048;
                const int r = j >> 3, c8 = j & 7;
                src = Bh + (size_t)(colbase + r) * K + k0 + c8 * 8;
                dst = sb + st + 32768u + SMEM_SWIZZLE_128B((uint32_t)(r * 128 + c8 * 16));
            }
            CP_ASYNC16(dst, src);
        }
    };

    issue_chunk(0);
    CP_COMMIT();

    for (int i = 0; i < KC; i++) {
        CP_WAIT0();
        __syncthreads();
        if (i + 1 < KC) { issue_chunk(i + 1); CP_COMMIT(); }

        const uint32_t st = sb + (uint32_t)(i & 1) * 40960u;
        const uint32_t aH = st, aL = st + 16384u, bH = st + 32768u;
#pragma unroll
        for (int ks = 0; ks < 4; ks++) {
            uint32_t ah[2][4], al[2][4], bh[2][4];
#pragma unroll
            for (int mi = 0; mi < 2; mi++) {
                ldsmA(aH, wr * 32 + mi * 16, ks, lane, ah[mi]);
                ldsmA(aL, wr * 32 + mi * 16, ks, lane, al[mi]);
            }
#pragma unroll
            for (int np = 0; np < 2; np++)
                ldsmB(bH, wc * 32 + np * 16, ks, lane, bh[np]);
#pragma unroll
            for (int mi = 0; mi < 2; mi++)
#pragma unroll
                for (int ni = 0; ni < 4; ni++) {
                    const int np = ni >> 1, o = (ni & 1) << 1;
                    MMAH16816(acc[mi][ni], ah[mi], bh[np][o], bh[np][o + 1]);
                    MMAH16816(acc[mi][ni], al[mi], bh[np][o], bh[np][o + 1]);
                }
        }
        __syncthreads();
    }

#pragma unroll
    for (int mi = 0; mi < 2; mi++) {
        const int row = rowbase + wr * 32 + mi * 16 + (lane >> 2);
#pragma unroll
        for (int ni = 0; ni < 4; ni++) {
            const int col = colbase + wc * 32 + ni * 8 + (lane & 3) * 2;
            if (col < N) {
                *reinterpret_cast<float2*>(&C[(size_t)row * ldc + col]) =
                    make_float2(acc[mi][ni][0], acc[mi][ni][1]);
                *reinterpret_cast<float2*>(&C[(size_t)(row + 8) * ldc + col]) =
                    make_float2(acc[mi][ni][2], acc[mi][ni][3]);
            }
        }
    }
}

// ---------------- exact fp32 dt ----------------
__global__ __launch_bounds__(256) void dt_exact_kernel(const float* __restrict__ u,
                                                       const float* __restrict__ W_in,
                                                       const float* __restrict__ dt_bias) {
    __shared__ float us[16 * 256];
    __shared__ float ws[256 * 32];
    const int m0 = blockIdx.x * 16;
    const int t = threadIdx.x;
    const int mloc = t >> 4, h0 = t & 15, h1 = 16 + (t & 15);
    float acc0 = 0.f, acc1 = 0.f;
    for (int kc = 0; kc < 4; kc++) {
        __syncthreads();
        for (int i = t; i < 4096; i += 256) {
            int mm = i >> 8, kk = i & 255;
            us[i] = u[(size_t)(m0 + mm) * DMODEL + kc * 256 + kk];
        }
        for (int i = t; i < 8192; i += 256) {
            int kk = i >> 5, hh = i & 31;
            ws[i] = W_in[(size_t)(kc * 256 + kk) * DPROJ + (DPROJ - NH) + hh];
        }
        __syncthreads();
#pragma unroll 8
        for (int kk = 0; kk < 256; kk++) {
            float uv = us[mloc * 256 + kk];
            acc0 = fmaf(uv, ws[kk * 32 + h0], acc0);
            acc1 = fmaf(uv, ws[kk * 32 + h1], acc1);
        }
    }
    float x0 = acc0 + dt_bias[h0];
    float x1 = acc1 + dt_bias[h1];
    g_dt[(m0 + mloc) * NH + h0] = (x0 > 20.f) ? x0 : log1pf(expf(x0));
    g_dt[(m0 + mloc) * NH + h1] = (x1 > 20.f) ? x1 : log1pf(expf(x1));
}

// ---------------- prep A: u -> fp16 hi/lo ----------------
__global__ __launch_bounds__(1024) void prep_cvt_kernel(const float* __restrict__ u,
                                                        __half* __restrict__ a1h,
                                                        __half* __restrict__ a1l) {
    int i = blockIdx.x * 1024 + threadIdx.x;
    float4 x = reinterpret_cast<const float4*>(u)[i];
    float xs[4] = {x.x, x.y, x.z, x.w};
    __half h[4], l[4];
#pragma unroll
    for (int j = 0; j < 4; j++) {
        h[j] = __float2half(xs[j]);
        l[j] = __float2half(xs[j] - __half2float(h[j]));
    }
    reinterpret_cast<__half2*>(a1h)[2 * i]     = __half2(h[0], h[1]);
    reinterpret_cast<__half2*>(a1h)[2 * i + 1] = __half2(h[2], h[3]);
    reinterpret_cast<__half2*>(a1l)[2 * i]     = __half2(l[0], l[1]);
    reinterpret_cast<__half2*>(a1l)[2 * i + 1] = __half2(l[2], l[3]);
}

// ---------------- prep W: transpose W_in and W_out to fp16 [N][K] ----------------
__global__ __launch_bounds__(1024) void prep_w_kernel(const float* __restrict__ W_in,
                                                      const float* __restrict__ W_out,
                                                      __half* __restrict__ b1h,
                                                      __half* __restrict__ b2h) {
    __shared__ float t[32][33];
    const int bx = blockIdx.x, tid = threadIdx.x;
    const int tx = tid & 31, ty = tid >> 5;
    if (bx < 4480) {
        int bxx = bx % 140, byy = bx / 140;
        int n = bxx * 32 + tx, k = byy * 32 + ty;
        t[ty][tx] = (n < DPROJ) ? W_in[(size_t)k * DPROJ + n] : 0.f;
        __syncthreads();
        int nn = bxx * 32 + ty, kk = byy * 32 + tx;
        b1h[(size_t)nn * DMODEL + kk] = __float2half(t[tx][ty]);
    } else {
        int bb = bx - 4480;
        int bxx = bb % 32, byy = bb / 32;
        int n = bxx * 32 + tx, k = byy * 32 + ty;
        t[ty][tx] = W_out[(size_t)k * DMODEL + n];
        __syncthreads();
        int nn = bxx * 32 + ty, kk = byy * 32 + tx;
        b2h[(size_t)nn * DINNER + kk] = __float2half(t[tx][ty]);
    }
}

// ---------------- depthwise causal conv(4) + bias + SiLU (smem-tiled) ----------------
__global__ __launch_bounds__(256) void conv_kernel(const float* __restrict__ cw,
                                                   const float* __restrict__ cb) {
    __shared__ float s[19][256];
    int tid = threadIdx.x;
    int ch = blockIdx.x * 256 + tid;
    int m0 = blockIdx.y * 16;
    int l0 = m0 & (LSEQ - 1);
#pragma unroll
    for (int r = 0; r < 19; r++) {
        int l = l0 - 3 + r;
        s[r][tid] = (l >= 0) ? g_zx[(size_t)(m0 - 3 + r) * DPROJ + DINNER + ch] : 0.f;
    }
    __syncthreads();
    float w0 = cw[ch * 4], w1 = cw[ch * 4 + 1], w2 = cw[ch * 4 + 2], w3 = cw[ch * 4 + 3];
    float bias = cb[ch];
#pragma unroll
    for (int r = 0; r < 16; r++) {
        float acc = bias;
        acc = fmaf(s[r][tid], w0, acc);
        acc = fmaf(s[r + 1][tid], w1, acc);
        acc = fmaf(s[r + 2][tid], w2, acc);
        acc = fmaf(s[r + 3][tid], w3, acc);
        g_xbc[(size_t)(m0 + r) * CONVCH + ch] = acc / (1.f + expf(-acc));
    }
}

#define TS_STR 66
#define CS_STR 132
#define XS_STR 68

// ---------------- CB^T = C·B^T per (b,c), shared across heads ----------------
// grid 256: blk = bc*2 + half; block computes l-rows [half*32, +32) x 64 s-cols.
__global__ __launch_bounds__(256, 2) void cb_kernel() {
    int blk = blockIdx.x;
    int bc = blk >> 1, half = blk & 1;
    int m0 = (bc >> 6) * LSEQ + (bc & 63) * CHK;
    extern __shared__ float sm[];
    float* Bst = sm;                 // [n][s] 128 x 66
    float* Cs  = Bst + 128 * TS_STR; // [lloc][n] 32 x 132
    int tid = threadIdx.x;
    for (int i = tid; i < 64 * 128; i += 256) {
        int l = i >> 7, n = i & 127;
        Bst[n * TS_STR + l] = g_xbc[(size_t)(m0 + l) * CONVCH + DINNER + n];
    }
    for (int i = tid; i < 32 * 32; i += 256) {
        int ll = i >> 5, q = i & 31;
        float4 v = *reinterpret_cast<const float4*>(
            g_xbc + (size_t)(m0 + half * 32 + ll) * CONVCH + DINNER + DSTATE + 4 * q);
        *reinterpret_cast<float4*>(Cs + ll * CS_STR + 4 * q) = v;
    }
    __syncthreads();
    const int rg = tid >> 5, cg = tid & 31;        // 8 row-groups x 32 col-groups
    const int r0 = rg * 4, c0 = cg * 2;            // local rows; s-cols (pair)
    float* out = g_cb + (size_t)bc * 4096 + (size_t)(half * 32) * 64;
    if (c0 > half * 32 + r0 + 3) {                 // strictly above diagonal: zero
#pragma unroll
        for (int i = 0; i < 4; i++)
            *reinterpret_cast<float2*>(out + (r0 + i) * 64 + c0) = make_float2(0.f, 0.f);
        return;
    }
    uint64_t acc2[4] = {0ull, 0ull, 0ull, 0ull};
    for (int n4 = 0; n4 < 128; n4 += 4) {
        float4 cr[4];
#pragma unroll
        for (int i = 0; i < 4; i++)
            cr[i] = *reinterpret_cast<const float4*>(Cs + (r0 + i) * CS_STR + n4);
#pragma unroll
        for (int nn = 0; nn < 4; nn++) {
            uint64_t b2 = *reinterpret_cast<const uint64_t*>(Bst + (n4 + nn) * TS_STR + c0);
#pragma unroll
            for (int i = 0; i < 4; i++) {
                uint64_t a2 = dup2((&cr[i].x)[nn]);
                FMA2(acc2[i], a2, b2);
            }
        }
    }
#pragma unroll
    for (int i = 0; i < 4; i++) {
        float v0, v1;
        up2(acc2[i], v0, v1);
        *reinterpret_cast<float2*>(out + (r0 + i) * 64 + c0) = make_float2(v0, v1);
    }
}

// ---------------- SSD intra-chunk: loads shared CB, applies per-head decay ----------
__global__ __launch_bounds__(256, 2) void ssd_diag_kernel(const float* __restrict__ A_log) {
    int blk = blockIdx.x;
    int h = blk & 31;
    int c = (blk >> 5) & 63;
    int b = blk >> 11;
    int m0 = b * LSEQ + c * CHK;

    extern __shared__ float sm[];
    float* Bst = sm;                         // 128*66
    float* xs  = Bst + 128 * TS_STR;         // 64*68
    float* Gs  = xs + 64 * XS_STR;           // 64*68
    float* ac  = Gs + 64 * XS_STR;           // 64
    float* wd  = ac + 64;                    // 64
    float* dts = wd + 64;                    // 64
    int tid = threadIdx.x;

    // --- cumsum(A*dt): single warp shfl scan; dt exact from g_dt ---
    if (tid < 32) {
        float A = -expf(A_log[h]);
        float dt0 = g_dt[(m0 + 2 * tid) * NH + h];
        float dt1 = g_dt[(m0 + 2 * tid + 1) * NH + h];
        dts[2 * tid] = dt0;
        dts[2 * tid + 1] = dt1;
        float e0 = A * dt0, e1 = A * dt1;
        float run = e0 + e1;
#pragma unroll
        for (int off = 1; off < 32; off <<= 1) {
            float v = __shfl_up_sync(0xFFFFFFFFu, run, off);
            if (tid >= off) run += v;
        }
        ac[2 * tid]     = run - e1;
        ac[2 * tid + 1] = run;
    }
    __syncthreads();
    if (tid < 64) {
        wd[tid] = expf(ac[63] - ac[tid]);
        g_acum[blk * CHK + tid] = ac[tid];
    }
    if (tid == 0) g_suma[blk] = expf(ac[63]);

    // --- tile loads: B (transposed), x*dt, and masked CB -> Gs ---
    for (int i = tid; i < 64 * 128; i += 256) {
        int l = i >> 7, n = i & 127;
        Bst[n * TS_STR + l] = g_xbc[(size_t)(m0 + l) * CONVCH + DINNER + n];
    }
    for (int i = tid; i < 64 * 16; i += 256) {
        int l = i >> 4, q = i & 15;
        float dtv = dts[l];
        float4 v = *reinterpret_cast<const float4*>(
            g_xbc + (size_t)(m0 + l) * CONVCH + h * HD + 4 * q);
        v.x *= dtv; v.y *= dtv; v.z *= dtv; v.w *= dtv;
        *reinterpret_cast<float4*>(xs + l * XS_STR + 4 * q) = v;
    }
    {
        const float* cb = g_cb + (size_t)(b * NC + c) * 4096;
        for (int i = tid; i < 4096; i += 256) {
            int l = i >> 6, s = i & 63;
            float v = cb[i];
            Gs[l * XS_STR + s] = (s <= l) ? v * expf(ac[l] - ac[s]) : 0.f;
        }
    }
    __syncthreads();

    const int tr = tid >> 4, tc = tid & 15;
    const int r0 = tr * 4, c0 = tc * 4;

    // --- Y_diag[l][p] = sum_{s<=l} G[l][s]*x[s][p] ---
    {
        uint64_t acc2[4][2] = {{0ull,0ull},{0ull,0ull},{0ull,0ull},{0ull,0ull}};
        for (int s4 = 0; s4 < r0 + 4; s4 += 4) {
            float4 gr[4];
#pragma unroll
            for (int i = 0; i < 4; i++)
                gr[i] = *reinterpret_cast<const float4*>(Gs + (r0 + i) * XS_STR + s4);
#pragma unroll
            for (int ss = 0; ss < 4; ss++) {
                uint64_t x0 = *reinterpret_cast<const uint64_t*>(xs + (s4 + ss) * XS_STR + c0);
                uint64_t x1 = *reinterpret_cast<const uint64_t*>(xs + (s4 + ss) * XS_STR + c0 + 2);
#pragma unroll
                for (int i = 0; i < 4; i++) {
                    uint64_t a2 = dup2((&gr[i].x)[ss]);
                    FMA2(acc2[i][0], a2, x0);
                    FMA2(acc2[i][1], a2, x1);
                }
            }
        }
#pragma unroll
        for (int i = 0; i < 4; i++) {
            float v0, v1, v2, v3;
            up2(acc2[i][0], v0, v1);
            up2(acc2[i][1], v2, v3);
            *reinterpret_cast<float4*>(g_y + (size_t)(m0 + r0 + i) * DINNER + h * HD + c0) =
                make_float4(v0, v1, v2, v3);
        }
    }

    // --- states S[p][n] = sum_l wd[l]*x[l][p]*B[l][n] ---
    {
        const int p0 = (tid & 15) * 4, n0 = (tid >> 4) * 8;
        uint64_t acc2[2][8];
#pragma unroll
        for (int pp = 0; pp < 2; pp++)
#pragma unroll
            for (int j = 0; j < 8; j++) acc2[pp][j] = 0ull;
        for (int l = 0; l < 64; l++) {
            uint64_t w2 = dup2(wd[l]);
            uint64_t xa = *reinterpret_cast<const uint64_t*>(xs + l * XS_STR + p0);
            uint64_t xb = *reinterpret_cast<const uint64_t*>(xs + l * XS_STR + p0 + 2);
            uint64_t wxa, wxb;
            MUL2(wxa, xa, w2);
            MUL2(wxb, xb, w2);
#pragma unroll
            for (int j = 0; j < 8; j++) {
                uint64_t b2 = dup2(Bst[(n0 + j) * TS_STR + l]);
                FMA2(acc2[0][j], wxa, b2);
                FMA2(acc2[1][j], wxb, b2);
            }
        }
        float rowv[4][8];
#pragma unroll
        for (int pp = 0; pp < 2; pp++)
#pragma unroll
            for (int j = 0; j < 8; j++)
                up2(acc2[pp][j], rowv[2 * pp][j], rowv[2 * pp + 1][j]);
#pragma unroll
        for (int i = 0; i < 4; i++) {
            float* dst = g_states + ((size_t)blk * HD + p0 + i) * DSTATE + n0;
            *reinterpret_cast<float4*>(dst)     = make_float4(rowv[i][0], rowv[i][1], rowv[i][2], rowv[i][3]);
            *reinterpret_cast<float4*>(dst + 4) = make_float4(rowv[i][4], rowv[i][5], rowv[i][6], rowv[i][7]);
        }
    }
}

// ---------------- inter-chunk scan (float2 + prefetch) ----------------
__global__ void scan_kernel() {
    int idx = blockIdx.x * blockDim.x + threadIdx.x;   // BQ*NH*HD*DSTATE/2
    int n2 = idx & 63;
    int p = (idx >> 6) & 63;
    int h = (idx >> 12) & 31;
    int b = idx >> 17;
    const size_t cstep = (size_t)NH * HD * DSTATE;
    int bch0 = b * NC * NH + h;
    size_t off = ((size_t)bch0 * HD + p) * DSTATE + 2 * n2;
    float2 prev = make_float2(0.f, 0.f);
    float2 loc = *reinterpret_cast<float2*>(g_states + off);
    for (int c = 0; c < NC; c++) {
        float2 nxt = (c + 1 < NC) ? *reinterpret_cast<float2*>(g_states + off + cstep)
                                  : make_float2(0.f, 0.f);
        float e = g_suma[bch0 + c * NH];
        *reinterpret_cast<float2*>(g_states + off) = prev;
        prev.x = fmaf(prev.x, e, loc.x);
        prev.y = fmaf(prev.y, e, loc.y);
        loc = nxt;
        off += cstep;
    }
}

// ---------------- Y_off + skip (f32x2, half-C double pass, 2 CTAs/SM) ----------------
#define CS2_STR 68
__global__ __launch_bounds__(256, 2) void yoff_kernel(const float* __restrict__ Dv) {
    int blk = blockIdx.x;
    int h = blk & 31;
    int c = (blk >> 5) & 63;
    int b = blk >> 11;
    int m0 = b * LSEQ + c * CHK;

    extern __shared__ float sm[];
    float* Pst = sm;                        // 128 x stride 66 ([n][p])
    float* Cs2 = Pst + 128 * TS_STR;        // 64 x stride 68 (half of C)
    float* ac  = Cs2 + 64 * CS2_STR;        // 64
    int tid = threadIdx.x;

    for (int i = tid; i < 64 * 128; i += 256) {
        int p = i >> 7, n = i & 127;
        Pst[n * TS_STR + p] = g_states[((size_t)blk * HD + p) * DSTATE + n];
    }
    if (tid < 64) ac[tid] = g_acum[blk * CHK + tid];
    float Dh = Dv[h];

    const int tr = tid >> 4, tc = tid & 15;
    const int r0 = tr * 4, c0 = tc * 4;
    uint64_t acc2[4][2] = {{0ull,0ull},{0ull,0ull},{0ull,0ull},{0ull,0ull}};

#pragma unroll
    for (int half = 0; half < 2; half++) {
        __syncthreads();
        for (int i = tid; i < 64 * 16; i += 256) {
            int l = i >> 4, q = i & 15;
            float4 v = *reinterpret_cast<const float4*>(
                g_xbc + (size_t)(m0 + l) * CONVCH + DINNER + DSTATE + half * 64 + 4 * q);
            *reinterpret_cast<float4*>(Cs2 + l * CS2_STR + 4 * q) = v;
        }
        __syncthreads();
        for (int n4 = 0; n4 < 64; n4 += 4) {
            float4 cr[4];
#pragma unroll
            for (int i = 0; i < 4; i++)
                cr[i] = *reinterpret_cast<const float4*>(Cs2 + (r0 + i) * CS2_STR + n4);
#pragma unroll
            for (int nn = 0; nn < 4; nn++) {
                int n = half * 64 + n4 + nn;
                uint64_t p0v = *reinterpret_cast<const uint64_t*>(Pst + n * TS_STR + c0);
                uint64_t p1v = *reinterpret_cast<const uint64_t*>(Pst + n * TS_STR + c0 + 2);
#pragma unroll
                for (int i = 0; i < 4; i++) {
                    uint64_t a2 = dup2((&cr[i].x)[nn]);
                    FMA2(acc2[i][0], a2, p0v);
                    FMA2(acc2[i][1], a2, p1v);
                }
            }
        }
    }

#pragma unroll
    for (int i = 0; i < 4; i++) {
        int l = r0 + i;
        int row = m0 + l;
        float el = expf(ac[l]);
        float v0, v1, v2, v3;
        up2(acc2[i][0], v0, v1);
        up2(acc2[i][1], v2, v3);
        float4 xv = *reinterpret_cast<const float4*>(
            g_xbc + (size_t)row * CONVCH + h * HD + c0);
        float4* yp = reinterpret_cast<float4*>(g_y + (size_t)row * DINNER + h * HD + c0);
        float4 yv = *yp;
        yv.x += v0 * el + xv.x * Dh;
        yv.y += v1 * el + xv.y * Dh;
        yv.z += v2 * el + xv.z * Dh;
        yv.w += v3 * el + xv.w * Dh;
        *yp = yv;
    }
}

// ---------------- gate (silu(z)) + RMSNorm, fused fp16 split output ----------------
__global__ void gate_kernel(const float* __restrict__ norm_w,
                            __half* __restrict__ a2h, __half* __restrict__ a2l) {
    int m = blockIdx.x;
    int tid = threadIdx.x;
    __shared__ float red[256];
    float tv[8];
    float ss = 0.f;
#pragma unroll
    for (int j = 0; j < 8; j++) {
        int i = tid + 256 * j;
        float zv = g_zx[(size_t)m * DPROJ + i];
        float yv = g_y[(size_t)m * DINNER + i];
        float g = yv * (zv / (1.f + expf(-zv)));
        tv[j] = g;
        ss += g * g;
    }
    red[tid] = ss;
    __syncthreads();
    for (int s = 128; s > 0; s >>= 1) {
        if (tid < s) red[tid] += red[tid + s];
        __syncthreads();
    }
    float scale = rsqrtf(red[0] / (float)DINNER + 1e-5f);
#pragma unroll
    for (int j = 0; j < 8; j++) {
        int i = tid + 256 * j;
        float val = tv[j] * scale * norm_w[i];
        __half hv = __float2half(val);
        a2h[(size_t)m * DINNER + i] = hv;
        a2l[(size_t)m * DINNER + i] = __float2half(val - __half2float(hv));
    }
}

// ---------------- launch ----------------
extern "C" void kernel_launch(void* const* d_in, const int* in_sizes, int n_in,
                              void* d_out, int out_size) {
    const float* u      = (const float*)d_in[0];
    const float* W_in   = (const float*)d_in[1];
    const float* conv_w = (const float*)d_in[2];
    const float* conv_b = (const float*)d_in[3];
    const float* dt_b   = (const float*)d_in[4];
    const float* A_log  = (const float*)d_in[5];
    const float* Dv     = (const float*)d_in[6];
    const float* norm_w = (const float*)d_in[7];
    const float* W_out  = (const float*)d_in[8];
    float* out = (float*)d_out;

    float* zx = nullptr;
    cudaGetSymbolAddress((void**)&zx, g_zx);
    __half *a1h, *a1l, *b1h, *a2h, *a2l, *b2h;
    cudaGetSymbolAddress((void**)&a1h, g_a1h);
    cudaGetSymbolAddress((void**)&a1l, g_a1l);
    cudaGetSymbolAddress((void**)&b1h, g_b1h);
    cudaGetSymbolAddress((void**)&a2h, g_a2h);
    cudaGetSymbolAddress((void**)&a2l, g_a2l);
    cudaGetSymbolAddress((void**)&b2h, g_b2h);

    const size_t gemm_smem = 2 * 40960;   // 81920, 2 CTAs/SM
    const size_t cb_smem   = (size_t)(128 * TS_STR + 32 * CS_STR) * sizeof(float);          // 50688
    const size_t diag_smem = (size_t)(128 * TS_STR + 2 * 64 * XS_STR + 192) * sizeof(float); // 69376
    const size_t yoff_smem = (size_t)(128 * TS_STR + 64 * CS2_STR + 64) * sizeof(float);
    cudaFuncSetAttribute(hgemm_kernel, cudaFuncAttributeMaxDynamicSharedMemorySize, (int)gemm_smem);
    cudaFuncSetAttribute(cb_kernel, cudaFuncAttributeMaxDynamicSharedMemorySize, (int)cb_smem);
    cudaFuncSetAttribute(ssd_diag_kernel, cudaFuncAttributeMaxDynamicSharedMemorySize, (int)diag_smem);
    cudaFuncSetAttribute(yoff_kernel, cudaFuncAttributeMaxDynamicSharedMemorySize, (int)yoff_smem);

    // 0: exact fp32 dt
    dt_exact_kernel<<<MROWS / 16, 256>>>(u, W_in, dt_b);

    // 1: prep A (u -> fp16 hi/lo)
    prep_cvt_kernel<<<MROWS * DMODEL / 4096, 1024>>>(u, a1h, a1l);

    // 2: prep W
    prep_w_kernel<<<4480 + 2048, 1024>>>(W_in, W_out, b1h, b2h);

    // 3: GEMM1 (profiled): zx = u @ W_in (fp16 2-product)
    hgemm_kernel<<<dim3(NPAD1 / 64, MROWS / 128), 256, gemm_smem>>>(
        a1h, a1l, b1h, zx, DPROJ, DMODEL, DPROJ);

    // 4: conv
    conv_kernel<<<dim3(CONVCH / 256, MROWS / 16), 256>>>(conv_w, conv_b);

    // 5: CB^T shared across heads
    cb_kernel<<<BQ * NC * 2, 256, cb_smem>>>();

    // 6: SSD intra-chunk
    ssd_diag_kernel<<<BQ * NC * NH, 256, diag_smem>>>(A_log);

    // 7: inter-chunk scan
    scan_kernel<<<(BQ * NH * HD * DSTATE / 2) / 256, 256>>>();

    // 8: Y_off + skip
    yoff_kernel<<<BQ * NC * NH, 256, yoff_smem>>>(Dv);

    // 9: gate + rmsnorm (writes fp16 split A for GEMM2)
    gate_kernel<<<MROWS, 256>>>(norm_w, a2h, a2l);

    // 10: GEMM2: out = y @ W_out (fp16 2-product)
    hgemm_kernel<<<dim3(DMODEL / 64, MROWS / 128), 256, gemm_smem>>>(
        a2h, a2l, b2h, out, DMODEL, DINNER, DMODEL);
}

// round 14
// speedup vs baseline: 2.3802x; 1.1038x over previous
#include <cuda_runtime.h>
#include <cuda_bf16.h>
#include <cuda_fp16.h>
#include <math.h>
#include <cstdint>

// ---------------- problem constants ----------------
#define BQ 2
#define LSEQ 4096
#define DMODEL 1024
#define DINNER 2048
#define NH 32
#define HD 64
#define DSTATE 128
#define CHK 64
#define NC 64
#define DPROJ 4384
#define CONVCH 2304
#define MROWS (BQ*LSEQ)
#define NPAD1 4480
#define NGEMM1 4352     // z (2048) + xBC (2304); dt cols handled exactly elsewhere

// ---------------- scratch (device globals; no allocation) ----------------
__device__ float g_zx[(size_t)MROWS * DPROJ];
__device__ float g_xbc[(size_t)MROWS * CONVCH];
__device__ float g_dt[MROWS * NH];
__device__ float g_acum[BQ * NC * NH * CHK];
__device__ float g_suma[BQ * NC * NH];
__device__ float g_states[(size_t)BQ * NC * NH * HD * DSTATE];
__device__ float g_y[(size_t)MROWS * DINNER];
__device__ float g_cb[(size_t)BQ * NC * CHK * CHK];   // CB^T shared across heads (2MB)

// GEMM operands: fp16, A hi/lo 2-product, B single
__device__ __half g_a1h[(size_t)MROWS * DMODEL];
__device__ __half g_a1l[(size_t)MROWS * DMODEL];
__device__ __half g_b1h[(size_t)NPAD1 * DMODEL];
__device__ __half g_a2h[(size_t)MROWS * DINNER];
__device__ __half g_a2l[(size_t)MROWS * DINNER];
__device__ __half g_b2h[(size_t)DMODEL * DINNER];

// ---------------- PTX helpers ----------------
__device__ __forceinline__ uint32_t smem_u32(const void* p) {
    uint32_t a;
    asm("{ .reg .u64 t; cvta.to.shared.u64 t, %1; cvt.u32.u64 %0, t; }" : "=r"(a) : "l"(p));
    return a;
}
#define SMEM_SWIZZLE_128B(byte_offset) ((byte_offset) ^ (((byte_offset) >> 3) & 0x70))
#define CP_ASYNC16(dst, src) \
    asm volatile("cp.async.cg.shared.global [%0], [%1], 16;" :: "r"(dst), "l"(src) : "memory")
#define CP_COMMIT() asm volatile("cp.async.commit_group;" ::: "memory")
#define CP_WAIT0()  asm volatile("cp.async.wait_group 0;" ::: "memory")

#define LDSM_X4(r0,r1,r2,r3,addr) \
    asm volatile("ldmatrix.sync.aligned.m8n8.x4.shared.b16 {%0,%1,%2,%3}, [%4];" \
        : "=r"(r0), "=r"(r1), "=r"(r2), "=r"(r3) : "r"(addr))

#define MMAH16816(d, a, b0, b1) \
    asm volatile("mma.sync.aligned.m16n8k16.row.col.f32.f16.f16.f32 " \
        "{%0,%1,%2,%3}, {%4,%5,%6,%7}, {%8,%9}, {%0,%1,%2,%3};" \
        : "+f"((d)[0]), "+f"((d)[1]), "+f"((d)[2]), "+f"((d)[3]) \
        : "r"((a)[0]), "r"((a)[1]), "r"((a)[2]), "r"((a)[3]), "r"(b0), "r"(b1))

// packed f32x2 (2x fp32 FMA rate)
#define FMA2(d, a, b) asm("fma.rn.f32x2 %0, %1, %2, %0;" : "+l"(d) : "l"(a), "l"(b))
#define MUL2(d, a, b) asm("mul.rn.f32x2 %0, %1, %2;" : "=l"(d) : "l"(a), "l"(b))
__device__ __forceinline__ uint64_t dup2(float x) {
    uint64_t r; asm("mov.b64 %0, {%1, %1};" : "=l"(r) : "f"(x)); return r;
}
__device__ __forceinline__ void up2(uint64_t v, float& lo, float& hi) {
    asm("mov.b64 {%0, %1}, %2;" : "=f"(lo), "=f"(hi) : "l"(v));
}

__device__ __forceinline__ void ldsmA(uint32_t base, int row, int ks, int lane, uint32_t* r) {
    int rr = row + (lane & 15);
    int off = rr * 128 + ks * 32 + ((lane >> 4) << 4);
    LDSM_X4(r[0], r[1], r[2], r[3], base + SMEM_SWIZZLE_128B((uint32_t)off));
}
__device__ __forceinline__ void ldsmB(uint32_t base, int nrow, int ks, int lane, uint32_t* r) {
    int n = nrow + ((lane >> 4) << 3) + (lane & 7);
    int off = n * 128 + ks * 32 + (((lane >> 3) & 1) << 4);
    LDSM_X4(r[0], r[1], r[2], r[3], base + SMEM_SWIZZLE_128B((uint32_t)off));
}

// ---------------- fp16 2-product GEMM (70.5% tensor) ----------------
__global__ __launch_bounds__(256, 2) void hgemm_kernel(
    const __half* __restrict__ Ah, const __half* __restrict__ Al,
    const __half* __restrict__ Bh, float* __restrict__ C, int N, int K, int ldc)
{
    extern __shared__ char smem[];
    const uint32_t sb = smem_u32(smem);
    const int tid = threadIdx.x, wid = tid >> 5, lane = tid & 31;
    const int wr = wid & 3, wc = wid >> 2;
    const int rowbase = blockIdx.y * 128, colbase = blockIdx.x * 64;
    const int KC = K >> 6;

    float acc[2][4][4];
#pragma unroll
    for (int mi = 0; mi < 2; mi++)
#pragma unroll
        for (int ni = 0; ni < 4; ni++)
#pragma unroll
            for (int j = 0; j < 4; j++) acc[mi][ni][j] = 0.f;

    auto issue_chunk = [&](int i) {
        const uint32_t st = (uint32_t)(i & 1) * 40960u;
        const int k0 = i << 6;
#pragma unroll
        for (int v = 0; v < 10; v++) {
            const int idx = v * 256 + tid;
            const __half* src;
            uint32_t dst;
            if (idx < 2048) {
                const int buf = idx >> 10;
                const int r = (idx & 1023) >> 3, c8 = idx & 7;
                src = (buf ? Al : Ah) + (size_t)(rowbase + r) * K + k0 + c8 * 8;
                dst = sb + st + (uint32_t)buf * 16384u +
                      SMEM_SWIZZLE_128B((uint32_t)(r * 128 + c8 * 16));
            } else {
                const int j = idx - 2048;
                const int r = j >> 3, c8 = j & 7;
                src = Bh + (size_t)(colbase + r) * K + k0 + c8 * 8;
                dst = sb + st + 32768u + SMEM_SWIZZLE_128B((uint32_t)(r * 128 + c8 * 16));
            }
            CP_ASYNC16(dst, src);
        }
    };

    issue_chunk(0);
    CP_COMMIT();

    for (int i = 0; i < KC; i++) {
        CP_WAIT0();
        __syncthreads();
        if (i + 1 < KC) { issue_chunk(i + 1); CP_COMMIT(); }

        const uint32_t st = sb + (uint32_t)(i & 1) * 40960u;
        const uint32_t aH = st, aL = st + 16384u, bH = st + 32768u;
#pragma unroll
        for (int ks = 0; ks < 4; ks++) {
            uint32_t ah[2][4], al[2][4], bh[2][4];
#pragma unroll
            for (int mi = 0; mi < 2; mi++) {
                ldsmA(aH, wr * 32 + mi * 16, ks, lane, ah[mi]);
                ldsmA(aL, wr * 32 + mi * 16, ks, lane, al[mi]);
            }
#pragma unroll
            for (int np = 0; np < 2; np++)
                ldsmB(bH, wc * 32 + np * 16, ks, lane, bh[np]);
#pragma unroll
            for (int mi = 0; mi < 2; mi++)
#pragma unroll
                for (int ni = 0; ni < 4; ni++) {
                    const int np = ni >> 1, o = (ni & 1) << 1;
                    MMAH16816(acc[mi][ni], ah[mi], bh[np][o], bh[np][o + 1]);
                    MMAH16816(acc[mi][ni], al[mi], bh[np][o], bh[np][o + 1]);
                }
        }
        __syncthreads();
    }

#pragma unroll
    for (int mi = 0; mi < 2; mi++) {
        const int row = rowbase + wr * 32 + mi * 16 + (lane >> 2);
#pragma unroll
        for (int ni = 0; ni < 4; ni++) {
            const int col = colbase + wc * 32 + ni * 8 + (lane & 3) * 2;
            if (col < N) {
                *reinterpret_cast<float2*>(&C[(size_t)row * ldc + col]) =
                    make_float2(acc[mi][ni][0], acc[mi][ni][1]);
                *reinterpret_cast<float2*>(&C[(size_t)(row + 8) * ldc + col]) =
                    make_float2(acc[mi][ni][2], acc[mi][ni][3]);
            }
        }
    }
}

// ---------------- exact fp32 dt ----------------
__global__ __launch_bounds__(256) void dt_exact_kernel(const float* __restrict__ u,
                                                       const float* __restrict__ W_in,
                                                       const float* __restrict__ dt_bias) {
    __shared__ float us[16 * 256];
    __shared__ float ws[256 * 32];
    const int m0 = blockIdx.x * 16;
    const int t = threadIdx.x;
    const int mloc = t >> 4, h0 = t & 15, h1 = 16 + (t & 15);
    float acc0 = 0.f, acc1 = 0.f;
    for (int kc = 0; kc < 4; kc++) {
        __syncthreads();
        for (int i = t; i < 4096; i += 256) {
            int mm = i >> 8, kk = i & 255;
            us[i] = u[(size_t)(m0 + mm) * DMODEL + kc * 256 + kk];
        }
        for (int i = t; i < 8192; i += 256) {
            int kk = i >> 5, hh = i & 31;
            ws[i] = W_in[(size_t)(kc * 256 + kk) * DPROJ + (DPROJ - NH) + hh];
        }
        __syncthreads();
#pragma unroll 8
        for (int kk = 0; kk < 256; kk++) {
            float uv = us[mloc * 256 + kk];
            acc0 = fmaf(uv, ws[kk * 32 + h0], acc0);
            acc1 = fmaf(uv, ws[kk * 32 + h1], acc1);
        }
    }
    float x0 = acc0 + dt_bias[h0];
    float x1 = acc1 + dt_bias[h1];
    g_dt[(m0 + mloc) * NH + h0] = (x0 > 20.f) ? x0 : log1pf(expf(x0));
    g_dt[(m0 + mloc) * NH + h1] = (x1 > 20.f) ? x1 : log1pf(expf(x1));
}

// ---------------- prep A: u -> fp16 hi/lo ----------------
__global__ __launch_bounds__(1024) void prep_cvt_kernel(const float* __restrict__ u,
                                                        __half* __restrict__ a1h,
                                                        __half* __restrict__ a1l) {
    int i = blockIdx.x * 1024 + threadIdx.x;
    float4 x = reinterpret_cast<const float4*>(u)[i];
    float xs[4] = {x.x, x.y, x.z, x.w};
    __half h[4], l[4];
#pragma unroll
    for (int j = 0; j < 4; j++) {
        h[j] = __float2half(xs[j]);
        l[j] = __float2half(xs[j] - __half2float(h[j]));
    }
    reinterpret_cast<__half2*>(a1h)[2 * i]     = __half2(h[0], h[1]);
    reinterpret_cast<__half2*>(a1h)[2 * i + 1] = __half2(h[2], h[3]);
    reinterpret_cast<__half2*>(a1l)[2 * i]     = __half2(l[0], l[1]);
    reinterpret_cast<__half2*>(a1l)[2 * i + 1] = __half2(l[2], l[3]);
}

// ---------------- prep W: transpose W_in and W_out to fp16 [N][K] ----------------
__global__ __launch_bounds__(1024) void prep_w_kernel(const float* __restrict__ W_in,
                                                      const float* __restrict__ W_out,
                                                      __half* __restrict__ b1h,
                                                      __half* __restrict__ b2h) {
    __shared__ float t[32][33];
    const int bx = blockIdx.x, tid = threadIdx.x;
    const int tx = tid & 31, ty = tid >> 5;
    if (bx < 4352) {                        // only the 4352 used n-rows (136 per k-strip)
        int bxx = bx % 136, byy = bx / 136;
        int n = bxx * 32 + tx, k = byy * 32 + ty;
        t[ty][tx] = W_in[(size_t)k * DPROJ + n];
        __syncthreads();
        int nn = bxx * 32 + ty, kk = byy * 32 + tx;
        b1h[(size_t)nn * DMODEL + kk] = __float2half(t[tx][ty]);
    } else {
        int bb = bx - 4352;
        int bxx = bb % 32, byy = bb / 32;
        int n = bxx * 32 + tx, k = byy * 32 + ty;
        t[ty][tx] = W_out[(size_t)k * DMODEL + n];
        __syncthreads();
        int nn = bxx * 32 + ty, kk = byy * 32 + tx;
        b2h[(size_t)nn * DINNER + kk] = __float2half(t[tx][ty]);
    }
}

// ---------------- depthwise causal conv(4) + bias + SiLU (32 rows/block) ----------------
__global__ __launch_bounds__(256) void conv_kernel(const float* __restrict__ cw,
                                                   const float* __restrict__ cb) {
    __shared__ float s[35][256];
    int tid = threadIdx.x;
    int ch = blockIdx.x * 256 + tid;
    int m0 = blockIdx.y * 32;
    int l0 = m0 & (LSEQ - 1);
#pragma unroll
    for (int r = 0; r < 35; r++) {
        int l = l0 - 3 + r;
        s[r][tid] = (l >= 0) ? g_zx[(size_t)(m0 - 3 + r) * DPROJ + DINNER + ch] : 0.f;
    }
    __syncthreads();
    float w0 = cw[ch * 4], w1 = cw[ch * 4 + 1], w2 = cw[ch * 4 + 2], w3 = cw[ch * 4 + 3];
    float bias = cb[ch];
#pragma unroll
    for (int r = 0; r < 32; r++) {
        float acc = bias;
        acc = fmaf(s[r][tid], w0, acc);
        acc = fmaf(s[r + 1][tid], w1, acc);
        acc = fmaf(s[r + 2][tid], w2, acc);
        acc = fmaf(s[r + 3][tid], w3, acc);
        g_xbc[(size_t)(m0 + r) * CONVCH + ch] = acc / (1.f + expf(-acc));
    }
}

#define TS_STR 66
#define CS_STR 132
#define XS_STR 68

// ---------------- CB^T = C·B^T per (b,c), shared across heads ----------------
__global__ __launch_bounds__(256, 2) void cb_kernel() {
    int blk = blockIdx.x;
    int bc = blk >> 1, half = blk & 1;
    int m0 = (bc >> 6) * LSEQ + (bc & 63) * CHK;
    extern __shared__ float sm[];
    float* Bst = sm;                 // [n][s] 128 x 66
    float* Cs  = Bst + 128 * TS_STR; // [lloc][n] 32 x 132
    int tid = threadIdx.x;
    for (int i = tid; i < 64 * 128; i += 256) {
        int l = i >> 7, n = i & 127;
        Bst[n * TS_STR + l] = g_xbc[(size_t)(m0 + l) * CONVCH + DINNER + n];
    }
    for (int i = tid; i < 32 * 32; i += 256) {
        int ll = i >> 5, q = i & 31;
        float4 v = *reinterpret_cast<const float4*>(
            g_xbc + (size_t)(m0 + half * 32 + ll) * CONVCH + DINNER + DSTATE + 4 * q);
        *reinterpret_cast<float4*>(Cs + ll * CS_STR + 4 * q) = v;
    }
    __syncthreads();
    const int rg = tid >> 5, cg = tid & 31;
    const int r0 = rg * 4, c0 = cg * 2;
    float* out = g_cb + (size_t)bc * 4096 + (size_t)(half * 32) * 64;
    if (c0 > half * 32 + r0 + 3) {
#pragma unroll
        for (int i = 0; i < 4; i++)
            *reinterpret_cast<float2*>(out + (r0 + i) * 64 + c0) = make_float2(0.f, 0.f);
        return;
    }
    uint64_t acc2[4] = {0ull, 0ull, 0ull, 0ull};
    for (int n4 = 0; n4 < 128; n4 += 4) {
        float4 cr[4];
#pragma unroll
        for (int i = 0; i < 4; i++)
            cr[i] = *reinterpret_cast<const float4*>(Cs + (r0 + i) * CS_STR + n4);
#pragma unroll
        for (int nn = 0; nn < 4; nn++) {
            uint64_t b2 = *reinterpret_cast<const uint64_t*>(Bst + (n4 + nn) * TS_STR + c0);
#pragma unroll
            for (int i = 0; i < 4; i++) {
                uint64_t a2 = dup2((&cr[i].x)[nn]);
                FMA2(acc2[i], a2, b2);
            }
        }
    }
#pragma unroll
    for (int i = 0; i < 4; i++) {
        float v0, v1;
        up2(acc2[i], v0, v1);
        *reinterpret_cast<float2*>(out + (r0 + i) * 64 + c0) = make_float2(v0, v1);
    }
}

// ---------------- SSD intra-chunk: loads shared CB, applies per-head decay ----------
__global__ __launch_bounds__(256, 3) void ssd_diag_kernel(const float* __restrict__ A_log) {
    int blk = blockIdx.x;
    int h = blk & 31;
    int c = (blk >> 5) & 63;
    int b = blk >> 11;
    int m0 = b * LSEQ + c * CHK;

    extern __shared__ float sm[];
    float* Bst = sm;                         // 128*66
    float* xs  = Bst + 128 * TS_STR;         // 64*68
    float* Gs  = xs + 64 * XS_STR;           // 64*68
    float* ac  = Gs + 64 * XS_STR;           // 64
    float* wd  = ac + 64;                    // 64
    float* dts = wd + 64;                    // 64
    int tid = threadIdx.x;

    if (tid < 32) {
        float A = -expf(A_log[h]);
        float dt0 = g_dt[(m0 + 2 * tid) * NH + h];
        float dt1 = g_dt[(m0 + 2 * tid + 1) * NH + h];
        dts[2 * tid] = dt0;
        dts[2 * tid + 1] = dt1;
        float e0 = A * dt0, e1 = A * dt1;
        float run = e0 + e1;
#pragma unroll
        for (int off = 1; off < 32; off <<= 1) {
            float v = __shfl_up_sync(0xFFFFFFFFu, run, off);
            if (tid >= off) run += v;
        }
        ac[2 * tid]     = run - e1;
        ac[2 * tid + 1] = run;
    }
    __syncthreads();
    if (tid < 64) {
        wd[tid] = expf(ac[63] - ac[tid]);
        g_acum[blk * CHK + tid] = ac[tid];
    }
    if (tid == 0) g_suma[blk] = expf(ac[63]);

    for (int i = tid; i < 64 * 128; i += 256) {
        int l = i >> 7, n = i & 127;
        Bst[n * TS_STR + l] = g_xbc[(size_t)(m0 + l) * CONVCH + DINNER + n];
    }
    for (int i = tid; i < 64 * 16; i += 256) {
        int l = i >> 4, q = i & 15;
        float dtv = dts[l];
        float4 v = *reinterpret_cast<const float4*>(
            g_xbc + (size_t)(m0 + l) * CONVCH + h * HD + 4 * q);
        v.x *= dtv; v.y *= dtv; v.z *= dtv; v.w *= dtv;
        *reinterpret_cast<float4*>(xs + l * XS_STR + 4 * q) = v;
    }
    {
        const float* cb = g_cb + (size_t)(b * NC + c) * 4096;
        for (int i = tid; i < 4096; i += 256) {
            int l = i >> 6, s = i & 63;
            float v = cb[i];
            Gs[l * XS_STR + s] = (s <= l) ? v * expf(ac[l] - ac[s]) : 0.f;
        }
    }
    __syncthreads();

    const int tr = tid >> 4, tc = tid & 15;
    const int r0 = tr * 4, c0 = tc * 4;

    // --- Y_diag[l][p] = sum_{s<=l} G[l][s]*x[s][p] ---
    {
        uint64_t acc2[4][2] = {{0ull,0ull},{0ull,0ull},{0ull,0ull},{0ull,0ull}};
        for (int s4 = 0; s4 < r0 + 4; s4 += 4) {
            float4 gr[4];
#pragma unroll
            for (int i = 0; i < 4; i++)
                gr[i] = *reinterpret_cast<const float4*>(Gs + (r0 + i) * XS_STR + s4);
#pragma unroll
            for (int ss = 0; ss < 4; ss++) {
                uint64_t x0 = *reinterpret_cast<const uint64_t*>(xs + (s4 + ss) * XS_STR + c0);
                uint64_t x1 = *reinterpret_cast<const uint64_t*>(xs + (s4 + ss) * XS_STR + c0 + 2);
#pragma unroll
                for (int i = 0; i < 4; i++) {
                    uint64_t a2 = dup2((&gr[i].x)[ss]);
                    FMA2(acc2[i][0], a2, x0);
                    FMA2(acc2[i][1], a2, x1);
                }
            }
        }
#pragma unroll
        for (int i = 0; i < 4; i++) {
            float v0, v1, v2, v3;
            up2(acc2[i][0], v0, v1);
            up2(acc2[i][1], v2, v3);
            *reinterpret_cast<float4*>(g_y + (size_t)(m0 + r0 + i) * DINNER + h * HD + c0) =
                make_float4(v0, v1, v2, v3);
        }
    }

    // --- states S[p][n] = sum_l wd[l]*x[l][p]*B[l][n] ---
    {
        const int p0 = (tid & 15) * 4, n0 = (tid >> 4) * 8;
        uint64_t acc2[2][8];
#pragma unroll
        for (int pp = 0; pp < 2; pp++)
#pragma unroll
            for (int j = 0; j < 8; j++) acc2[pp][j] = 0ull;
        for (int l = 0; l < 64; l++) {
            uint64_t w2 = dup2(wd[l]);
            uint64_t xa = *reinterpret_cast<const uint64_t*>(xs + l * XS_STR + p0);
            uint64_t xb = *reinterpret_cast<const uint64_t*>(xs + l * XS_STR + p0 + 2);
            uint64_t wxa, wxb;
            MUL2(wxa, xa, w2);
            MUL2(wxb, xb, w2);
#pragma unroll
            for (int j = 0; j < 8; j++) {
                uint64_t b2 = dup2(Bst[(n0 + j) * TS_STR + l]);
                FMA2(acc2[0][j], wxa, b2);
                FMA2(acc2[1][j], wxb, b2);
            }
        }
        float rowv[4][8];
#pragma unroll
        for (int pp = 0; pp < 2; pp++)
#pragma unroll
            for (int j = 0; j < 8; j++)
                up2(acc2[pp][j], rowv[2 * pp][j], rowv[2 * pp + 1][j]);
#pragma unroll
        for (int i = 0; i < 4; i++) {
            float* dst = g_states + ((size_t)blk * HD + p0 + i) * DSTATE + n0;
            *reinterpret_cast<float4*>(dst)     = make_float4(rowv[i][0], rowv[i][1], rowv[i][2], rowv[i][3]);
            *reinterpret_cast<float4*>(dst + 4) = make_float4(rowv[i][4], rowv[i][5], rowv[i][6], rowv[i][7]);
        }
    }
}

// ---------------- inter-chunk scan (float2 + prefetch) ----------------
__global__ void scan_kernel() {
    int idx = blockIdx.x * blockDim.x + threadIdx.x;
    int n2 = idx & 63;
    int p = (idx >> 6) & 63;
    int h = (idx >> 12) & 31;
    int b = idx >> 17;
    const size_t cstep = (size_t)NH * HD * DSTATE;
    int bch0 = b * NC * NH + h;
    size_t off = ((size_t)bch0 * HD + p) * DSTATE + 2 * n2;
    float2 prev = make_float2(0.f, 0.f);
    float2 loc = *reinterpret_cast<float2*>(g_states + off);
    for (int c = 0; c < NC; c++) {
        float2 nxt = (c + 1 < NC) ? *reinterpret_cast<float2*>(g_states + off + cstep)
                                  : make_float2(0.f, 0.f);
        float e = g_suma[bch0 + c * NH];
        *reinterpret_cast<float2*>(g_states + off) = prev;
        prev.x = fmaf(prev.x, e, loc.x);
        prev.y = fmaf(prev.y, e, loc.y);
        loc = nxt;
        off += cstep;
    }
}

// ---------------- Y_off + skip (f32x2, half-C double pass, 3 CTAs/SM) ----------------
#define CS2_STR 68
__global__ __launch_bounds__(256, 3) void yoff_kernel(const float* __restrict__ Dv) {
    int blk = blockIdx.x;
    int h = blk & 31;
    int c = (blk >> 5) & 63;
    int b = blk >> 11;
    int m0 = b * LSEQ + c * CHK;

    extern __shared__ float sm[];
    float* Pst = sm;                        // 128 x stride 66 ([n][p])
    float* Cs2 = Pst + 128 * TS_STR;        // 64 x stride 68 (half of C)
    float* ac  = Cs2 + 64 * CS2_STR;        // 64
    int tid = threadIdx.x;

    for (int i = tid; i < 64 * 128; i += 256) {
        int p = i >> 7, n = i & 127;
        Pst[n * TS_STR + p] = g_states[((size_t)blk * HD + p) * DSTATE + n];
    }
    if (tid < 64) ac[tid] = g_acum[blk * CHK + tid];
    float Dh = Dv[h];

    const int tr = tid >> 4, tc = tid & 15;
    const int r0 = tr * 4, c0 = tc * 4;
    uint64_t acc2[4][2] = {{0ull,0ull},{0ull,0ull},{0ull,0ull},{0ull,0ull}};

#pragma unroll
    for (int half = 0; half < 2; half++) {
        __syncthreads();
        for (int i = tid; i < 64 * 16; i += 256) {
            int l = i >> 4, q = i & 15;
            float4 v = *reinterpret_cast<const float4*>(
                g_xbc + (size_t)(m0 + l) * CONVCH + DINNER + DSTATE + half * 64 + 4 * q);
            *reinterpret_cast<float4*>(Cs2 + l * CS2_STR + 4 * q) = v;
        }
        __syncthreads();
        for (int n4 = 0; n4 < 64; n4 += 4) {
            float4 cr[4];
#pragma unroll
            for (int i = 0; i < 4; i++)
                cr[i] = *reinterpret_cast<const float4*>(Cs2 + (r0 + i) * CS2_STR + n4);
#pragma unroll
            for (int nn = 0; nn < 4; nn++) {
                int n = half * 64 + n4 + nn;
                uint64_t p0v = *reinterpret_cast<const uint64_t*>(Pst + n * TS_STR + c0);
                uint64_t p1v = *reinterpret_cast<const uint64_t*>(Pst + n * TS_STR + c0 + 2);
#pragma unroll
                for (int i = 0; i < 4; i++) {
                    uint64_t a2 = dup2((&cr[i].x)[nn]);
                    FMA2(acc2[i][0], a2, p0v);
                    FMA2(acc2[i][1], a2, p1v);
                }
            }
        }
    }

#pragma unroll
    for (int i = 0; i < 4; i++) {
        int l = r0 + i;
        int row = m0 + l;
        float el = expf(ac[l]);
        float v0, v1, v2, v3;
        up2(acc2[i][0], v0, v1);
        up2(acc2[i][1], v2, v3);
        float4 xv = *reinterpret_cast<const float4*>(
            g_xbc + (size_t)row * CONVCH + h * HD + c0);
        float4* yp = reinterpret_cast<float4*>(g_y + (size_t)row * DINNER + h * HD + c0);
        float4 yv = *yp;
        yv.x += v0 * el + xv.x * Dh;
        yv.y += v1 * el + xv.y * Dh;
        yv.z += v2 * el + xv.z * Dh;
        yv.w += v3 * el + xv.w * Dh;
        *yp = yv;
    }
}

// ---------------- gate (silu(z)) + RMSNorm, shuffle reduction, fp16 split out ----------
__global__ void gate_kernel(const float* __restrict__ norm_w,
                            __half* __restrict__ a2h, __half* __restrict__ a2l) {
    int m = blockIdx.x;
    int tid = threadIdx.x;
    __shared__ float wsum[8];
    float tv[8];
    float ss = 0.f;
#pragma unroll
    for (int j = 0; j < 8; j++) {
        int i = tid + 256 * j;
        float zv = g_zx[(size_t)m * DPROJ + i];
        float yv = g_y[(size_t)m * DINNER + i];
        float g = yv * (zv / (1.f + expf(-zv)));
        tv[j] = g;
        ss += g * g;
    }
#pragma unroll
    for (int o = 16; o; o >>= 1) ss += __shfl_xor_sync(0xFFFFFFFFu, ss, o);
    if ((tid & 31) == 0) wsum[tid >> 5] = ss;
    __syncthreads();
    float tot = wsum[0] + wsum[1] + wsum[2] + wsum[3] +
                wsum[4] + wsum[5] + wsum[6] + wsum[7];
    float scale = rsqrtf(tot / (float)DINNER + 1e-5f);
#pragma unroll
    for (int j = 0; j < 8; j++) {
        int i = tid + 256 * j;
        float val = tv[j] * scale * norm_w[i];
        __half hv = __float2half(val);
        a2h[(size_t)m * DINNER + i] = hv;
        a2l[(size_t)m * DINNER + i] = __float2half(val - __half2float(hv));
    }
}

// ---------------- launch ----------------
extern "C" void kernel_launch(void* const* d_in, const int* in_sizes, int n_in,
                              void* d_out, int out_size) {
    const float* u      = (const float*)d_in[0];
    const float* W_in   = (const float*)d_in[1];
    const float* conv_w = (const float*)d_in[2];
    const float* conv_b = (const float*)d_in[3];
    const float* dt_b   = (const float*)d_in[4];
    const float* A_log  = (const float*)d_in[5];
    const float* Dv     = (const float*)d_in[6];
    const float* norm_w = (const float*)d_in[7];
    const float* W_out  = (const float*)d_in[8];
    float* out = (float*)d_out;

    float* zx = nullptr;
    cudaGetSymbolAddress((void**)&zx, g_zx);
    __half *a1h, *a1l, *b1h, *a2h, *a2l, *b2h;
    cudaGetSymbolAddress((void**)&a1h, g_a1h);
    cudaGetSymbolAddress((void**)&a1l, g_a1l);
    cudaGetSymbolAddress((void**)&b1h, g_b1h);
    cudaGetSymbolAddress((void**)&a2h, g_a2h);
    cudaGetSymbolAddress((void**)&a2l, g_a2l);
    cudaGetSymbolAddress((void**)&b2h, g_b2h);

    const size_t gemm_smem = 2 * 40960;
    const size_t cb_smem   = (size_t)(128 * TS_STR + 32 * CS_STR) * sizeof(float);
    const size_t diag_smem = (size_t)(128 * TS_STR + 2 * 64 * XS_STR + 192) * sizeof(float);
    const size_t yoff_smem = (size_t)(128 * TS_STR + 64 * CS2_STR + 64) * sizeof(float);
    cudaFuncSetAttribute(hgemm_kernel, cudaFuncAttributeMaxDynamicSharedMemorySize, (int)gemm_smem);
    cudaFuncSetAttribute(cb_kernel, cudaFuncAttributeMaxDynamicSharedMemorySize, (int)cb_smem);
    cudaFuncSetAttribute(ssd_diag_kernel, cudaFuncAttributeMaxDynamicSharedMemorySize, (int)diag_smem);
    cudaFuncSetAttribute(yoff_kernel, cudaFuncAttributeMaxDynamicSharedMemorySize, (int)yoff_smem);

    // 0: exact fp32 dt
    dt_exact_kernel<<<MROWS / 16, 256>>>(u, W_in, dt_b);

    // 1: prep A (u -> fp16 hi/lo)
    prep_cvt_kernel<<<MROWS * DMODEL / 4096, 1024>>>(u, a1h, a1l);

    // 2: prep W
    prep_w_kernel<<<4352 + 2048, 1024>>>(W_in, W_out, b1h, b2h);

    // 3: GEMM1 (profiled): zx[:, :4352] = u @ W_in (fp16 2-product, dt cols skipped)
    hgemm_kernel<<<dim3(NGEMM1 / 64, MROWS / 128), 256, gemm_smem>>>(
        a1h, a1l, b1h, zx, NGEMM1, DMODEL, DPROJ);

    // 4: conv (32 rows/block)
    conv_kernel<<<dim3(CONVCH / 256, MROWS / 32), 256>>>(conv_w, conv_b);

    // 5: CB^T shared across heads
    cb_kernel<<<BQ * NC * 2, 256, cb_smem>>>();

    // 6: SSD intra-chunk
    ssd_diag_kernel<<<BQ * NC * NH, 256, diag_smem>>>(A_log);

    // 7: inter-chunk scan
    scan_kernel<<<(BQ * NH * HD * DSTATE / 2) / 256, 256>>>();

    // 8: Y_off + skip
    yoff_kernel<<<BQ * NC * NH, 256, yoff_smem>>>(Dv);

    // 9: gate + rmsnorm (writes fp16 split A for GEMM2)
    gate_kernel<<<MROWS, 256>>>(norm_w, a2h, a2l);

    // 10: GEMM2: out = y @ W_out (fp16 2-product)
    hgemm_kernel<<<dim3(DMODEL / 64, MROWS / 128), 256, gemm_smem>>>(
        a2h, a2l, b2h, out, DMODEL, DINNER, DMODEL);
}

// round 15
// speedup vs baseline: 2.6818x; 1.1267x over previous
#include <cuda_runtime.h>
#include <cuda_bf16.h>
#include <cuda_fp16.h>
#include <math.h>
#include <cstdint>

// ---------------- problem constants ----------------
#define BQ 2
#define LSEQ 4096
#define DMODEL 1024
#define DINNER 2048
#define NH 32
#define HD 64
#define DSTATE 128
#define CHK 64
#define NC 64
#define DPROJ 4384
#define CONVCH 2304
#define MROWS (BQ*LSEQ)
#define NPAD1 4480
#define NGEMM1 4352     // z (2048) + xBC (2304); dt cols handled exactly elsewhere

// ---------------- scratch (device globals; no allocation) ----------------
__device__ float g_zx[(size_t)MROWS * DPROJ];
__device__ float g_xbc[(size_t)MROWS * CONVCH];
__device__ float g_dt[MROWS * NH];
__device__ float g_acum[BQ * NC * NH * CHK];
__device__ float g_suma[BQ * NC * NH];
__device__ float g_states[(size_t)BQ * NC * NH * HD * DSTATE];
__device__ float g_y[(size_t)MROWS * DINNER];
__device__ float g_cb[(size_t)BQ * NC * CHK * CHK];   // CB^T shared across heads (2MB)

// GEMM operands (fp16). GEMM1: single product (Ah x Bh). GEMM2: A hi/lo 2-product.
__device__ __half g_a1h[(size_t)MROWS * DMODEL];
__device__ __half g_b1h[(size_t)NPAD1 * DMODEL];
__device__ __half g_a2h[(size_t)MROWS * DINNER];
__device__ __half g_a2l[(size_t)MROWS * DINNER];
__device__ __half g_b2h[(size_t)DMODEL * DINNER];

// ---------------- PTX helpers ----------------
__device__ __forceinline__ uint32_t smem_u32(const void* p) {
    uint32_t a;
    asm("{ .reg .u64 t; cvta.to.shared.u64 t, %1; cvt.u32.u64 %0, t; }" : "=r"(a) : "l"(p));
    return a;
}
#define SMEM_SWIZZLE_128B(byte_offset) ((byte_offset) ^ (((byte_offset) >> 3) & 0x70))
#define CP_ASYNC16(dst, src) \
    asm volatile("cp.async.cg.shared.global [%0], [%1], 16;" :: "r"(dst), "l"(src) : "memory")
#define CP_COMMIT() asm volatile("cp.async.commit_group;" ::: "memory")
#define CP_WAIT0()  asm volatile("cp.async.wait_group 0;" ::: "memory")

#define LDSM_X4(r0,r1,r2,r3,addr) \
    asm volatile("ldmatrix.sync.aligned.m8n8.x4.shared.b16 {%0,%1,%2,%3}, [%4];" \
        : "=r"(r0), "=r"(r1), "=r"(r2), "=r"(r3) : "r"(addr))

#define MMAH16816(d, a, b0, b1) \
    asm volatile("mma.sync.aligned.m16n8k16.row.col.f32.f16.f16.f32 " \
        "{%0,%1,%2,%3}, {%4,%5,%6,%7}, {%8,%9}, {%0,%1,%2,%3};" \
        : "+f"((d)[0]), "+f"((d)[1]), "+f"((d)[2]), "+f"((d)[3]) \
        : "r"((a)[0]), "r"((a)[1]), "r"((a)[2]), "r"((a)[3]), "r"(b0), "r"(b1))

// packed f32x2 (2x fp32 FMA rate)
#define FMA2(d, a, b) asm("fma.rn.f32x2 %0, %1, %2, %0;" : "+l"(d) : "l"(a), "l"(b))
#define MUL2(d, a, b) asm("mul.rn.f32x2 %0, %1, %2;" : "=l"(d) : "l"(a), "l"(b))
__device__ __forceinline__ uint64_t dup2(float x) {
    uint64_t r; asm("mov.b64 %0, {%1, %1};" : "=l"(r) : "f"(x)); return r;
}
__device__ __forceinline__ void up2(uint64_t v, float& lo, float& hi) {
    asm("mov.b64 {%0, %1}, %2;" : "=f"(lo), "=f"(hi) : "l"(v));
}

__device__ __forceinline__ void ldsmA(uint32_t base, int row, int ks, int lane, uint32_t* r) {
    int rr = row + (lane & 15);
    int off = rr * 128 + ks * 32 + ((lane >> 4) << 4);
    LDSM_X4(r[0], r[1], r[2], r[3], base + SMEM_SWIZZLE_128B((uint32_t)off));
}
__device__ __forceinline__ void ldsmB(uint32_t base, int nrow, int ks, int lane, uint32_t* r) {
    int n = nrow + ((lane >> 4) << 3) + (lane & 7);
    int off = n * 128 + ks * 32 + (((lane >> 3) & 1) << 4);
    LDSM_X4(r[0], r[1], r[2], r[3], base + SMEM_SWIZZLE_128B((uint32_t)off));
}

// ---------------- GEMM1: single-product fp16. stage: A 16K + B 8K = 24K; 2 stages ----------------
__global__ __launch_bounds__(256, 2) void hgemm1_kernel(
    const __half* __restrict__ Ah, const __half* __restrict__ Bh,
    float* __restrict__ C, int N, int K, int ldc)
{
    extern __shared__ char smem[];
    const uint32_t sb = smem_u32(smem);
    const int tid = threadIdx.x, wid = tid >> 5, lane = tid & 31;
    const int wr = wid & 3, wc = wid >> 2;
    const int rowbase = blockIdx.y * 128, colbase = blockIdx.x * 64;
    const int KC = K >> 6;

    float acc[2][4][4];
#pragma unroll
    for (int mi = 0; mi < 2; mi++)
#pragma unroll
        for (int ni = 0; ni < 4; ni++)
#pragma unroll
            for (int j = 0; j < 4; j++) acc[mi][ni][j] = 0.f;

    auto issue_chunk = [&](int i) {
        const uint32_t st = (uint32_t)(i & 1) * 24576u;
        const int k0 = i << 6;
#pragma unroll
        for (int v = 0; v < 6; v++) {
            const int idx = v * 256 + tid;     // 0..1535
            const __half* src;
            uint32_t dst;
            if (idx < 1024) {                  // A: 128 rows x 8 c8
                const int r = idx >> 3, c8 = idx & 7;
                src = Ah + (size_t)(rowbase + r) * K + k0 + c8 * 8;
                dst = sb + st + SMEM_SWIZZLE_128B((uint32_t)(r * 128 + c8 * 16));
            } else {                           // B: 64 rows x 8 c8
                const int j = idx - 1024;
                const int r = j >> 3, c8 = j & 7;
                src = Bh + (size_t)(colbase + r) * K + k0 + c8 * 8;
                dst = sb + st + 16384u + SMEM_SWIZZLE_128B((uint32_t)(r * 128 + c8 * 16));
            }
            CP_ASYNC16(dst, src);
        }
    };

    issue_chunk(0);
    CP_COMMIT();

    for (int i = 0; i < KC; i++) {
        CP_WAIT0();
        __syncthreads();
        if (i + 1 < KC) { issue_chunk(i + 1); CP_COMMIT(); }

        const uint32_t st = sb + (uint32_t)(i & 1) * 24576u;
        const uint32_t aH = st, bH = st + 16384u;
#pragma unroll
        for (int ks = 0; ks < 4; ks++) {
            uint32_t ah[2][4], bh[2][4];
#pragma unroll
            for (int mi = 0; mi < 2; mi++)
                ldsmA(aH, wr * 32 + mi * 16, ks, lane, ah[mi]);
#pragma unroll
            for (int np = 0; np < 2; np++)
                ldsmB(bH, wc * 32 + np * 16, ks, lane, bh[np]);
#pragma unroll
            for (int mi = 0; mi < 2; mi++)
#pragma unroll
                for (int ni = 0; ni < 4; ni++) {
                    const int np = ni >> 1, o = (ni & 1) << 1;
                    MMAH16816(acc[mi][ni], ah[mi], bh[np][o], bh[np][o + 1]);
                }
        }
        __syncthreads();
    }

#pragma unroll
    for (int mi = 0; mi < 2; mi++) {
        const int row = rowbase + wr * 32 + mi * 16 + (lane >> 2);
#pragma unroll
        for (int ni = 0; ni < 4; ni++) {
            const int col = colbase + wc * 32 + ni * 8 + (lane & 3) * 2;
            if (col < N) {
                *reinterpret_cast<float2*>(&C[(size_t)row * ldc + col]) =
                    make_float2(acc[mi][ni][0], acc[mi][ni][1]);
                *reinterpret_cast<float2*>(&C[(size_t)(row + 8) * ldc + col]) =
                    make_float2(acc[mi][ni][2], acc[mi][ni][3]);
            }
        }
    }
}

// ---------------- GEMM2: fp16 2-product (A hi/lo, B single) ----------------
__global__ __launch_bounds__(256, 2) void hgemm_kernel(
    const __half* __restrict__ Ah, const __half* __restrict__ Al,
    const __half* __restrict__ Bh, float* __restrict__ C, int N, int K, int ldc)
{
    extern __shared__ char smem[];
    const uint32_t sb = smem_u32(smem);
    const int tid = threadIdx.x, wid = tid >> 5, lane = tid & 31;
    const int wr = wid & 3, wc = wid >> 2;
    const int rowbase = blockIdx.y * 128, colbase = blockIdx.x * 64;
    const int KC = K >> 6;

    float acc[2][4][4];
#pragma unroll
    for (int mi = 0; mi < 2; mi++)
#pragma unroll
        for (int ni = 0; ni < 4; ni++)
#pragma unroll
            for (int j = 0; j < 4; j++) acc[mi][ni][j] = 0.f;

    auto issue_chunk = [&](int i) {
        const uint32_t st = (uint32_t)(i & 1) * 40960u;
        const int k0 = i << 6;
#pragma unroll
        for (int v = 0; v < 10; v++) {
            const int idx = v * 256 + tid;
            const __half* src;
            uint32_t dst;
            if (idx < 2048) {
                const int buf = idx >> 10;
                const int r = (idx & 1023) >> 3, c8 = idx & 7;
                src = (buf ? Al : Ah) + (size_t)(rowbase + r) * K + k0 + c8 * 8;
                dst = sb + st + (uint32_t)buf * 16384u +
                      SMEM_SWIZZLE_128B((uint32_t)(r * 128 + c8 * 16));
            } else {
                const int j = idx - 2048;
                const int r = j >> 3, c8 = j & 7;
                src = Bh + (size_t)(colbase + r) * K + k0 + c8 * 8;
                dst = sb + st + 32768u + SMEM_SWIZZLE_128B((uint32_t)(r * 128 + c8 * 16));
            }
            CP_ASYNC16(dst, src);
        }
    };

    issue_chunk(0);
    CP_COMMIT();

    for (int i = 0; i < KC; i++) {
        CP_WAIT0();
        __syncthreads();
        if (i + 1 < KC) { issue_chunk(i + 1); CP_COMMIT(); }

        const uint32_t st = sb + (uint32_t)(i & 1) * 40960u;
        const uint32_t aH = st, aL = st + 16384u, bH = st + 32768u;
#pragma unroll
        for (int ks = 0; ks < 4; ks++) {
            uint32_t ah[2][4], al[2][4], bh[2][4];
#pragma unroll
            for (int mi = 0; mi < 2; mi++) {
                ldsmA(aH, wr * 32 + mi * 16, ks, lane, ah[mi]);
                ldsmA(aL, wr * 32 + mi * 16, ks, lane, al[mi]);
            }
#pragma unroll
            for (int np = 0; np < 2; np++)
                ldsmB(bH, wc * 32 + np * 16, ks, lane, bh[np]);
#pragma unroll
            for (int mi = 0; mi < 2; mi++)
#pragma unroll
                for (int ni = 0; ni < 4; ni++) {
                    const int np = ni >> 1, o = (ni & 1) << 1;
                    MMAH16816(acc[mi][ni], ah[mi], bh[np][o], bh[np][o + 1]);
                    MMAH16816(acc[mi][ni], al[mi], bh[np][o], bh[np][o + 1]);
                }
        }
        __syncthreads();
    }

#pragma unroll
    for (int mi = 0; mi < 2; mi++) {
        const int row = rowbase + wr * 32 + mi * 16 + (lane >> 2);
#pragma unroll
        for (int ni = 0; ni < 4; ni++) {
            const int col = colbase + wc * 32 + ni * 8 + (lane & 3) * 2;
            if (col < N) {
                *reinterpret_cast<float2*>(&C[(size_t)row * ldc + col]) =
                    make_float2(acc[mi][ni][0], acc[mi][ni][1]);
                *reinterpret_cast<float2*>(&C[(size_t)(row + 8) * ldc + col]) =
                    make_float2(acc[mi][ni][2], acc[mi][ni][3]);
            }
        }
    }
}

// ---------------- exact fp32 dt ----------------
__global__ __launch_bounds__(256) void dt_exact_kernel(const float* __restrict__ u,
                                                       const float* __restrict__ W_in,
                                                       const float* __restrict__ dt_bias) {
    __shared__ float us[16 * 256];
    __shared__ float ws[256 * 32];
    const int m0 = blockIdx.x * 16;
    const int t = threadIdx.x;
    const int mloc = t >> 4, h0 = t & 15, h1 = 16 + (t & 15);
    float acc0 = 0.f, acc1 = 0.f;
    for (int kc = 0; kc < 4; kc++) {
        __syncthreads();
        for (int i = t; i < 4096; i += 256) {
            int mm = i >> 8, kk = i & 255;
            us[i] = u[(size_t)(m0 + mm) * DMODEL + kc * 256 + kk];
        }
        for (int i = t; i < 8192; i += 256) {
            int kk = i >> 5, hh = i & 31;
            ws[i] = W_in[(size_t)(kc * 256 + kk) * DPROJ + (DPROJ - NH) + hh];
        }
        __syncthreads();
#pragma unroll 8
        for (int kk = 0; kk < 256; kk++) {
            float uv = us[mloc * 256 + kk];
            acc0 = fmaf(uv, ws[kk * 32 + h0], acc0);
            acc1 = fmaf(uv, ws[kk * 32 + h1], acc1);
        }
    }
    float x0 = acc0 + dt_bias[h0];
    float x1 = acc1 + dt_bias[h1];
    g_dt[(m0 + mloc) * NH + h0] = (x0 > 20.f) ? x0 : log1pf(expf(x0));
    g_dt[(m0 + mloc) * NH + h1] = (x1 > 20.f) ? x1 : log1pf(expf(x1));
}

// ---------------- prep A: u -> fp16 (single) ----------------
__global__ __launch_bounds__(1024) void prep_cvt_kernel(const float* __restrict__ u,
                                                        __half* __restrict__ a1h) {
    int i = blockIdx.x * 1024 + threadIdx.x;
    float4 x = reinterpret_cast<const float4*>(u)[i];
    reinterpret_cast<__half2*>(a1h)[2 * i]     = __half2(__float2half(x.x), __float2half(x.y));
    reinterpret_cast<__half2*>(a1h)[2 * i + 1] = __half2(__float2half(x.z), __float2half(x.w));
}

// ---------------- prep W: transpose W_in and W_out to fp16 [N][K] ----------------
__global__ __launch_bounds__(1024) void prep_w_kernel(const float* __restrict__ W_in,
                                                      const float* __restrict__ W_out,
                                                      __half* __restrict__ b1h,
                                                      __half* __restrict__ b2h) {
    __shared__ float t[32][33];
    const int bx = blockIdx.x, tid = threadIdx.x;
    const int tx = tid & 31, ty = tid >> 5;
    if (bx < 4352) {
        int bxx = bx % 136, byy = bx / 136;
        int n = bxx * 32 + tx, k = byy * 32 + ty;
        t[ty][tx] = W_in[(size_t)k * DPROJ + n];
        __syncthreads();
        int nn = bxx * 32 + ty, kk = byy * 32 + tx;
        b1h[(size_t)nn * DMODEL + kk] = __float2half(t[tx][ty]);
    } else {
        int bb = bx - 4352;
        int bxx = bb % 32, byy = bb / 32;
        int n = bxx * 32 + tx, k = byy * 32 + ty;
        t[ty][tx] = W_out[(size_t)k * DMODEL + n];
        __syncthreads();
        int nn = bxx * 32 + ty, kk = byy * 32 + tx;
        b2h[(size_t)nn * DINNER + kk] = __float2half(t[tx][ty]);
    }
}

// ---------------- depthwise causal conv(4) + bias + SiLU (32 rows/block) ----------------
__global__ __launch_bounds__(256) void conv_kernel(const float* __restrict__ cw,
                                                   const float* __restrict__ cb) {
    __shared__ float s[35][256];
    int tid = threadIdx.x;
    int ch = blockIdx.x * 256 + tid;
    int m0 = blockIdx.y * 32;
    int l0 = m0 & (LSEQ - 1);
#pragma unroll
    for (int r = 0; r < 35; r++) {
        int l = l0 - 3 + r;
        s[r][tid] = (l >= 0) ? g_zx[(size_t)(m0 - 3 + r) * DPROJ + DINNER + ch] : 0.f;
    }
    __syncthreads();
    float w0 = cw[ch * 4], w1 = cw[ch * 4 + 1], w2 = cw[ch * 4 + 2], w3 = cw[ch * 4 + 3];
    float bias = cb[ch];
#pragma unroll
    for (int r = 0; r < 32; r++) {
        float acc = bias;
        acc = fmaf(s[r][tid], w0, acc);
        acc = fmaf(s[r + 1][tid], w1, acc);
        acc = fmaf(s[r + 2][tid], w2, acc);
        acc = fmaf(s[r + 3][tid], w3, acc);
        g_xbc[(size_t)(m0 + r) * CONVCH + ch] = acc / (1.f + expf(-acc));
    }
}

#define TS_STR 66
#define CS_STR 132
#define XS_STR 68

// ---------------- CB^T = C·B^T per (b,c), shared across heads ----------------
__global__ __launch_bounds__(256, 2) void cb_kernel() {
    int blk = blockIdx.x;
    int bc = blk >> 1, half = blk & 1;
    int m0 = (bc >> 6) * LSEQ + (bc & 63) * CHK;
    extern __shared__ float sm[];
    float* Bst = sm;
    float* Cs  = Bst + 128 * TS_STR;
    int tid = threadIdx.x;
    for (int i = tid; i < 64 * 128; i += 256) {
        int l = i >> 7, n = i & 127;
        Bst[n * TS_STR + l] = g_xbc[(size_t)(m0 + l) * CONVCH + DINNER + n];
    }
    for (int i = tid; i < 32 * 32; i += 256) {
        int ll = i >> 5, q = i & 31;
        float4 v = *reinterpret_cast<const float4*>(
            g_xbc + (size_t)(m0 + half * 32 + ll) * CONVCH + DINNER + DSTATE + 4 * q);
        *reinterpret_cast<float4*>(Cs + ll * CS_STR + 4 * q) = v;
    }
    __syncthreads();
    const int rg = tid >> 5, cg = tid & 31;
    const int r0 = rg * 4, c0 = cg * 2;
    float* out = g_cb + (size_t)bc * 4096 + (size_t)(half * 32) * 64;
    if (c0 > half * 32 + r0 + 3) {
#pragma unroll
        for (int i = 0; i < 4; i++)
            *reinterpret_cast<float2*>(out + (r0 + i) * 64 + c0) = make_float2(0.f, 0.f);
        return;
    }
    uint64_t acc2[4] = {0ull, 0ull, 0ull, 0ull};
    for (int n4 = 0; n4 < 128; n4 += 4) {
        float4 cr[4];
#pragma unroll
        for (int i = 0; i < 4; i++)
            cr[i] = *reinterpret_cast<const float4*>(Cs + (r0 + i) * CS_STR + n4);
#pragma unroll
        for (int nn = 0; nn < 4; nn++) {
            uint64_t b2 = *reinterpret_cast<const uint64_t*>(Bst + (n4 + nn) * TS_STR + c0);
#pragma unroll
            for (int i = 0; i < 4; i++) {
                uint64_t a2 = dup2((&cr[i].x)[nn]);
                FMA2(acc2[i], a2, b2);
            }
        }
    }
#pragma unroll
    for (int i = 0; i < 4; i++) {
        float v0, v1;
        up2(acc2[i], v0, v1);
        *reinterpret_cast<float2*>(out + (r0 + i) * 64 + c0) = make_float2(v0, v1);
    }
}

// ---------------- SSD intra-chunk ----------------
__global__ __launch_bounds__(256, 3) void ssd_diag_kernel(const float* __restrict__ A_log) {
    int blk = blockIdx.x;
    int h = blk & 31;
    int c = (blk >> 5) & 63;
    int b = blk >> 11;
    int m0 = b * LSEQ + c * CHK;

    extern __shared__ float sm[];
    float* Bst = sm;
    float* xs  = Bst + 128 * TS_STR;
    float* Gs  = xs + 64 * XS_STR;
    float* ac  = Gs + 64 * XS_STR;
    float* wd  = ac + 64;
    float* dts = wd + 64;
    int tid = threadIdx.x;

    if (tid < 32) {
        float A = -expf(A_log[h]);
        float dt0 = g_dt[(m0 + 2 * tid) * NH + h];
        float dt1 = g_dt[(m0 + 2 * tid + 1) * NH + h];
        dts[2 * tid] = dt0;
        dts[2 * tid + 1] = dt1;
        float e0 = A * dt0, e1 = A * dt1;
        float run = e0 + e1;
#pragma unroll
        for (int off = 1; off < 32; off <<= 1) {
            float v = __shfl_up_sync(0xFFFFFFFFu, run, off);
            if (tid >= off) run += v;
        }
        ac[2 * tid]     = run - e1;
        ac[2 * tid + 1] = run;
    }
    __syncthreads();
    if (tid < 64) {
        wd[tid] = expf(ac[63] - ac[tid]);
        g_acum[blk * CHK + tid] = ac[tid];
    }
    if (tid == 0) g_suma[blk] = expf(ac[63]);

    for (int i = tid; i < 64 * 128; i += 256) {
        int l = i >> 7, n = i & 127;
        Bst[n * TS_STR + l] = g_xbc[(size_t)(m0 + l) * CONVCH + DINNER + n];
    }
    for (int i = tid; i < 64 * 16; i += 256) {
        int l = i >> 4, q = i & 15;
        float dtv = dts[l];
        float4 v = *reinterpret_cast<const float4*>(
            g_xbc + (size_t)(m0 + l) * CONVCH + h * HD + 4 * q);
        v.x *= dtv; v.y *= dtv; v.z *= dtv; v.w *= dtv;
        *reinterpret_cast<float4*>(xs + l * XS_STR + 4 * q) = v;
    }
    {
        const float* cb = g_cb + (size_t)(b * NC + c) * 4096;
        for (int i = tid; i < 4096; i += 256) {
            int l = i >> 6, s = i & 63;
            float v = cb[i];
            Gs[l * XS_STR + s] = (s <= l) ? v * expf(ac[l] - ac[s]) : 0.f;
        }
    }
    __syncthreads();

    const int tr = tid >> 4, tc = tid & 15;
    const int r0 = tr * 4, c0 = tc * 4;

    {
        uint64_t acc2[4][2] = {{0ull,0ull},{0ull,0ull},{0ull,0ull},{0ull,0ull}};
        for (int s4 = 0; s4 < r0 + 4; s4 += 4) {
            float4 gr[4];
#pragma unroll
            for (int i = 0; i < 4; i++)
                gr[i] = *reinterpret_cast<const float4*>(Gs + (r0 + i) * XS_STR + s4);
#pragma unroll
            for (int ss = 0; ss < 4; ss++) {
                uint64_t x0 = *reinterpret_cast<const uint64_t*>(xs + (s4 + ss) * XS_STR + c0);
                uint64_t x1 = *reinterpret_cast<const uint64_t*>(xs + (s4 + ss) * XS_STR + c0 + 2);
#pragma unroll
                for (int i = 0; i < 4; i++) {
                    uint64_t a2 = dup2((&gr[i].x)[ss]);
                    FMA2(acc2[i][0], a2, x0);
                    FMA2(acc2[i][1], a2, x1);
                }
            }
        }
#pragma unroll
        for (int i = 0; i < 4; i++) {
            float v0, v1, v2, v3;
            up2(acc2[i][0], v0, v1);
            up2(acc2[i][1], v2, v3);
            *reinterpret_cast<float4*>(g_y + (size_t)(m0 + r0 + i) * DINNER + h * HD + c0) =
                make_float4(v0, v1, v2, v3);
        }
    }

    {
        const int p0 = (tid & 15) * 4, n0 = (tid >> 4) * 8;
        uint64_t acc2[2][8];
#pragma unroll
        for (int pp = 0; pp < 2; pp++)
#pragma unroll
            for (int j = 0; j < 8; j++) acc2[pp][j] = 0ull;
        for (int l = 0; l < 64; l++) {
            uint64_t w2 = dup2(wd[l]);
            uint64_t xa = *reinterpret_cast<const uint64_t*>(xs + l * XS_STR + p0);
            uint64_t xb = *reinterpret_cast<const uint64_t*>(xs + l * XS_STR + p0 + 2);
            uint64_t wxa, wxb;
            MUL2(wxa, xa, w2);
            MUL2(wxb, xb, w2);
#pragma unroll
            for (int j = 0; j < 8; j++) {
                uint64_t b2 = dup2(Bst[(n0 + j) * TS_STR + l]);
                FMA2(acc2[0][j], wxa, b2);
                FMA2(acc2[1][j], wxb, b2);
            }
        }
        float rowv[4][8];
#pragma unroll
        for (int pp = 0; pp < 2; pp++)
#pragma unroll
            for (int j = 0; j < 8; j++)
                up2(acc2[pp][j], rowv[2 * pp][j], rowv[2 * pp + 1][j]);
#pragma unroll
        for (int i = 0; i < 4; i++) {
            float* dst = g_states + ((size_t)blk * HD + p0 + i) * DSTATE + n0;
            *reinterpret_cast<float4*>(dst)     = make_float4(rowv[i][0], rowv[i][1], rowv[i][2], rowv[i][3]);
            *reinterpret_cast<float4*>(dst + 4) = make_float4(rowv[i][4], rowv[i][5], rowv[i][6], rowv[i][7]);
        }
    }
}

// ---------------- inter-chunk scan (float2 + prefetch) ----------------
__global__ void scan_kernel() {
    int idx = blockIdx.x * blockDim.x + threadIdx.x;
    int n2 = idx & 63;
    int p = (idx >> 6) & 63;
    int h = (idx >> 12) & 31;
    int b = idx >> 17;
    const size_t cstep = (size_t)NH * HD * DSTATE;
    int bch0 = b * NC * NH + h;
    size_t off = ((size_t)bch0 * HD + p) * DSTATE + 2 * n2;
    float2 prev = make_float2(0.f, 0.f);
    float2 loc = *reinterpret_cast<float2*>(g_states + off);
    for (int c = 0; c < NC; c++) {
        float2 nxt = (c + 1 < NC) ? *reinterpret_cast<float2*>(g_states + off + cstep)
                                  : make_float2(0.f, 0.f);
        float e = g_suma[bch0 + c * NH];
        *reinterpret_cast<float2*>(g_states + off) = prev;
        prev.x = fmaf(prev.x, e, loc.x);
        prev.y = fmaf(prev.y, e, loc.y);
        loc = nxt;
        off += cstep;
    }
}

// ---------------- Y_off + skip (f32x2, half-C double pass, 3 CTAs/SM) ----------------
#define CS2_STR 68
__global__ __launch_bounds__(256, 3) void yoff_kernel(const float* __restrict__ Dv) {
    int blk = blockIdx.x;
    int h = blk & 31;
    int c = (blk >> 5) & 63;
    int b = blk >> 11;
    int m0 = b * LSEQ + c * CHK;

    extern __shared__ float sm[];
    float* Pst = sm;
    float* Cs2 = Pst + 128 * TS_STR;
    float* ac  = Cs2 + 64 * CS2_STR;
    int tid = threadIdx.x;

    for (int i = tid; i < 64 * 128; i += 256) {
        int p = i >> 7, n = i & 127;
        Pst[n * TS_STR + p] = g_states[((size_t)blk * HD + p) * DSTATE + n];
    }
    if (tid < 64) ac[tid] = g_acum[blk * CHK + tid];
    float Dh = Dv[h];

    const int tr = tid >> 4, tc = tid & 15;
    const int r0 = tr * 4, c0 = tc * 4;
    uint64_t acc2[4][2] = {{0ull,0ull},{0ull,0ull},{0ull,0ull},{0ull,0ull}};

#pragma unroll
    for (int half = 0; half < 2; half++) {
        __syncthreads();
        for (int i = tid; i < 64 * 16; i += 256) {
            int l = i >> 4, q = i & 15;
            float4 v = *reinterpret_cast<const float4*>(
                g_xbc + (size_t)(m0 + l) * CONVCH + DINNER + DSTATE + half * 64 + 4 * q);
            *reinterpret_cast<float4*>(Cs2 + l * CS2_STR + 4 * q) = v;
        }
        __syncthreads();
        for (int n4 = 0; n4 < 64; n4 += 4) {
            float4 cr[4];
#pragma unroll
            for (int i = 0; i < 4; i++)
                cr[i] = *reinterpret_cast<const float4*>(Cs2 + (r0 + i) * CS2_STR + n4);
#pragma unroll
            for (int nn = 0; nn < 4; nn++) {
                int n = half * 64 + n4 + nn;
                uint64_t p0v = *reinterpret_cast<const uint64_t*>(Pst + n * TS_STR + c0);
                uint64_t p1v = *reinterpret_cast<const uint64_t*>(Pst + n * TS_STR + c0 + 2);
#pragma unroll
                for (int i = 0; i < 4; i++) {
                    uint64_t a2 = dup2((&cr[i].x)[nn]);
                    FMA2(acc2[i][0], a2, p0v);
                    FMA2(acc2[i][1], a2, p1v);
                }
            }
        }
    }

#pragma unroll
    for (int i = 0; i < 4; i++) {
        int l = r0 + i;
        int row = m0 + l;
        float el = expf(ac[l]);
        float v0, v1, v2, v3;
        up2(acc2[i][0], v0, v1);
        up2(acc2[i][1], v2, v3);
        float4 xv = *reinterpret_cast<const float4*>(
            g_xbc + (size_t)row * CONVCH + h * HD + c0);
        float4* yp = reinterpret_cast<float4*>(g_y + (size_t)row * DINNER + h * HD + c0);
        float4 yv = *yp;
        yv.x += v0 * el + xv.x * Dh;
        yv.y += v1 * el + xv.y * Dh;
        yv.z += v2 * el + xv.z * Dh;
        yv.w += v3 * el + xv.w * Dh;
        *yp = yv;
    }
}

// ---------------- gate (silu(z)) + RMSNorm, shuffle reduction, fp16 split out ----------
__global__ void gate_kernel(const float* __restrict__ norm_w,
                            __half* __restrict__ a2h, __half* __restrict__ a2l) {
    int m = blockIdx.x;
    int tid = threadIdx.x;
    __shared__ float wsum[8];
    float tv[8];
    float ss = 0.f;
#pragma unroll
    for (int j = 0; j < 8; j++) {
        int i = tid + 256 * j;
        float zv = g_zx[(size_t)m * DPROJ + i];
        float yv = g_y[(size_t)m * DINNER + i];
        float g = yv * (zv / (1.f + expf(-zv)));
        tv[j] = g;
        ss += g * g;
    }
#pragma unroll
    for (int o = 16; o; o >>= 1) ss += __shfl_xor_sync(0xFFFFFFFFu, ss, o);
    if ((tid & 31) == 0) wsum[tid >> 5] = ss;
    __syncthreads();
    float tot = wsum[0] + wsum[1] + wsum[2] + wsum[3] +
                wsum[4] + wsum[5] + wsum[6] + wsum[7];
    float scale = rsqrtf(tot / (float)DINNER + 1e-5f);
#pragma unroll
    for (int j = 0; j < 8; j++) {
        int i = tid + 256 * j;
        float val = tv[j] * scale * norm_w[i];
        __half hv = __float2half(val);
        a2h[(size_t)m * DINNER + i] = hv;
        a2l[(size_t)m * DINNER + i] = __float2half(val - __half2float(hv));
    }
}

// ---------------- launch ----------------
extern "C" void kernel_launch(void* const* d_in, const int* in_sizes, int n_in,
                              void* d_out, int out_size) {
    const float* u      = (const float*)d_in[0];
    const float* W_in   = (const float*)d_in[1];
    const float* conv_w = (const float*)d_in[2];
    const float* conv_b = (const float*)d_in[3];
    const float* dt_b   = (const float*)d_in[4];
    const float* A_log  = (const float*)d_in[5];
    const float* Dv     = (const float*)d_in[6];
    const float* norm_w = (const float*)d_in[7];
    const float* W_out  = (const float*)d_in[8];
    float* out = (float*)d_out;

    float* zx = nullptr;
    cudaGetSymbolAddress((void**)&zx, g_zx);
    __half *a1h, *b1h, *a2h, *a2l, *b2h;
    cudaGetSymbolAddress((void**)&a1h, g_a1h);
    cudaGetSymbolAddress((void**)&b1h, g_b1h);
    cudaGetSymbolAddress((void**)&a2h, g_a2h);
    cudaGetSymbolAddress((void**)&a2l, g_a2l);
    cudaGetSymbolAddress((void**)&b2h, g_b2h);

    const size_t gemm1_smem = 2 * 24576;  // 49152
    const size_t gemm2_smem = 2 * 40960;  // 81920
    const size_t cb_smem   = (size_t)(128 * TS_STR + 32 * CS_STR) * sizeof(float);
    const size_t diag_smem = (size_t)(128 * TS_STR + 2 * 64 * XS_STR + 192) * sizeof(float);
    const size_t yoff_smem = (size_t)(128 * TS_STR + 64 * CS2_STR + 64) * sizeof(float);
    cudaFuncSetAttribute(hgemm1_kernel, cudaFuncAttributeMaxDynamicSharedMemorySize, (int)gemm1_smem);
    cudaFuncSetAttribute(hgemm_kernel, cudaFuncAttributeMaxDynamicSharedMemorySize, (int)gemm2_smem);
    cudaFuncSetAttribute(cb_kernel, cudaFuncAttributeMaxDynamicSharedMemorySize, (int)cb_smem);
    cudaFuncSetAttribute(ssd_diag_kernel, cudaFuncAttributeMaxDynamicSharedMemorySize, (int)diag_smem);
    cudaFuncSetAttribute(yoff_kernel, cudaFuncAttributeMaxDynamicSharedMemorySize, (int)yoff_smem);

    // 0: exact fp32 dt
    dt_exact_kernel<<<MROWS / 16, 256>>>(u, W_in, dt_b);

    // 1: prep A (u -> fp16)
    prep_cvt_kernel<<<MROWS * DMODEL / 4096, 1024>>>(u, a1h);

    // 2: prep W
    prep_w_kernel<<<4352 + 2048, 1024>>>(W_in, W_out, b1h, b2h);

    // 3: GEMM1 (profiled): zx[:, :4352] = u @ W_in (fp16 single product)
    hgemm1_kernel<<<dim3(NGEMM1 / 64, MROWS / 128), 256, gemm1_smem>>>(
        a1h, b1h, zx, NGEMM1, DMODEL, DPROJ);

    // 4: conv
    conv_kernel<<<dim3(CONVCH / 256, MROWS / 32), 256>>>(conv_w, conv_b);

    // 5: CB^T shared across heads
    cb_kernel<<<BQ * NC * 2, 256, cb_smem>>>();

    // 6: SSD intra-chunk
    ssd_diag_kernel<<<BQ * NC * NH, 256, diag_smem>>>(A_log);

    // 7: inter-chunk scan
    scan_kernel<<<(BQ * NH * HD * DSTATE / 2) / 256, 256>>>();

    // 8: Y_off + skip
    yoff_kernel<<<BQ * NC * NH, 256, yoff_smem>>>(Dv);

    // 9: gate + rmsnorm (writes fp16 split A for GEMM2)
    gate_kernel<<<MROWS, 256>>>(norm_w, a2h, a2l);

    // 10: GEMM2: out = y @ W_out (fp16 2-product)
    hgemm_kernel<<<dim3(DMODEL / 64, MROWS / 128), 256, gemm2_smem>>>(
        a2h, a2l, b2h, out, DMODEL, DINNER, DMODEL);
}

// round 16
// speedup vs baseline: 2.8482x; 1.0620x over previous
#include <cuda_runtime.h>
#include <cuda_bf16.h>
#include <cuda_fp16.h>
#include <math.h>
#include <cstdint>

// ---------------- problem constants ----------------
#define BQ 2
#define LSEQ 4096
#define DMODEL 1024
#define DINNER 2048
#define NH 32
#define HD 64
#define DSTATE 128
#define CHK 64
#define NC 64
#define DPROJ 4384
#define CONVCH 2304
#define MROWS (BQ*LSEQ)
#define NPAD1 4480
#define NGEMM1 4352     // z (2048) + xBC (2304); dt cols handled exactly elsewhere

// ---------------- scratch (device globals; no allocation) ----------------
__device__ float g_zx[(size_t)MROWS * DPROJ];
__device__ float g_xbc[(size_t)MROWS * CONVCH];
__device__ float g_dt[MROWS * NH];
__device__ float g_acum[BQ * NC * NH * CHK];
__device__ float g_suma[BQ * NC * NH];
__device__ float g_states[(size_t)BQ * NC * NH * HD * DSTATE];
__device__ float g_y[(size_t)MROWS * DINNER];
__device__ float g_cb[(size_t)BQ * NC * CHK * CHK];   // CB^T shared across heads (2MB)

// GEMM operands (fp16, single product both GEMMs)
__device__ __half g_a1h[(size_t)MROWS * DMODEL];
__device__ __half g_b1h[(size_t)NPAD1 * DMODEL];
__device__ __half g_a2h[(size_t)MROWS * DINNER];
__device__ __half g_b2h[(size_t)DMODEL * DINNER];

// ---------------- PTX helpers ----------------
__device__ __forceinline__ uint32_t smem_u32(const void* p) {
    uint32_t a;
    asm("{ .reg .u64 t; cvta.to.shared.u64 t, %1; cvt.u32.u64 %0, t; }" : "=r"(a) : "l"(p));
    return a;
}
#define SMEM_SWIZZLE_128B(byte_offset) ((byte_offset) ^ (((byte_offset) >> 3) & 0x70))
#define CP_ASYNC16(dst, src) \
    asm volatile("cp.async.cg.shared.global [%0], [%1], 16;" :: "r"(dst), "l"(src) : "memory")
#define CP_COMMIT() asm volatile("cp.async.commit_group;" ::: "memory")
#define CP_WAIT0()  asm volatile("cp.async.wait_group 0;" ::: "memory")
#define CP_WAIT1()  asm volatile("cp.async.wait_group 1;" ::: "memory")

#define LDSM_X4(r0,r1,r2,r3,addr) \
    asm volatile("ldmatrix.sync.aligned.m8n8.x4.shared.b16 {%0,%1,%2,%3}, [%4];" \
        : "=r"(r0), "=r"(r1), "=r"(r2), "=r"(r3) : "r"(addr))

#define MMAH16816(d, a, b0, b1) \
    asm volatile("mma.sync.aligned.m16n8k16.row.col.f32.f16.f16.f32 " \
        "{%0,%1,%2,%3}, {%4,%5,%6,%7}, {%8,%9}, {%0,%1,%2,%3};" \
        : "+f"((d)[0]), "+f"((d)[1]), "+f"((d)[2]), "+f"((d)[3]) \
        : "r"((a)[0]), "r"((a)[1]), "r"((a)[2]), "r"((a)[3]), "r"(b0), "r"(b1))

// packed f32x2 (2x fp32 FMA rate)
#define FMA2(d, a, b) asm("fma.rn.f32x2 %0, %1, %2, %0;" : "+l"(d) : "l"(a), "l"(b))
#define MUL2(d, a, b) asm("mul.rn.f32x2 %0, %1, %2;" : "=l"(d) : "l"(a), "l"(b))
__device__ __forceinline__ uint64_t dup2(float x) {
    uint64_t r; asm("mov.b64 %0, {%1, %1};" : "=l"(r) : "f"(x)); return r;
}
__device__ __forceinline__ void up2(uint64_t v, float& lo, float& hi) {
    asm("mov.b64 {%0, %1}, %2;" : "=f"(lo), "=f"(hi) : "l"(v));
}

__device__ __forceinline__ void ldsmA(uint32_t base, int row, int ks, int lane, uint32_t* r) {
    int rr = row + (lane & 15);
    int off = rr * 128 + ks * 32 + ((lane >> 4) << 4);
    LDSM_X4(r[0], r[1], r[2], r[3], base + SMEM_SWIZZLE_128B((uint32_t)off));
}
__device__ __forceinline__ void ldsmB(uint32_t base, int nrow, int ks, int lane, uint32_t* r) {
    int n = nrow + ((lane >> 4) << 3) + (lane & 7);
    int off = n * 128 + ks * 32 + (((lane >> 3) & 1) << 4);
    LDSM_X4(r[0], r[1], r[2], r[3], base + SMEM_SWIZZLE_128B((uint32_t)off));
}

// ---------------- single-product fp16 GEMM, 3-stage cp.async ring ----------------
// stage: A 16K + B 8K = 24K; 3 stages = 72K, 2 CTAs/SM.
__global__ __launch_bounds__(256, 2) void hgemm1_kernel(
    const __half* __restrict__ Ah, const __half* __restrict__ Bh,
    float* __restrict__ C, int N, int K, int ldc)
{
    extern __shared__ char smem[];
    const uint32_t sb = smem_u32(smem);
    const int tid = threadIdx.x, wid = tid >> 5, lane = tid & 31;
    const int wr = wid & 3, wc = wid >> 2;
    const int rowbase = blockIdx.y * 128, colbase = blockIdx.x * 64;
    const int KC = K >> 6;

    float acc[2][4][4];
#pragma unroll
    for (int mi = 0; mi < 2; mi++)
#pragma unroll
        for (int ni = 0; ni < 4; ni++)
#pragma unroll
            for (int j = 0; j < 4; j++) acc[mi][ni][j] = 0.f;

    auto issue_chunk = [&](int i) {
        const uint32_t st = (uint32_t)(i % 3) * 24576u;
        const int k0 = i << 6;
#pragma unroll
        for (int v = 0; v < 6; v++) {
            const int idx = v * 256 + tid;
            const __half* src;
            uint32_t dst;
            if (idx < 1024) {
                const int r = idx >> 3, c8 = idx & 7;
                src = Ah + (size_t)(rowbase + r) * K + k0 + c8 * 8;
                dst = sb + st + SMEM_SWIZZLE_128B((uint32_t)(r * 128 + c8 * 16));
            } else {
                const int j = idx - 1024;
                const int r = j >> 3, c8 = j & 7;
                src = Bh + (size_t)(colbase + r) * K + k0 + c8 * 8;
                dst = sb + st + 16384u + SMEM_SWIZZLE_128B((uint32_t)(r * 128 + c8 * 16));
            }
            CP_ASYNC16(dst, src);
        }
    };

    issue_chunk(0); CP_COMMIT();
    issue_chunk(1); CP_COMMIT();

    for (int i = 0; i < KC; i++) {
        if (i == KC - 1) { CP_WAIT0(); } else { CP_WAIT1(); }
        __syncthreads();
        if (i + 2 < KC) { issue_chunk(i + 2); CP_COMMIT(); }

        const uint32_t st = sb + (uint32_t)(i % 3) * 24576u;
        const uint32_t aH = st, bH = st + 16384u;
#pragma unroll
        for (int ks = 0; ks < 4; ks++) {
            uint32_t ah[2][4], bh[2][4];
#pragma unroll
            for (int mi = 0; mi < 2; mi++)
                ldsmA(aH, wr * 32 + mi * 16, ks, lane, ah[mi]);
#pragma unroll
            for (int np = 0; np < 2; np++)
                ldsmB(bH, wc * 32 + np * 16, ks, lane, bh[np]);
#pragma unroll
            for (int mi = 0; mi < 2; mi++)
#pragma unroll
                for (int ni = 0; ni < 4; ni++) {
                    const int np = ni >> 1, o = (ni & 1) << 1;
                    MMAH16816(acc[mi][ni], ah[mi], bh[np][o], bh[np][o + 1]);
                }
        }
        __syncthreads();
    }

#pragma unroll
    for (int mi = 0; mi < 2; mi++) {
        const int row = rowbase + wr * 32 + mi * 16 + (lane >> 2);
#pragma unroll
        for (int ni = 0; ni < 4; ni++) {
            const int col = colbase + wc * 32 + ni * 8 + (lane & 3) * 2;
            if (col < N) {
                *reinterpret_cast<float2*>(&C[(size_t)row * ldc + col]) =
                    make_float2(acc[mi][ni][0], acc[mi][ni][1]);
                *reinterpret_cast<float2*>(&C[(size_t)(row + 8) * ldc + col]) =
                    make_float2(acc[mi][ni][2], acc[mi][ni][3]);
            }
        }
    }
}

// ---------------- exact fp32 dt ----------------
__global__ __launch_bounds__(256) void dt_exact_kernel(const float* __restrict__ u,
                                                       const float* __restrict__ W_in,
                                                       const float* __restrict__ dt_bias) {
    __shared__ float us[16 * 256];
    __shared__ float ws[256 * 32];
    const int m0 = blockIdx.x * 16;
    const int t = threadIdx.x;
    const int mloc = t >> 4, h0 = t & 15, h1 = 16 + (t & 15);
    float acc0 = 0.f, acc1 = 0.f;
    for (int kc = 0; kc < 4; kc++) {
        __syncthreads();
        for (int i = t; i < 4096; i += 256) {
            int mm = i >> 8, kk = i & 255;
            us[i] = u[(size_t)(m0 + mm) * DMODEL + kc * 256 + kk];
        }
        for (int i = t; i < 8192; i += 256) {
            int kk = i >> 5, hh = i & 31;
            ws[i] = W_in[(size_t)(kc * 256 + kk) * DPROJ + (DPROJ - NH) + hh];
        }
        __syncthreads();
#pragma unroll 8
        for (int kk = 0; kk < 256; kk++) {
            float uv = us[mloc * 256 + kk];
            acc0 = fmaf(uv, ws[kk * 32 + h0], acc0);
            acc1 = fmaf(uv, ws[kk * 32 + h1], acc1);
        }
    }
    float x0 = acc0 + dt_bias[h0];
    float x1 = acc1 + dt_bias[h1];
    g_dt[(m0 + mloc) * NH + h0] = (x0 > 20.f) ? x0 : log1pf(expf(x0));
    g_dt[(m0 + mloc) * NH + h1] = (x1 > 20.f) ? x1 : log1pf(expf(x1));
}

// ---------------- prep A: u -> fp16 ----------------
__global__ __launch_bounds__(1024) void prep_cvt_kernel(const float* __restrict__ u,
                                                        __half* __restrict__ a1h) {
    int i = blockIdx.x * 1024 + threadIdx.x;
    float4 x = reinterpret_cast<const float4*>(u)[i];
    reinterpret_cast<__half2*>(a1h)[2 * i]     = __half2(__float2half(x.x), __float2half(x.y));
    reinterpret_cast<__half2*>(a1h)[2 * i + 1] = __half2(__float2half(x.z), __float2half(x.w));
}

// ---------------- prep W: transpose W_in and W_out to fp16 [N][K] ----------------
__global__ __launch_bounds__(1024) void prep_w_kernel(const float* __restrict__ W_in,
                                                      const float* __restrict__ W_out,
                                                      __half* __restrict__ b1h,
                                                      __half* __restrict__ b2h) {
    __shared__ float t[32][33];
    const int bx = blockIdx.x, tid = threadIdx.x;
    const int tx = tid & 31, ty = tid >> 5;
    if (bx < 4352) {
        int bxx = bx % 136, byy = bx / 136;
        int n = bxx * 32 + tx, k = byy * 32 + ty;
        t[ty][tx] = W_in[(size_t)k * DPROJ + n];
        __syncthreads();
        int nn = bxx * 32 + ty, kk = byy * 32 + tx;
        b1h[(size_t)nn * DMODEL + kk] = __float2half(t[tx][ty]);
    } else {
        int bb = bx - 4352;
        int bxx = bb % 32, byy = bb / 32;
        int n = bxx * 32 + tx, k = byy * 32 + ty;
        t[ty][tx] = W_out[(size_t)k * DMODEL + n];
        __syncthreads();
        int nn = bxx * 32 + ty, kk = byy * 32 + tx;
        b2h[(size_t)nn * DINNER + kk] = __float2half(t[tx][ty]);
    }
}

// ---------------- depthwise causal conv(4) + bias + SiLU (32 rows/block) ----------------
__global__ __launch_bounds__(256) void conv_kernel(const float* __restrict__ cw,
                                                   const float* __restrict__ cb) {
    __shared__ float s[35][256];
    int tid = threadIdx.x;
    int ch = blockIdx.x * 256 + tid;
    int m0 = blockIdx.y * 32;
    int l0 = m0 & (LSEQ - 1);
#pragma unroll
    for (int r = 0; r < 35; r++) {
        int l = l0 - 3 + r;
        s[r][tid] = (l >= 0) ? g_zx[(size_t)(m0 - 3 + r) * DPROJ + DINNER + ch] : 0.f;
    }
    __syncthreads();
    float w0 = cw[ch * 4], w1 = cw[ch * 4 + 1], w2 = cw[ch * 4 + 2], w3 = cw[ch * 4 + 3];
    float bias = cb[ch];
#pragma unroll
    for (int r = 0; r < 32; r++) {
        float acc = bias;
        acc = fmaf(s[r][tid], w0, acc);
        acc = fmaf(s[r + 1][tid], w1, acc);
        acc = fmaf(s[r + 2][tid], w2, acc);
        acc = fmaf(s[r + 3][tid], w3, acc);
        g_xbc[(size_t)(m0 + r) * CONVCH + ch] = acc / (1.f + expf(-acc));
    }
}

#define TS_STR 66
#define CS_STR 132
#define XS_STR 68

// ---------------- CB^T = C·B^T per (b,c), shared across heads ----------------
__global__ __launch_bounds__(256, 2) void cb_kernel() {
    int blk = blockIdx.x;
    int bc = blk >> 1, half = blk & 1;
    int m0 = (bc >> 6) * LSEQ + (bc & 63) * CHK;
    extern __shared__ float sm[];
    float* Bst = sm;
    float* Cs  = Bst + 128 * TS_STR;
    int tid = threadIdx.x;
    for (int i = tid; i < 64 * 128; i += 256) {
        int l = i >> 7, n = i & 127;
        Bst[n * TS_STR + l] = g_xbc[(size_t)(m0 + l) * CONVCH + DINNER + n];
    }
    for (int i = tid; i < 32 * 32; i += 256) {
        int ll = i >> 5, q = i & 31;
        float4 v = *reinterpret_cast<const float4*>(
            g_xbc + (size_t)(m0 + half * 32 + ll) * CONVCH + DINNER + DSTATE + 4 * q);
        *reinterpret_cast<float4*>(Cs + ll * CS_STR + 4 * q) = v;
    }
    __syncthreads();
    const int rg = tid >> 5, cg = tid & 31;
    const int r0 = rg * 4, c0 = cg * 2;
    float* out = g_cb + (size_t)bc * 4096 + (size_t)(half * 32) * 64;
    if (c0 > half * 32 + r0 + 3) {
#pragma unroll
        for (int i = 0; i < 4; i++)
            *reinterpret_cast<float2*>(out + (r0 + i) * 64 + c0) = make_float2(0.f, 0.f);
        return;
    }
    uint64_t acc2[4] = {0ull, 0ull, 0ull, 0ull};
    for (int n4 = 0; n4 < 128; n4 += 4) {
        float4 cr[4];
#pragma unroll
        for (int i = 0; i < 4; i++)
            cr[i] = *reinterpret_cast<const float4*>(Cs + (r0 + i) * CS_STR + n4);
#pragma unroll
        for (int nn = 0; nn < 4; nn++) {
            uint64_t b2 = *reinterpret_cast<const uint64_t*>(Bst + (n4 + nn) * TS_STR + c0);
#pragma unroll
            for (int i = 0; i < 4; i++) {
                uint64_t a2 = dup2((&cr[i].x)[nn]);
                FMA2(acc2[i], a2, b2);
            }
        }
    }
#pragma unroll
    for (int i = 0; i < 4; i++) {
        float v0, v1;
        up2(acc2[i], v0, v1);
        *reinterpret_cast<float2*>(out + (r0 + i) * 64 + c0) = make_float2(v0, v1);
    }
}

// ---------------- SSD intra-chunk ----------------
__global__ __launch_bounds__(256, 3) void ssd_diag_kernel(const float* __restrict__ A_log) {
    int blk = blockIdx.x;
    int h = blk & 31;
    int c = (blk >> 5) & 63;
    int b = blk >> 11;
    int m0 = b * LSEQ + c * CHK;

    extern __shared__ float sm[];
    float* Bst = sm;
    float* xs  = Bst + 128 * TS_STR;
    float* Gs  = xs + 64 * XS_STR;
    float* ac  = Gs + 64 * XS_STR;
    float* wd  = ac + 64;
    float* dts = wd + 64;
    int tid = threadIdx.x;

    if (tid < 32) {
        float A = -expf(A_log[h]);
        float dt0 = g_dt[(m0 + 2 * tid) * NH + h];
        float dt1 = g_dt[(m0 + 2 * tid + 1) * NH + h];
        dts[2 * tid] = dt0;
        dts[2 * tid + 1] = dt1;
        float e0 = A * dt0, e1 = A * dt1;
        float run = e0 + e1;
#pragma unroll
        for (int off = 1; off < 32; off <<= 1) {
            float v = __shfl_up_sync(0xFFFFFFFFu, run, off);
            if (tid >= off) run += v;
        }
        ac[2 * tid]     = run - e1;
        ac[2 * tid + 1] = run;
    }
    __syncthreads();
    if (tid < 64) {
        wd[tid] = expf(ac[63] - ac[tid]);
        g_acum[blk * CHK + tid] = ac[tid];
    }
    if (tid == 0) g_suma[blk] = expf(ac[63]);

    for (int i = tid; i < 64 * 128; i += 256) {
        int l = i >> 7, n = i & 127;
        Bst[n * TS_STR + l] = g_xbc[(size_t)(m0 + l) * CONVCH + DINNER + n];
    }
    for (int i = tid; i < 64 * 16; i += 256) {
        int l = i >> 4, q = i & 15;
        float dtv = dts[l];
        float4 v = *reinterpret_cast<const float4*>(
            g_xbc + (size_t)(m0 + l) * CONVCH + h * HD + 4 * q);
        v.x *= dtv; v.y *= dtv; v.z *= dtv; v.w *= dtv;
        *reinterpret_cast<float4*>(xs + l * XS_STR + 4 * q) = v;
    }
    {
        const float* cb = g_cb + (size_t)(b * NC + c) * 4096;
        for (int i = tid; i < 4096; i += 256) {
            int l = i >> 6, s = i & 63;
            float v = cb[i];
            Gs[l * XS_STR + s] = (s <= l) ? v * expf(ac[l] - ac[s]) : 0.f;
        }
    }
    __syncthreads();

    const int tr = tid >> 4, tc = tid & 15;
    const int r0 = tr * 4, c0 = tc * 4;

    {
        uint64_t acc2[4][2] = {{0ull,0ull},{0ull,0ull},{0ull,0ull},{0ull,0ull}};
        for (int s4 = 0; s4 < r0 + 4; s4 += 4) {
            float4 gr[4];
#pragma unroll
            for (int i = 0; i < 4; i++)
                gr[i] = *reinterpret_cast<const float4*>(Gs + (r0 + i) * XS_STR + s4);
#pragma unroll
            for (int ss = 0; ss < 4; ss++) {
                uint64_t x0 = *reinterpret_cast<const uint64_t*>(xs + (s4 + ss) * XS_STR + c0);
                uint64_t x1 = *reinterpret_cast<const uint64_t*>(xs + (s4 + ss) * XS_STR + c0 + 2);
#pragma unroll
                for (int i = 0; i < 4; i++) {
                    uint64_t a2 = dup2((&gr[i].x)[ss]);
                    FMA2(acc2[i][0], a2, x0);
                    FMA2(acc2[i][1], a2, x1);
                }
            }
        }
#pragma unroll
        for (int i = 0; i < 4; i++) {
            float v0, v1, v2, v3;
            up2(acc2[i][0], v0, v1);
            up2(acc2[i][1], v2, v3);
            *reinterpret_cast<float4*>(g_y + (size_t)(m0 + r0 + i) * DINNER + h * HD + c0) =
                make_float4(v0, v1, v2, v3);
        }
    }

    {
        const int p0 = (tid & 15) * 4, n0 = (tid >> 4) * 8;
        uint64_t acc2[2][8];
#pragma unroll
        for (int pp = 0; pp < 2; pp++)
#pragma unroll
            for (int j = 0; j < 8; j++) acc2[pp][j] = 0ull;
        for (int l = 0; l < 64; l++) {
            uint64_t w2 = dup2(wd[l]);
            uint64_t xa = *reinterpret_cast<const uint64_t*>(xs + l * XS_STR + p0);
            uint64_t xb = *reinterpret_cast<const uint64_t*>(xs + l * XS_STR + p0 + 2);
            uint64_t wxa, wxb;
            MUL2(wxa, xa, w2);
            MUL2(wxb, xb, w2);
#pragma unroll
            for (int j = 0; j < 8; j++) {
                uint64_t b2 = dup2(Bst[(n0 + j) * TS_STR + l]);
                FMA2(acc2[0][j], wxa, b2);
                FMA2(acc2[1][j], wxb, b2);
            }
        }
        float rowv[4][8];
#pragma unroll
        for (int pp = 0; pp < 2; pp++)
#pragma unroll
            for (int j = 0; j < 8; j++)
                up2(acc2[pp][j], rowv[2 * pp][j], rowv[2 * pp + 1][j]);
#pragma unroll
        for (int i = 0; i < 4; i++) {
            float* dst = g_states + ((size_t)blk * HD + p0 + i) * DSTATE + n0;
            *reinterpret_cast<float4*>(dst)     = make_float4(rowv[i][0], rowv[i][1], rowv[i][2], rowv[i][3]);
            *reinterpret_cast<float4*>(dst + 4) = make_float4(rowv[i][4], rowv[i][5], rowv[i][6], rowv[i][7]);
        }
    }
}

// ---------------- inter-chunk scan (float2 + prefetch) ----------------
__global__ void scan_kernel() {
    int idx = blockIdx.x * blockDim.x + threadIdx.x;
    int n2 = idx & 63;
    int p = (idx >> 6) & 63;
    int h = (idx >> 12) & 31;
    int b = idx >> 17;
    const size_t cstep = (size_t)NH * HD * DSTATE;
    int bch0 = b * NC * NH + h;
    size_t off = ((size_t)bch0 * HD + p) * DSTATE + 2 * n2;
    float2 prev = make_float2(0.f, 0.f);
    float2 loc = *reinterpret_cast<float2*>(g_states + off);
    for (int c = 0; c < NC; c++) {
        float2 nxt = (c + 1 < NC) ? *reinterpret_cast<float2*>(g_states + off + cstep)
                                  : make_float2(0.f, 0.f);
        float e = g_suma[bch0 + c * NH];
        *reinterpret_cast<float2*>(g_states + off) = prev;
        prev.x = fmaf(prev.x, e, loc.x);
        prev.y = fmaf(prev.y, e, loc.y);
        loc = nxt;
        off += cstep;
    }
}

// ---------------- Y_off + skip (f32x2, half-C double pass, 3 CTAs/SM) ----------------
#define CS2_STR 68
__global__ __launch_bounds__(256, 3) void yoff_kernel(const float* __restrict__ Dv) {
    int blk = blockIdx.x;
    int h = blk & 31;
    int c = (blk >> 5) & 63;
    int b = blk >> 11;
    int m0 = b * LSEQ + c * CHK;

    extern __shared__ float sm[];
    float* Pst = sm;
    float* Cs2 = Pst + 128 * TS_STR;
    float* ac  = Cs2 + 64 * CS2_STR;
    int tid = threadIdx.x;

    for (int i = tid; i < 64 * 128; i += 256) {
        int p = i >> 7, n = i & 127;
        Pst[n * TS_STR + p] = g_states[((size_t)blk * HD + p) * DSTATE + n];
    }
    if (tid < 64) ac[tid] = g_acum[blk * CHK + tid];
    float Dh = Dv[h];

    const int tr = tid >> 4, tc = tid & 15;
    const int r0 = tr * 4, c0 = tc * 4;
    uint64_t acc2[4][2] = {{0ull,0ull},{0ull,0ull},{0ull,0ull},{0ull,0ull}};

#pragma unroll
    for (int half = 0; half < 2; half++) {
        __syncthreads();
        for (int i = tid; i < 64 * 16; i += 256) {
            int l = i >> 4, q = i & 15;
            float4 v = *reinterpret_cast<const float4*>(
                g_xbc + (size_t)(m0 + l) * CONVCH + DINNER + DSTATE + half * 64 + 4 * q);
            *reinterpret_cast<float4*>(Cs2 + l * CS2_STR + 4 * q) = v;
        }
        __syncthreads();
        for (int n4 = 0; n4 < 64; n4 += 4) {
            float4 cr[4];
#pragma unroll
            for (int i = 0; i < 4; i++)
                cr[i] = *reinterpret_cast<const float4*>(Cs2 + (r0 + i) * CS2_STR + n4);
#pragma unroll
            for (int nn = 0; nn < 4; nn++) {
                int n = half * 64 + n4 + nn;
                uint64_t p0v = *reinterpret_cast<const uint64_t*>(Pst + n * TS_STR + c0);
                uint64_t p1v = *reinterpret_cast<const uint64_t*>(Pst + n * TS_STR + c0 + 2);
#pragma unroll
                for (int i = 0; i < 4; i++) {
                    uint64_t a2 = dup2((&cr[i].x)[nn]);
                    FMA2(acc2[i][0], a2, p0v);
                    FMA2(acc2[i][1], a2, p1v);
                }
            }
        }
    }

#pragma unroll
    for (int i = 0; i < 4; i++) {
        int l = r0 + i;
        int row = m0 + l;
        float el = expf(ac[l]);
        float v0, v1, v2, v3;
        up2(acc2[i][0], v0, v1);
        up2(acc2[i][1], v2, v3);
        float4 xv = *reinterpret_cast<const float4*>(
            g_xbc + (size_t)row * CONVCH + h * HD + c0);
        float4* yp = reinterpret_cast<float4*>(g_y + (size_t)row * DINNER + h * HD + c0);
        float4 yv = *yp;
        yv.x += v0 * el + xv.x * Dh;
        yv.y += v1 * el + xv.y * Dh;
        yv.z += v2 * el + xv.z * Dh;
        yv.w += v3 * el + xv.w * Dh;
        *yp = yv;
    }
}

// ---------------- gate (silu(z)) + RMSNorm, shuffle reduction, fp16 out ----------
__global__ void gate_kernel(const float* __restrict__ norm_w, __half* __restrict__ a2h) {
    int m = blockIdx.x;
    int tid = threadIdx.x;
    __shared__ float wsum[8];
    float tv[8];
    float ss = 0.f;
#pragma unroll
    for (int j = 0; j < 8; j++) {
        int i = tid + 256 * j;
        float zv = g_zx[(size_t)m * DPROJ + i];
        float yv = g_y[(size_t)m * DINNER + i];
        float g = yv * (zv / (1.f + expf(-zv)));
        tv[j] = g;
        ss += g * g;
    }
#pragma unroll
    for (int o = 16; o; o >>= 1) ss += __shfl_xor_sync(0xFFFFFFFFu, ss, o);
    if ((tid & 31) == 0) wsum[tid >> 5] = ss;
    __syncthreads();
    float tot = wsum[0] + wsum[1] + wsum[2] + wsum[3] +
                wsum[4] + wsum[5] + wsum[6] + wsum[7];
    float scale = rsqrtf(tot / (float)DINNER + 1e-5f);
#pragma unroll
    for (int j = 0; j < 8; j++) {
        int i = tid + 256 * j;
        a2h[(size_t)m * DINNER + i] = __float2half(tv[j] * scale * norm_w[i]);
    }
}

// ---------------- launch ----------------
extern "C" void kernel_launch(void* const* d_in, const int* in_sizes, int n_in,
                              void* d_out, int out_size) {
    const float* u      = (const float*)d_in[0];
    const float* W_in   = (const float*)d_in[1];
    const float* conv_w = (const float*)d_in[2];
    const float* conv_b = (const float*)d_in[3];
    const float* dt_b   = (const float*)d_in[4];
    const float* A_log  = (const float*)d_in[5];
    const float* Dv     = (const float*)d_in[6];
    const float* norm_w = (const float*)d_in[7];
    const float* W_out  = (const float*)d_in[8];
    float* out = (float*)d_out;

    float* zx = nullptr;
    cudaGetSymbolAddress((void**)&zx, g_zx);
    __half *a1h, *b1h, *a2h, *b2h;
    cudaGetSymbolAddress((void**)&a1h, g_a1h);
    cudaGetSymbolAddress((void**)&b1h, g_b1h);
    cudaGetSymbolAddress((void**)&a2h, g_a2h);
    cudaGetSymbolAddress((void**)&b2h, g_b2h);

    const size_t gemm_smem = 3 * 24576;   // 73728, 2 CTAs/SM
    const size_t cb_smem   = (size_t)(128 * TS_STR + 32 * CS_STR) * sizeof(float);
    const size_t diag_smem = (size_t)(128 * TS_STR + 2 * 64 * XS_STR + 192) * sizeof(float);
    const size_t yoff_smem = (size_t)(128 * TS_STR + 64 * CS2_STR + 64) * sizeof(float);
    cudaFuncSetAttribute(hgemm1_kernel, cudaFuncAttributeMaxDynamicSharedMemorySize, (int)gemm_smem);
    cudaFuncSetAttribute(cb_kernel, cudaFuncAttributeMaxDynamicSharedMemorySize, (int)cb_smem);
    cudaFuncSetAttribute(ssd_diag_kernel, cudaFuncAttributeMaxDynamicSharedMemorySize, (int)diag_smem);
    cudaFuncSetAttribute(yoff_kernel, cudaFuncAttributeMaxDynamicSharedMemorySize, (int)yoff_smem);

    // 0: exact fp32 dt
    dt_exact_kernel<<<MROWS / 16, 256>>>(u, W_in, dt_b);

    // 1: prep A (u -> fp16)
    prep_cvt_kernel<<<MROWS * DMODEL / 4096, 1024>>>(u, a1h);

    // 2: prep W
    prep_w_kernel<<<4352 + 2048, 1024>>>(W_in, W_out, b1h, b2h);

    // 3: GEMM1 (profiled): zx[:, :4352] = u @ W_in (fp16 single product, 3-stage)
    hgemm1_kernel<<<dim3(NGEMM1 / 64, MROWS / 128), 256, gemm_smem>>>(
        a1h, b1h, zx, NGEMM1, DMODEL, DPROJ);

    // 4: conv
    conv_kernel<<<dim3(CONVCH / 256, MROWS / 32), 256>>>(conv_w, conv_b);

    // 5: CB^T shared across heads
    cb_kernel<<<BQ * NC * 2, 256, cb_smem>>>();

    // 6: SSD intra-chunk
    ssd_diag_kernel<<<BQ * NC * NH, 256, diag_smem>>>(A_log);

    // 7: inter-chunk scan
    scan_kernel<<<(BQ * NH * HD * DSTATE / 2) / 256, 256>>>();

    // 8: Y_off + skip
    yoff_kernel<<<BQ * NC * NH, 256, yoff_smem>>>(Dv);

    // 9: gate + rmsnorm (writes fp16 A for GEMM2)
    gate_kernel<<<MROWS, 256>>>(norm_w, a2h);

    // 10: GEMM2: out = y @ W_out (fp16 single product, 3-stage)
    hgemm1_kernel<<<dim3(DMODEL / 64, MROWS / 128), 256, gemm_smem>>>(
        a2h, b2h, out, DMODEL, DINNER, DMODEL);
}

// round 17
// speedup vs baseline: 2.9598x; 1.0392x over previous
#include <cuda_runtime.h>
#include <cuda_bf16.h>
#include <cuda_fp16.h>
#include <math.h>
#include <cstdint>

// ---------------- problem constants ----------------
#define BQ 2
#define LSEQ 4096
#define DMODEL 1024
#define DINNER 2048
#define NH 32
#define HD 64
#define DSTATE 128
#define CHK 64
#define NC 64
#define DPROJ 4384
#define CONVCH 2304
#define MROWS (BQ*LSEQ)
#define NPAD1 4480
#define NGEMM1 4352

// ---------------- scratch (device globals; no allocation) ----------------
__device__ float g_zx[(size_t)MROWS * DPROJ];
__device__ float g_xbc[(size_t)MROWS * CONVCH];
__device__ float g_dt[MROWS * NH];
__device__ float g_acum[BQ * NC * NH * CHK];
__device__ float g_suma[BQ * NC * NH];
__device__ __half g_states[(size_t)BQ * NC * NH * HD * DSTATE];  // fp16: 64MB, L2-resident
__device__ float g_y[(size_t)MROWS * DINNER];
__device__ float g_cb[(size_t)BQ * NC * CHK * CHK];

// GEMM operands (fp16, single product both GEMMs)
__device__ __half g_a1h[(size_t)MROWS * DMODEL];
__device__ __half g_b1h[(size_t)NPAD1 * DMODEL];
__device__ __half g_a2h[(size_t)MROWS * DINNER];
__device__ __half g_b2h[(size_t)DMODEL * DINNER];

// ---------------- PTX helpers ----------------
__device__ __forceinline__ uint32_t smem_u32(const void* p) {
    uint32_t a;
    asm("{ .reg .u64 t; cvta.to.shared.u64 t, %1; cvt.u32.u64 %0, t; }" : "=r"(a) : "l"(p));
    return a;
}
#define SMEM_SWIZZLE_128B(byte_offset) ((byte_offset) ^ (((byte_offset) >> 3) & 0x70))
#define CP_ASYNC16(dst, src) \
    asm volatile("cp.async.cg.shared.global [%0], [%1], 16;" :: "r"(dst), "l"(src) : "memory")
#define CP_COMMIT() asm volatile("cp.async.commit_group;" ::: "memory")
#define CP_WAIT0()  asm volatile("cp.async.wait_group 0;" ::: "memory")
#define CP_WAIT1()  asm volatile("cp.async.wait_group 1;" ::: "memory")
#define CP_WAIT2()  asm volatile("cp.async.wait_group 2;" ::: "memory")

#define LDSM_X4(r0,r1,r2,r3,addr) \
    asm volatile("ldmatrix.sync.aligned.m8n8.x4.shared.b16 {%0,%1,%2,%3}, [%4];" \
        : "=r"(r0), "=r"(r1), "=r"(r2), "=r"(r3) : "r"(addr))

#define MMAH16816(d, a, b0, b1) \
    asm volatile("mma.sync.aligned.m16n8k16.row.col.f32.f16.f16.f32 " \
        "{%0,%1,%2,%3}, {%4,%5,%6,%7}, {%8,%9}, {%0,%1,%2,%3};" \
        : "+f"((d)[0]), "+f"((d)[1]), "+f"((d)[2]), "+f"((d)[3]) \
        : "r"((a)[0]), "r"((a)[1]), "r"((a)[2]), "r"((a)[3]), "r"(b0), "r"(b1))

// packed f32x2 (2x fp32 FMA rate)
#define FMA2(d, a, b) asm("fma.rn.f32x2 %0, %1, %2, %0;" : "+l"(d) : "l"(a), "l"(b))
#define MUL2(d, a, b) asm("mul.rn.f32x2 %0, %1, %2;" : "=l"(d) : "l"(a), "l"(b))
__device__ __forceinline__ uint64_t dup2(float x) {
    uint64_t r; asm("mov.b64 %0, {%1, %1};" : "=l"(r) : "f"(x)); return r;
}
__device__ __forceinline__ void up2(uint64_t v, float& lo, float& hi) {
    asm("mov.b64 {%0, %1}, %2;" : "=f"(lo), "=f"(hi) : "l"(v));
}

__device__ __forceinline__ void ldsmA(uint32_t base, int row, int ks, int lane, uint32_t* r) {
    int rr = row + (lane & 15);
    int off = rr * 128 + ks * 32 + ((lane >> 4) << 4);
    LDSM_X4(r[0], r[1], r[2], r[3], base + SMEM_SWIZZLE_128B((uint32_t)off));
}
__device__ __forceinline__ void ldsmB(uint32_t base, int nrow, int ks, int lane, uint32_t* r) {
    int n = nrow + ((lane >> 4) << 3) + (lane & 7);
    int off = n * 128 + ks * 32 + (((lane >> 3) & 1) << 4);
    LDSM_X4(r[0], r[1], r[2], r[3], base + SMEM_SWIZZLE_128B((uint32_t)off));
}

// ---------------- single-product fp16 GEMM, 4-stage cp.async ring ----------------
// stage: A 16K + B 8K = 24K; 4 stages = 96K, 2 CTAs/SM.
__global__ __launch_bounds__(256, 2) void hgemm1_kernel(
    const __half* __restrict__ Ah, const __half* __restrict__ Bh,
    float* __restrict__ C, int N, int K, int ldc)
{
    extern __shared__ char smem[];
    const uint32_t sb = smem_u32(smem);
    const int tid = threadIdx.x, wid = tid >> 5, lane = tid & 31;
    const int wr = wid & 3, wc = wid >> 2;
    const int rowbase = blockIdx.y * 128, colbase = blockIdx.x * 64;
    const int KC = K >> 6;

    float acc[2][4][4];
#pragma unroll
    for (int mi = 0; mi < 2; mi++)
#pragma unroll
        for (int ni = 0; ni < 4; ni++)
#pragma unroll
            for (int j = 0; j < 4; j++) acc[mi][ni][j] = 0.f;

    auto issue_chunk = [&](int i) {
        const uint32_t st = (uint32_t)(i & 3) * 24576u;
        const int k0 = i << 6;
#pragma unroll
        for (int v = 0; v < 6; v++) {
            const int idx = v * 256 + tid;
            const __half* src;
            uint32_t dst;
            if (idx < 1024) {
                const int r = idx >> 3, c8 = idx & 7;
                src = Ah + (size_t)(rowbase + r) * K + k0 + c8 * 8;
                dst = sb + st + SMEM_SWIZZLE_128B((uint32_t)(r * 128 + c8 * 16));
            } else {
                const int j = idx - 1024;
                const int r = j >> 3, c8 = j & 7;
                src = Bh + (size_t)(colbase + r) * K + k0 + c8 * 8;
                dst = sb + st + 16384u + SMEM_SWIZZLE_128B((uint32_t)(r * 128 + c8 * 16));
            }
            CP_ASYNC16(dst, src);
        }
    };

    issue_chunk(0); CP_COMMIT();
    issue_chunk(1); CP_COMMIT();
    issue_chunk(2); CP_COMMIT();

    for (int i = 0; i < KC; i++) {
        const int rem = KC - 1 - i;
        if (rem >= 2) { CP_WAIT2(); } else if (rem == 1) { CP_WAIT1(); } else { CP_WAIT0(); }
        __syncthreads();
        if (i + 3 < KC) { issue_chunk(i + 3); CP_COMMIT(); }

        const uint32_t st = sb + (uint32_t)(i & 3) * 24576u;
        const uint32_t aH = st, bH = st + 16384u;
#pragma unroll
        for (int ks = 0; ks < 4; ks++) {
            uint32_t ah[2][4], bh[2][4];
#pragma unroll
            for (int mi = 0; mi < 2; mi++)
                ldsmA(aH, wr * 32 + mi * 16, ks, lane, ah[mi]);
#pragma unroll
            for (int np = 0; np < 2; np++)
                ldsmB(bH, wc * 32 + np * 16, ks, lane, bh[np]);
#pragma unroll
            for (int mi = 0; mi < 2; mi++)
#pragma unroll
                for (int ni = 0; ni < 4; ni++) {
                    const int np = ni >> 1, o = (ni & 1) << 1;
                    MMAH16816(acc[mi][ni], ah[mi], bh[np][o], bh[np][o + 1]);
                }
        }
    }

#pragma unroll
    for (int mi = 0; mi < 2; mi++) {
        const int row = rowbase + wr * 32 + mi * 16 + (lane >> 2);
#pragma unroll
        for (int ni = 0; ni < 4; ni++) {
            const int col = colbase + wc * 32 + ni * 8 + (lane & 3) * 2;
            if (col < N) {
                *reinterpret_cast<float2*>(&C[(size_t)row * ldc + col]) =
                    make_float2(acc[mi][ni][0], acc[mi][ni][1]);
                *reinterpret_cast<float2*>(&C[(size_t)(row + 8) * ldc + col]) =
                    make_float2(acc[mi][ni][2], acc[mi][ni][3]);
            }
        }
    }
}

// ---------------- exact fp32 dt ----------------
__global__ __launch_bounds__(256) void dt_exact_kernel(const float* __restrict__ u,
                                                       const float* __restrict__ W_in,
                                                       const float* __restrict__ dt_bias) {
    __shared__ float us[16 * 256];
    __shared__ float ws[256 * 32];
    const int m0 = blockIdx.x * 16;
    const int t = threadIdx.x;
    const int mloc = t >> 4, h0 = t & 15, h1 = 16 + (t & 15);
    float acc0 = 0.f, acc1 = 0.f;
    for (int kc = 0; kc < 4; kc++) {
        __syncthreads();
        for (int i = t; i < 4096; i += 256) {
            int mm = i >> 8, kk = i & 255;
            us[i] = u[(size_t)(m0 + mm) * DMODEL + kc * 256 + kk];
        }
        for (int i = t; i < 8192; i += 256) {
            int kk = i >> 5, hh = i & 31;
            ws[i] = W_in[(size_t)(kc * 256 + kk) * DPROJ + (DPROJ - NH) + hh];
        }
        __syncthreads();
#pragma unroll 8
        for (int kk = 0; kk < 256; kk++) {
            float uv = us[mloc * 256 + kk];
            acc0 = fmaf(uv, ws[kk * 32 + h0], acc0);
            acc1 = fmaf(uv, ws[kk * 32 + h1], acc1);
        }
    }
    float x0 = acc0 + dt_bias[h0];
    float x1 = acc1 + dt_bias[h1];
    g_dt[(m0 + mloc) * NH + h0] = (x0 > 20.f) ? x0 : log1pf(expf(x0));
    g_dt[(m0 + mloc) * NH + h1] = (x1 > 20.f) ? x1 : log1pf(expf(x1));
}

// ---------------- prep A: u -> fp16 ----------------
__global__ __launch_bounds__(1024) void prep_cvt_kernel(const float* __restrict__ u,
                                                        __half* __restrict__ a1h) {
    int i = blockIdx.x * 1024 + threadIdx.x;
    float4 x = reinterpret_cast<const float4*>(u)[i];
    reinterpret_cast<__half2*>(a1h)[2 * i]     = __half2(__float2half(x.x), __float2half(x.y));
    reinterpret_cast<__half2*>(a1h)[2 * i + 1] = __half2(__float2half(x.z), __float2half(x.w));
}

// ---------------- prep W ----------------
__global__ __launch_bounds__(1024) void prep_w_kernel(const float* __restrict__ W_in,
                                                      const float* __restrict__ W_out,
                                                      __half* __restrict__ b1h,
                                                      __half* __restrict__ b2h) {
    __shared__ float t[32][33];
    const int bx = blockIdx.x, tid = threadIdx.x;
    const int tx = tid & 31, ty = tid >> 5;
    if (bx < 4352) {
        int bxx = bx % 136, byy = bx / 136;
        int n = bxx * 32 + tx, k = byy * 32 + ty;
        t[ty][tx] = W_in[(size_t)k * DPROJ + n];
        __syncthreads();
        int nn = bxx * 32 + ty, kk = byy * 32 + tx;
        b1h[(size_t)nn * DMODEL + kk] = __float2half(t[tx][ty]);
    } else {
        int bb = bx - 4352;
        int bxx = bb % 32, byy = bb / 32;
        int n = bxx * 32 + tx, k = byy * 32 + ty;
        t[ty][tx] = W_out[(size_t)k * DMODEL + n];
        __syncthreads();
        int nn = bxx * 32 + ty, kk = byy * 32 + tx;
        b2h[(size_t)nn * DINNER + kk] = __float2half(t[tx][ty]);
    }
}

// ---------------- depthwise causal conv(4) + bias + SiLU (32 rows/block) ----------------
__global__ __launch_bounds__(256) void conv_kernel(const float* __restrict__ cw,
                                                   const float* __restrict__ cb) {
    __shared__ float s[35][256];
    int tid = threadIdx.x;
    int ch = blockIdx.x * 256 + tid;
    int m0 = blockIdx.y * 32;
    int l0 = m0 & (LSEQ - 1);
#pragma unroll
    for (int r = 0; r < 35; r++) {
        int l = l0 - 3 + r;
        s[r][tid] = (l >= 0) ? g_zx[(size_t)(m0 - 3 + r) * DPROJ + DINNER + ch] : 0.f;
    }
    __syncthreads();
    float w0 = cw[ch * 4], w1 = cw[ch * 4 + 1], w2 = cw[ch * 4 + 2], w3 = cw[ch * 4 + 3];
    float bias = cb[ch];
#pragma unroll
    for (int r = 0; r < 32; r++) {
        float acc = bias;
        acc = fmaf(s[r][tid], w0, acc);
        acc = fmaf(s[r + 1][tid], w1, acc);
        acc = fmaf(s[r + 2][tid], w2, acc);
        acc = fmaf(s[r + 3][tid], w3, acc);
        g_xbc[(size_t)(m0 + r) * CONVCH + ch] = acc / (1.f + expf(-acc));
    }
}

#define TS_STR 66
#define CS_STR 132
#define XS_STR 68

// ---------------- CB^T = C·B^T per (b,c) ----------------
__global__ __launch_bounds__(256, 2) void cb_kernel() {
    int blk = blockIdx.x;
    int bc = blk >> 1, half = blk & 1;
    int m0 = (bc >> 6) * LSEQ + (bc & 63) * CHK;
    extern __shared__ float sm[];
    float* Bst = sm;
    float* Cs  = Bst + 128 * TS_STR;
    int tid = threadIdx.x;
    for (int i = tid; i < 64 * 128; i += 256) {
        int l = i >> 7, n = i & 127;
        Bst[n * TS_STR + l] = g_xbc[(size_t)(m0 + l) * CONVCH + DINNER + n];
    }
    for (int i = tid; i < 32 * 32; i += 256) {
        int ll = i >> 5, q = i & 31;
        float4 v = *reinterpret_cast<const float4*>(
            g_xbc + (size_t)(m0 + half * 32 + ll) * CONVCH + DINNER + DSTATE + 4 * q);
        *reinterpret_cast<float4*>(Cs + ll * CS_STR + 4 * q) = v;
    }
    __syncthreads();
    const int rg = tid >> 5, cg = tid & 31;
    const int r0 = rg * 4, c0 = cg * 2;
    float* out = g_cb + (size_t)bc * 4096 + (size_t)(half * 32) * 64;
    if (c0 > half * 32 + r0 + 3) {
#pragma unroll
        for (int i = 0; i < 4; i++)
            *reinterpret_cast<float2*>(out + (r0 + i) * 64 + c0) = make_float2(0.f, 0.f);
        return;
    }
    uint64_t acc2[4] = {0ull, 0ull, 0ull, 0ull};
    for (int n4 = 0; n4 < 128; n4 += 4) {
        float4 cr[4];
#pragma unroll
        for (int i = 0; i < 4; i++)
            cr[i] = *reinterpret_cast<const float4*>(Cs + (r0 + i) * CS_STR + n4);
#pragma unroll
        for (int nn = 0; nn < 4; nn++) {
            uint64_t b2 = *reinterpret_cast<const uint64_t*>(Bst + (n4 + nn) * TS_STR + c0);
#pragma unroll
            for (int i = 0; i < 4; i++) {
                uint64_t a2 = dup2((&cr[i].x)[nn]);
                FMA2(acc2[i], a2, b2);
            }
        }
    }
#pragma unroll
    for (int i = 0; i < 4; i++) {
        float v0, v1;
        up2(acc2[i], v0, v1);
        *reinterpret_cast<float2*>(out + (r0 + i) * 64 + c0) = make_float2(v0, v1);
    }
}

// ---------------- SSD intra-chunk (states stored fp16) ----------------
__global__ __launch_bounds__(256, 3) void ssd_diag_kernel(const float* __restrict__ A_log) {
    int blk = blockIdx.x;
    int h = blk & 31;
    int c = (blk >> 5) & 63;
    int b = blk >> 11;
    int m0 = b * LSEQ + c * CHK;

    extern __shared__ float sm[];
    float* Bst = sm;
    float* xs  = Bst + 128 * TS_STR;
    float* Gs  = xs + 64 * XS_STR;
    float* ac  = Gs + 64 * XS_STR;
    float* wd  = ac + 64;
    float* dts = wd + 64;
    int tid = threadIdx.x;

    if (tid < 32) {
        float A = -expf(A_log[h]);
        float dt0 = g_dt[(m0 + 2 * tid) * NH + h];
        float dt1 = g_dt[(m0 + 2 * tid + 1) * NH + h];
        dts[2 * tid] = dt0;
        dts[2 * tid + 1] = dt1;
        float e0 = A * dt0, e1 = A * dt1;
        float run = e0 + e1;
#pragma unroll
        for (int off = 1; off < 32; off <<= 1) {
            float v = __shfl_up_sync(0xFFFFFFFFu, run, off);
            if (tid >= off) run += v;
        }
        ac[2 * tid]     = run - e1;
        ac[2 * tid + 1] = run;
    }
    __syncthreads();
    if (tid < 64) {
        wd[tid] = expf(ac[63] - ac[tid]);
        g_acum[blk * CHK + tid] = ac[tid];
    }
    if (tid == 0) g_suma[blk] = expf(ac[63]);

    for (int i = tid; i < 64 * 128; i += 256) {
        int l = i >> 7, n = i & 127;
        Bst[n * TS_STR + l] = g_xbc[(size_t)(m0 + l) * CONVCH + DINNER + n];
    }
    for (int i = tid; i < 64 * 16; i += 256) {
        int l = i >> 4, q = i & 15;
        float dtv = dts[l];
        float4 v = *reinterpret_cast<const float4*>(
            g_xbc + (size_t)(m0 + l) * CONVCH + h * HD + 4 * q);
        v.x *= dtv; v.y *= dtv; v.z *= dtv; v.w *= dtv;
        *reinterpret_cast<float4*>(xs + l * XS_STR + 4 * q) = v;
    }
    {
        const float* cb = g_cb + (size_t)(b * NC + c) * 4096;
        for (int i = tid; i < 4096; i += 256) {
            int l = i >> 6, s = i & 63;
            float v = cb[i];
            Gs[l * XS_STR + s] = (s <= l) ? v * expf(ac[l] - ac[s]) : 0.f;
        }
    }
    __syncthreads();

    const int tr = tid >> 4, tc = tid & 15;
    const int r0 = tr * 4, c0 = tc * 4;

    {
        uint64_t acc2[4][2] = {{0ull,0ull},{0ull,0ull},{0ull,0ull},{0ull,0ull}};
        for (int s4 = 0; s4 < r0 + 4; s4 += 4) {
            float4 gr[4];
#pragma unroll
            for (int i = 0; i < 4; i++)
                gr[i] = *reinterpret_cast<const float4*>(Gs + (r0 + i) * XS_STR + s4);
#pragma unroll
            for (int ss = 0; ss < 4; ss++) {
                uint64_t x0 = *reinterpret_cast<const uint64_t*>(xs + (s4 + ss) * XS_STR + c0);
                uint64_t x1 = *reinterpret_cast<const uint64_t*>(xs + (s4 + ss) * XS_STR + c0 + 2);
#pragma unroll
                for (int i = 0; i < 4; i++) {
                    uint64_t a2 = dup2((&gr[i].x)[ss]);
                    FMA2(acc2[i][0], a2, x0);
                    FMA2(acc2[i][1], a2, x1);
                }
            }
        }
#pragma unroll
        for (int i = 0; i < 4; i++) {
            float v0, v1, v2, v3;
            up2(acc2[i][0], v0, v1);
            up2(acc2[i][1], v2, v3);
            *reinterpret_cast<float4*>(g_y + (size_t)(m0 + r0 + i) * DINNER + h * HD + c0) =
                make_float4(v0, v1, v2, v3);
        }
    }

    {
        const int p0 = (tid & 15) * 4, n0 = (tid >> 4) * 8;
        uint64_t acc2[2][8];
#pragma unroll
        for (int pp = 0; pp < 2; pp++)
#pragma unroll
            for (int j = 0; j < 8; j++) acc2[pp][j] = 0ull;
        for (int l = 0; l < 64; l++) {
            uint64_t w2 = dup2(wd[l]);
            uint64_t xa = *reinterpret_cast<const uint64_t*>(xs + l * XS_STR + p0);
            uint64_t xb = *reinterpret_cast<const uint64_t*>(xs + l * XS_STR + p0 + 2);
            uint64_t wxa, wxb;
            MUL2(wxa, xa, w2);
            MUL2(wxb, xb, w2);
#pragma unroll
            for (int j = 0; j < 8; j++) {
                uint64_t b2 = dup2(Bst[(n0 + j) * TS_STR + l]);
                FMA2(acc2[0][j], wxa, b2);
                FMA2(acc2[1][j], wxb, b2);
            }
        }
        float rowv[4][8];
#pragma unroll
        for (int pp = 0; pp < 2; pp++)
#pragma unroll
            for (int j = 0; j < 8; j++)
                up2(acc2[pp][j], rowv[2 * pp][j], rowv[2 * pp + 1][j]);
#pragma unroll
        for (int i = 0; i < 4; i++) {
            __half* dst = g_states + ((size_t)blk * HD + p0 + i) * DSTATE + n0;
            __half2 q0 = __floats2half2_rn(rowv[i][0], rowv[i][1]);
            __half2 q1 = __floats2half2_rn(rowv[i][2], rowv[i][3]);
            __half2 q2 = __floats2half2_rn(rowv[i][4], rowv[i][5]);
            __half2 q3 = __floats2half2_rn(rowv[i][6], rowv[i][7]);
            uint4 pk;
            pk.x = *reinterpret_cast<uint32_t*>(&q0);
            pk.y = *reinterpret_cast<uint32_t*>(&q1);
            pk.z = *reinterpret_cast<uint32_t*>(&q2);
            pk.w = *reinterpret_cast<uint32_t*>(&q3);
            *reinterpret_cast<uint4*>(dst) = pk;
        }
    }
}

// ---------------- inter-chunk scan (fp16 states, 4 lanes/thread, prefetch) ----------------
__global__ void scan_kernel() {
    int idx = blockIdx.x * blockDim.x + threadIdx.x;   // BQ*NH*HD*DSTATE/4 = 131072
    int n4 = idx & 31;
    int p = (idx >> 5) & 63;
    int h = (idx >> 11) & 31;
    int b = idx >> 16;
    const size_t cstep = (size_t)NH * HD * DSTATE;
    int bch0 = b * NC * NH + h;
    size_t off = ((size_t)bch0 * HD + p) * DSTATE + 4 * n4;
    float4 prev = make_float4(0.f, 0.f, 0.f, 0.f);
    uint2 raw = *reinterpret_cast<uint2*>(g_states + off);
    for (int c = 0; c < NC; c++) {
        uint2 nraw = (c + 1 < NC) ? *reinterpret_cast<uint2*>(g_states + off + cstep)
                                  : make_uint2(0u, 0u);
        float e = g_suma[bch0 + c * NH];
        __half2 l0 = *reinterpret_cast<__half2*>(&raw.x);
        __half2 l1 = *reinterpret_cast<__half2*>(&raw.y);
        float2 f0 = __half22float2(l0);
        float2 f1 = __half22float2(l1);
        // store prev (entering state) as fp16
        __half2 s0 = __floats2half2_rn(prev.x, prev.y);
        __half2 s1 = __floats2half2_rn(prev.z, prev.w);
        uint2 sraw;
        sraw.x = *reinterpret_cast<uint32_t*>(&s0);
        sraw.y = *reinterpret_cast<uint32_t*>(&s1);
        *reinterpret_cast<uint2*>(g_states + off) = sraw;
        prev.x = fmaf(prev.x, e, f0.x);
        prev.y = fmaf(prev.y, e, f0.y);
        prev.z = fmaf(prev.z, e, f1.x);
        prev.w = fmaf(prev.w, e, f1.y);
        raw = nraw;
        off += cstep;
    }
}

// ---------------- Y_off + skip (fp16 states) ----------------
#define CS2_STR 68
__global__ __launch_bounds__(256, 3) void yoff_kernel(const float* __restrict__ Dv) {
    int blk = blockIdx.x;
    int h = blk & 31;
    int c = (blk >> 5) & 63;
    int b = blk >> 11;
    int m0 = b * LSEQ + c * CHK;

    extern __shared__ float sm[];
    float* Pst = sm;
    float* Cs2 = Pst + 128 * TS_STR;
    float* ac  = Cs2 + 64 * CS2_STR;
    int tid = threadIdx.x;

    for (int i = tid; i < 64 * 128; i += 256) {
        int p = i >> 7, n = i & 127;
        Pst[n * TS_STR + p] = __half2float(g_states[((size_t)blk * HD + p) * DSTATE + n]);
    }
    if (tid < 64) ac[tid] = g_acum[blk * CHK + tid];
    float Dh = Dv[h];

    const int tr = tid >> 4, tc = tid & 15;
    const int r0 = tr * 4, c0 = tc * 4;
    uint64_t acc2[4][2] = {{0ull,0ull},{0ull,0ull},{0ull,0ull},{0ull,0ull}};

#pragma unroll
    for (int half = 0; half < 2; half++) {
        __syncthreads();
        for (int i = tid; i < 64 * 16; i += 256) {
            int l = i >> 4, q = i & 15;
            float4 v = *reinterpret_cast<const float4*>(
                g_xbc + (size_t)(m0 + l) * CONVCH + DINNER + DSTATE + half * 64 + 4 * q);
            *reinterpret_cast<float4*>(Cs2 + l * CS2_STR + 4 * q) = v;
        }
        __syncthreads();
        for (int n4 = 0; n4 < 64; n4 += 4) {
            float4 cr[4];
#pragma unroll
            for (int i = 0; i < 4; i++)
                cr[i] = *reinterpret_cast<const float4*>(Cs2 + (r0 + i) * CS2_STR + n4);
#pragma unroll
            for (int nn = 0; nn < 4; nn++) {
                int n = half * 64 + n4 + nn;
                uint64_t p0v = *reinterpret_cast<const uint64_t*>(Pst + n * TS_STR + c0);
                uint64_t p1v = *reinterpret_cast<const uint64_t*>(Pst + n * TS_STR + c0 + 2);
#pragma unroll
                for (int i = 0; i < 4; i++) {
                    uint64_t a2 = dup2((&cr[i].x)[nn]);
                    FMA2(acc2[i][0], a2, p0v);
                    FMA2(acc2[i][1], a2, p1v);
                }
            }
        }
    }

#pragma unroll
    for (int i = 0; i < 4; i++) {
        int l = r0 + i;
        int row = m0 + l;
        float el = expf(ac[l]);
        float v0, v1, v2, v3;
        up2(acc2[i][0], v0, v1);
        up2(acc2[i][1], v2, v3);
        float4 xv = *reinterpret_cast<const float4*>(
            g_xbc + (size_t)row * CONVCH + h * HD + c0);
        float4* yp = reinterpret_cast<float4*>(g_y + (size_t)row * DINNER + h * HD + c0);
        float4 yv = *yp;
        yv.x += v0 * el + xv.x * Dh;
        yv.y += v1 * el + xv.y * Dh;
        yv.z += v2 * el + xv.z * Dh;
        yv.w += v3 * el + xv.w * Dh;
        *yp = yv;
    }
}

// ---------------- gate (silu(z)) + RMSNorm, shuffle reduction, fp16 out ----------
__global__ void gate_kernel(const float* __restrict__ norm_w, __half* __restrict__ a2h) {
    int m = blockIdx.x;
    int tid = threadIdx.x;
    __shared__ float wsum[8];
    float tv[8];
    float ss = 0.f;
#pragma unroll
    for (int j = 0; j < 8; j++) {
        int i = tid + 256 * j;
        float zv = g_zx[(size_t)m * DPROJ + i];
        float yv = g_y[(size_t)m * DINNER + i];
        float g = yv * (zv / (1.f + expf(-zv)));
        tv[j] = g;
        ss += g * g;
    }
#pragma unroll
    for (int o = 16; o; o >>= 1) ss += __shfl_xor_sync(0xFFFFFFFFu, ss, o);
    if ((tid & 31) == 0) wsum[tid >> 5] = ss;
    __syncthreads();
    float tot = wsum[0] + wsum[1] + wsum[2] + wsum[3] +
                wsum[4] + wsum[5] + wsum[6] + wsum[7];
    float scale = rsqrtf(tot / (float)DINNER + 1e-5f);
#pragma unroll
    for (int j = 0; j < 8; j++) {
        int i = tid + 256 * j;
        a2h[(size_t)m * DINNER + i] = __float2half(tv[j] * scale * norm_w[i]);
    }
}

// ---------------- launch ----------------
extern "C" void kernel_launch(void* const* d_in, const int* in_sizes, int n_in,
                              void* d_out, int out_size) {
    const float* u      = (const float*)d_in[0];
    const float* W_in   = (const float*)d_in[1];
    const float* conv_w = (const float*)d_in[2];
    const float* conv_b = (const float*)d_in[3];
    const float* dt_b   = (const float*)d_in[4];
    const float* A_log  = (const float*)d_in[5];
    const float* Dv     = (const float*)d_in[6];
    const float* norm_w = (const float*)d_in[7];
    const float* W_out  = (const float*)d_in[8];
    float* out = (float*)d_out;

    float* zx = nullptr;
    cudaGetSymbolAddress((void**)&zx, g_zx);
    __half *a1h, *b1h, *a2h, *b2h;
    cudaGetSymbolAddress((void**)&a1h, g_a1h);
    cudaGetSymbolAddress((void**)&b1h, g_b1h);
    cudaGetSymbolAddress((void**)&a2h, g_a2h);
    cudaGetSymbolAddress((void**)&b2h, g_b2h);

    const size_t gemm_smem = 4 * 24576;   // 98304, 2 CTAs/SM
    const size_t cb_smem   = (size_t)(128 * TS_STR + 32 * CS_STR) * sizeof(float);
    const size_t diag_smem = (size_t)(128 * TS_STR + 2 * 64 * XS_STR + 192) * sizeof(float);
    const size_t yoff_smem = (size_t)(128 * TS_STR + 64 * CS2_STR + 64) * sizeof(float);
    cudaFuncSetAttribute(hgemm1_kernel, cudaFuncAttributeMaxDynamicSharedMemorySize, (int)gemm_smem);
    cudaFuncSetAttribute(cb_kernel, cudaFuncAttributeMaxDynamicSharedMemorySize, (int)cb_smem);
    cudaFuncSetAttribute(ssd_diag_kernel, cudaFuncAttributeMaxDynamicSharedMemorySize, (int)diag_smem);
    cudaFuncSetAttribute(yoff_kernel, cudaFuncAttributeMaxDynamicSharedMemorySize, (int)yoff_smem);

    // 0: exact fp32 dt
    dt_exact_kernel<<<MROWS / 16, 256>>>(u, W_in, dt_b);

    // 1: prep A (u -> fp16)
    prep_cvt_kernel<<<MROWS * DMODEL / 4096, 1024>>>(u, a1h);

    // 2: prep W
    prep_w_kernel<<<4352 + 2048, 1024>>>(W_in, W_out, b1h, b2h);

    // 3: GEMM1 (profiled): zx[:, :4352] = u @ W_in (fp16, 4-stage)
    hgemm1_kernel<<<dim3(NGEMM1 / 64, MROWS / 128), 256, gemm_smem>>>(
        a1h, b1h, zx, NGEMM1, DMODEL, DPROJ);

    // 4: conv
    conv_kernel<<<dim3(CONVCH / 256, MROWS / 32), 256>>>(conv_w, conv_b);

    // 5: CB^T shared across heads
    cb_kernel<<<BQ * NC * 2, 256, cb_smem>>>();

    // 6: SSD intra-chunk (fp16 state store)
    ssd_diag_kernel<<<BQ * NC * NH, 256, diag_smem>>>(A_log);

    // 7: inter-chunk scan (fp16 states, L2-resident)
    scan_kernel<<<(BQ * NH * HD * DSTATE / 4) / 256, 256>>>();

    // 8: Y_off + skip
    yoff_kernel<<<BQ * NC * NH, 256, yoff_smem>>>(Dv);

    // 9: gate + rmsnorm (writes fp16 A for GEMM2)
    gate_kernel<<<MROWS, 256>>>(norm_w, a2h);

    // 10: GEMM2: out = y @ W_out (fp16, 4-stage)
    hgemm1_kernel<<<dim3(DMODEL / 64, MROWS / 128), 256, gemm_smem>>>(
        a2h, b2h, out, DMODEL, DINNER, DMODEL);
}